// round 4
// baseline (speedup 1.0000x reference)
#include <cuda_runtime.h>
#include <cuda_bf16.h>

#define NN    50000
#define NRL   20
#define DEMB  64
#define DHID  128
#define EMAX  1600000
#define CSH   12              // chunk shift
#define CHUNK 4096            // nodes per chunk
#define NCH   13              // ceil(50000/4096)

// Static scratch (no allocations allowed). agg is reused across both layers.
__device__ float g_agg[(long)NN * NRL * DHID];          // 512 MB
__device__ float g_cnt[NN * NRL];                       // 4 MB
__device__ float g_inv[NN * NRL];                       // 4 MB
__device__ float g_h1[(long)NN * DHID];                 // 25.6 MB
__device__ float g_h2[(long)NN * DHID];                 // 25.6 MB
__device__ float g_B1[(NRL * DEMB + DEMB) * DHID];      // 1344 x 128
__device__ float g_B2[(NRL * DHID + DHID) * DHID];      // 2688 x 128
__device__ int   g_ebuf[EMAX];                          // bucketed edge ids
__device__ int   g_ccnt[32];
__device__ int   g_coff[32];
__device__ int   g_ccur[32];

__global__ void zero_kernel(float4* p, long n4) {
    long i = (long)blockIdx.x * blockDim.x + threadIdx.x;
    long stride = (long)gridDim.x * blockDim.x;
    float4 z = make_float4(0.f, 0.f, 0.f, 0.f);
    for (; i < n4; i += stride) p[i] = z;
}

__global__ void count_kernel(const int* __restrict__ dst, const int* __restrict__ et,
                             int E, float* __restrict__ cnt) {
    int i = blockIdx.x * blockDim.x + threadIdx.x;
    if (i < E) atomicAdd(&cnt[dst[i] * NRL + et[i]], 1.0f);
}

__global__ void inv_kernel(const float* __restrict__ cnt, float* __restrict__ inv, int n) {
    int i = blockIdx.x * blockDim.x + threadIdx.x;
    if (i < n) inv[i] = 1.0f / fmaxf(cnt[i], 1.0f);
}

// ---- edge bucketing by dst chunk (once per call; shared by both layers) ----
__global__ void zero_cnt32_kernel(int* c) {
    if (threadIdx.x < 32) c[threadIdx.x] = 0;
}

__global__ void hist_kernel(const int* __restrict__ dst, int E, int* __restrict__ cnt) {
    __shared__ int h[NCH];
    if (threadIdx.x < NCH) h[threadIdx.x] = 0;
    __syncthreads();
    for (long i = (long)blockIdx.x * blockDim.x + threadIdx.x; i < E;
         i += (long)gridDim.x * blockDim.x)
        atomicAdd(&h[dst[i] >> CSH], 1);
    __syncthreads();
    if (threadIdx.x < NCH && h[threadIdx.x]) atomicAdd(&cnt[threadIdx.x], h[threadIdx.x]);
}

__global__ void scan_kernel(const int* __restrict__ cnt, int* __restrict__ off,
                            int* __restrict__ cur) {
    if (threadIdx.x == 0) {
        int s = 0;
        for (int c = 0; c < NCH; c++) { off[c] = s; cur[c] = s; s += cnt[c]; }
        off[NCH] = s;
    }
}

#define BROUNDS 16
__global__ void bucket_kernel(const int* __restrict__ dst, int E,
                              int* __restrict__ cur, int* __restrict__ ebuf) {
    __shared__ int h[NCH], base[NCH];
    if (threadIdx.x < NCH) h[threadIdx.x] = 0;
    __syncthreads();
    long b0 = (long)blockIdx.x * blockDim.x * BROUNDS;
    int cc[BROUNDS], rr[BROUNDS];
#pragma unroll
    for (int t = 0; t < BROUNDS; t++) {
        long i = b0 + (long)t * blockDim.x + threadIdx.x;
        cc[t] = -1;
        if (i < E) { cc[t] = dst[i] >> CSH; rr[t] = atomicAdd(&h[cc[t]], 1); }
    }
    __syncthreads();
    if (threadIdx.x < NCH)
        base[threadIdx.x] = h[threadIdx.x] ? atomicAdd(&cur[threadIdx.x], h[threadIdx.x]) : 0;
    __syncthreads();
#pragma unroll
    for (int t = 0; t < BROUNDS; t++) {
        long i = b0 + (long)t * blockDim.x + threadIdx.x;
        if (i < E) ebuf[base[cc[t]] + rr[t]] = (int)i;
    }
}

// ---- chunked scatter: warp(-half) per edge, edges of one dst-chunk only ----
template <int DIN>
__global__ void scatter_chunk_kernel(const int* __restrict__ src, const int* __restrict__ dst,
                                     const int* __restrict__ et, const float* __restrict__ X,
                                     const int* __restrict__ ebuf, const int* __restrict__ off,
                                     int chunk, float* __restrict__ agg) {
    const int L = DIN / 4;                 // float4 lanes per edge (16 or 32)
    const int EPW = 32 / L;                // edges per warp (2 or 1)
    int s0 = off[chunk], s1 = off[chunk + 1];
    int w = (blockIdx.x * blockDim.x + threadIdx.x) >> 5;
    int nw = (gridDim.x * blockDim.x) >> 5;
    int lane = threadIdx.x & 31;
    int sub = lane / L;
    int l = lane % L;
    for (int i = s0 + w * EPW + sub; i < s1; i += nw * EPW) {
        int e = ebuf[i];
        int s = src[e], d = dst[e], r = et[e];
        float4 v = reinterpret_cast<const float4*>(X + (long)s * DIN)[l];
        float* p = agg + ((long)d * NRL + r) * DIN + l * 4;
        asm volatile("red.global.add.v4.f32 [%0], {%1,%2,%3,%4};"
                     :: "l"(p), "f"(v.x), "f"(v.y), "f"(v.z), "f"(v.w) : "memory");
    }
}

// Concatenate W [R*din,128] and root [din,128] into one B matrix.
__global__ void prep_kernel(const float* __restrict__ W, const float* __restrict__ root,
                            float* __restrict__ B, int wElems, int rootElems) {
    int total = wElems + rootElems;
    for (int i = blockIdx.x * blockDim.x + threadIdx.x; i < total;
         i += gridDim.x * blockDim.x) {
        B[i] = (i < wElems) ? W[i] : root[i - wElems];
    }
}

__device__ __forceinline__ unsigned pack2(__nv_bfloat16 lo, __nv_bfloat16 hi) {
    unsigned short a = *reinterpret_cast<unsigned short*>(&lo);
    unsigned short b = *reinterpret_cast<unsigned short*>(&hi);
    return (unsigned)a | ((unsigned)b << 16);
}

#define MMA_BF16(ACC, A, B0, B1)                                              \
    asm volatile(                                                             \
        "mma.sync.aligned.m16n8k16.row.col.f32.bf16.bf16.f32 "                \
        "{%0,%1,%2,%3}, {%4,%5,%6,%7}, {%8,%9}, {%0,%1,%2,%3};"               \
        : "+f"((ACC)[0]), "+f"((ACC)[1]), "+f"((ACC)[2]), "+f"((ACC)[3])      \
        : "r"((A)[0]), "r"((A)[1]), "r"((A)[2]), "r"((A)[3]),                 \
          "r"(B0), "r"(B1))

// C[NN,128] = A[NN, R*DIN + DIN] @ B[.,128] + bias, optional ReLU.
// A virtual: k < KA -> agg[n*KA+k]*inv[n*NRL+k/DIN]; else X[n*DIN+k-KA].
// bf16 split emulation: acc += Ah*Bh + Ah*Bl + Al*Bh (fp32 accumulate).
// B tile stored TRANSPOSED [n][k] so B fragments are 32-bit conflict-free LDS.
template <int DIN>
__global__ void __launch_bounds__(256)
gemm_mma_kernel(const float* __restrict__ Aagg, const float* __restrict__ inv,
                const float* __restrict__ X, const float* __restrict__ B,
                const float* __restrict__ bias, float* __restrict__ C, int relu) {
    const int KA = NRL * DIN;
    const int KT = KA + DIN;
    const int BK = 32;

    __shared__ __align__(16) __nv_bfloat16 Ah[128][40];
    __shared__ __align__(16) __nv_bfloat16 Al[128][40];
    __shared__ __align__(16) __nv_bfloat16 Bth[128][40];   // [n][k]
    __shared__ __align__(16) __nv_bfloat16 Btl[128][40];

    int tid = threadIdx.x;
    int wid = tid >> 5;
    int lane = tid & 31;
    int wm = wid & 3;        // warp row tile (32 rows)
    int wn = wid >> 2;       // warp col tile (64 cols)
    int bm = blockIdx.x * 128;

    int lg = lane >> 2;
    int lq = lane & 3;

    float acc[2][8][4];
#pragma unroll
    for (int ma = 0; ma < 2; ma++)
#pragma unroll
        for (int na = 0; na < 8; na++)
#pragma unroll
            for (int r = 0; r < 4; r++) acc[ma][na][r] = 0.f;

    for (int k0 = 0; k0 < KT; k0 += BK) {
        // ---- A tile (128x32 fp32) -> hi/lo bf16 planes
#pragma unroll
        for (int p = 0; p < 4; p++) {
            int idx = p * 256 + tid;
            int r = idx >> 3;
            int c4 = (idx & 7) * 4;
            int n = bm + r;
            float4 av = make_float4(0.f, 0.f, 0.f, 0.f);
            if (n < NN) {
                int k = k0 + c4;
                if (k < KA) {
                    float sc = inv[n * NRL + k / DIN];
                    av = *reinterpret_cast<const float4*>(Aagg + (long)n * KA + k);
                    av.x *= sc; av.y *= sc; av.z *= sc; av.w *= sc;
                } else {
                    av = *reinterpret_cast<const float4*>(X + (long)n * DIN + (k - KA));
                }
            }
            __nv_bfloat16 h0 = __float2bfloat16(av.x);
            __nv_bfloat16 h1 = __float2bfloat16(av.y);
            __nv_bfloat16 h2 = __float2bfloat16(av.z);
            __nv_bfloat16 h3 = __float2bfloat16(av.w);
            __nv_bfloat16 l0 = __float2bfloat16(av.x - __bfloat162float(h0));
            __nv_bfloat16 l1 = __float2bfloat16(av.y - __bfloat162float(h1));
            __nv_bfloat16 l2 = __float2bfloat16(av.z - __bfloat162float(h2));
            __nv_bfloat16 l3 = __float2bfloat16(av.w - __bfloat162float(h3));
            *reinterpret_cast<uint2*>(&Ah[r][c4]) = make_uint2(pack2(h0, h1), pack2(h2, h3));
            *reinterpret_cast<uint2*>(&Al[r][c4]) = make_uint2(pack2(l0, l1), pack2(l2, l3));
        }
        // ---- B tile (32x128 fp32) -> transposed hi/lo planes [n][k]
#pragma unroll
        for (int p = 0; p < 8; p++) {
            int idx = p * 256 + tid;
            int n = idx & 127;
            int k = (idx >> 7) * 2;
            float b0 = B[(long)(k0 + k) * DHID + n];
            float b1 = B[(long)(k0 + k + 1) * DHID + n];
            __nv_bfloat16 h0 = __float2bfloat16(b0);
            __nv_bfloat16 h1 = __float2bfloat16(b1);
            __nv_bfloat16 L0 = __float2bfloat16(b0 - __bfloat162float(h0));
            __nv_bfloat16 L1 = __float2bfloat16(b1 - __bfloat162float(h1));
            *reinterpret_cast<unsigned*>(&Bth[n][k]) = pack2(h0, h1);
            *reinterpret_cast<unsigned*>(&Btl[n][k]) = pack2(L0, L1);
        }
        __syncthreads();

#pragma unroll
        for (int ks = 0; ks < BK; ks += 16) {
            unsigned ah[2][4], al[2][4];
#pragma unroll
            for (int ma = 0; ma < 2; ma++) {
                int r0 = wm * 32 + ma * 16 + lg;
                int kc = ks + lq * 2;
                ah[ma][0] = *reinterpret_cast<unsigned*>(&Ah[r0][kc]);
                ah[ma][1] = *reinterpret_cast<unsigned*>(&Ah[r0 + 8][kc]);
                ah[ma][2] = *reinterpret_cast<unsigned*>(&Ah[r0][kc + 8]);
                ah[ma][3] = *reinterpret_cast<unsigned*>(&Ah[r0 + 8][kc + 8]);
                al[ma][0] = *reinterpret_cast<unsigned*>(&Al[r0][kc]);
                al[ma][1] = *reinterpret_cast<unsigned*>(&Al[r0 + 8][kc]);
                al[ma][2] = *reinterpret_cast<unsigned*>(&Al[r0][kc + 8]);
                al[ma][3] = *reinterpret_cast<unsigned*>(&Al[r0 + 8][kc + 8]);
            }
            unsigned bh0[8], bh1[8], bl0[8], bl1[8];
#pragma unroll
            for (int na = 0; na < 8; na++) {
                int nb = wn * 64 + na * 8 + lg;
                int kl = ks + lq * 2;
                bh0[na] = *reinterpret_cast<unsigned*>(&Bth[nb][kl]);
                bh1[na] = *reinterpret_cast<unsigned*>(&Bth[nb][kl + 8]);
                bl0[na] = *reinterpret_cast<unsigned*>(&Btl[nb][kl]);
                bl1[na] = *reinterpret_cast<unsigned*>(&Btl[nb][kl + 8]);
            }
#pragma unroll
            for (int na = 0; na < 8; na++)
#pragma unroll
                for (int ma = 0; ma < 2; ma++)
                    MMA_BF16(acc[ma][na], ah[ma], bh0[na], bh1[na]);
#pragma unroll
            for (int na = 0; na < 8; na++)
#pragma unroll
                for (int ma = 0; ma < 2; ma++)
                    MMA_BF16(acc[ma][na], ah[ma], bl0[na], bl1[na]);
#pragma unroll
            for (int na = 0; na < 8; na++)
#pragma unroll
                for (int ma = 0; ma < 2; ma++)
                    MMA_BF16(acc[ma][na], al[ma], bh0[na], bh1[na]);
        }
        __syncthreads();
    }

#pragma unroll
    for (int ma = 0; ma < 2; ma++) {
#pragma unroll
        for (int na = 0; na < 8; na++) {
            int col = wn * 64 + na * 8 + lq * 2;
            float2 bv = *reinterpret_cast<const float2*>(&bias[col]);
            float v0 = acc[ma][na][0] + bv.x;
            float v1 = acc[ma][na][1] + bv.y;
            float v2 = acc[ma][na][2] + bv.x;
            float v3 = acc[ma][na][3] + bv.y;
            if (relu) {
                v0 = fmaxf(v0, 0.f); v1 = fmaxf(v1, 0.f);
                v2 = fmaxf(v2, 0.f); v3 = fmaxf(v3, 0.f);
            }
            int row0 = bm + wm * 32 + ma * 16 + lg;
            int row1 = row0 + 8;
            if (row0 < NN)
                *reinterpret_cast<float2*>(&C[(long)row0 * DHID + col]) = make_float2(v0, v1);
            if (row1 < NN)
                *reinterpret_cast<float2*>(&C[(long)row1 * DHID + col]) = make_float2(v2, v3);
        }
    }
}

__global__ void decoder_kernel(const int* __restrict__ head, const int* __restrict__ tail,
                               const int* __restrict__ rel, const float* __restrict__ h,
                               const float* __restrict__ rel_emb, float* __restrict__ out,
                               int Bn) {
    int warp = (blockIdx.x * blockDim.x + threadIdx.x) >> 5;
    int lane = threadIdx.x & 31;
    if (warp >= Bn) return;
    const float4* hp = reinterpret_cast<const float4*>(h + (long)head[warp] * DHID);
    const float4* tp = reinterpret_cast<const float4*>(h + (long)tail[warp] * DHID);
    const float4* rp = reinterpret_cast<const float4*>(rel_emb + (long)rel[warp] * DHID);
    float4 a = hp[lane], b = tp[lane], c = rp[lane];
    float s = a.x * b.x * c.x + a.y * b.y * c.y + a.z * b.z * c.z + a.w * b.w * c.w;
#pragma unroll
    for (int o = 16; o; o >>= 1) s += __shfl_xor_sync(0xffffffffu, s, o);
    if (lane == 0) out[warp] = s;
}

extern "C" void kernel_launch(void* const* d_in, const int* in_sizes, int n_in,
                              void* d_out, int out_size) {
    const int*   edge_index = (const int*)d_in[0];
    const int*   edge_type  = (const int*)d_in[1];
    const int*   head       = (const int*)d_in[2];
    const int*   tail       = (const int*)d_in[3];
    const int*   rel        = (const int*)d_in[4];
    const float* node_emb   = (const float*)d_in[5];
    const float* W1         = (const float*)d_in[6];
    const float* root1      = (const float*)d_in[7];
    const float* b1         = (const float*)d_in[8];
    const float* W2         = (const float*)d_in[9];
    const float* root2      = (const float*)d_in[10];
    const float* b2         = (const float*)d_in[11];
    const float* rel_emb    = (const float*)d_in[12];

    int E = in_sizes[0] / 2;
    const int* src = edge_index;
    const int* dst = edge_index + E;

    float *agg, *cnt, *inv, *h1, *h2, *B1, *B2;
    int *ebuf, *ccnt, *coff, *ccur;
    cudaGetSymbolAddress((void**)&agg, g_agg);
    cudaGetSymbolAddress((void**)&cnt, g_cnt);
    cudaGetSymbolAddress((void**)&inv, g_inv);
    cudaGetSymbolAddress((void**)&h1, g_h1);
    cudaGetSymbolAddress((void**)&h2, g_h2);
    cudaGetSymbolAddress((void**)&B1, g_B1);
    cudaGetSymbolAddress((void**)&B2, g_B2);
    cudaGetSymbolAddress((void**)&ebuf, g_ebuf);
    cudaGetSymbolAddress((void**)&ccnt, g_ccnt);
    cudaGetSymbolAddress((void**)&coff, g_coff);
    cudaGetSymbolAddress((void**)&ccur, g_ccur);

    const int T = 256;

    // ---- shared prep: counts / inverse counts + edge bucketing by dst chunk
    zero_kernel<<<1024, T>>>((float4*)cnt, (long)NN * NRL / 4);
    zero_cnt32_kernel<<<1, 32>>>(ccnt);
    count_kernel<<<(E + T - 1) / T, T>>>(dst, edge_type, E, cnt);
    inv_kernel<<<(NN * NRL + T - 1) / T, T>>>(cnt, inv, NN * NRL);
    hist_kernel<<<592, T>>>(dst, E, ccnt);
    scan_kernel<<<1, 32>>>(ccnt, coff, ccur);
    bucket_kernel<<<(E + T * BROUNDS - 1) / (T * BROUNDS), T>>>(dst, E, ccur, ebuf);

    // ---- layer 1: chunked zero+scatter (L2-resident slices), then GEMM
    for (int c = 0; c < NCH; c++) {
        int rows = (c == NCH - 1) ? (NN - c * CHUNK) : CHUNK;
        float* slice = agg + (long)c * CHUNK * NRL * DEMB;
        zero_kernel<<<1024, T>>>((float4*)slice, (long)rows * NRL * DEMB / 4);
        scatter_chunk_kernel<DEMB><<<1024, T>>>(src, dst, edge_type, node_emb,
                                                ebuf, coff, c, agg);
    }
    prep_kernel<<<512, T>>>(W1, root1, B1, NRL * DEMB * DHID, DEMB * DHID);
    gemm_mma_kernel<DEMB><<<(NN + 127) / 128, T>>>(agg, inv, node_emb, B1, b1, h1, 1);

    // ---- layer 2
    for (int c = 0; c < NCH; c++) {
        int rows = (c == NCH - 1) ? (NN - c * CHUNK) : CHUNK;
        float* slice = agg + (long)c * CHUNK * NRL * DHID;
        zero_kernel<<<2048, T>>>((float4*)slice, (long)rows * NRL * DHID / 4);
        scatter_chunk_kernel<DHID><<<1024, T>>>(src, dst, edge_type, h1,
                                                ebuf, coff, c, agg);
    }
    prep_kernel<<<512, T>>>(W2, root2, B2, NRL * DHID * DHID, DHID * DHID);
    gemm_mma_kernel<DHID><<<(NN + 127) / 128, T>>>(agg, inv, h1, B2, b2, h2, 0);

    // ---- DistMult decoder
    int Bn = in_sizes[2];
    decoder_kernel<<<(Bn * 32 + T - 1) / T, T>>>(head, tail, rel, h2, rel_emb,
                                                 (float*)d_out, Bn);
}

// round 5
// speedup vs baseline: 1.1655x; 1.1655x over previous
#include <cuda_runtime.h>
#include <cuda_bf16.h>

#define NN    50000
#define NRL   20
#define DEMB  64
#define DHID  128
#define EMAX  1600000
#define NSEG  (NN * NRL)          // 1,000,000 segments

// Static scratch (no allocations allowed).
__device__ float g_agg[(long)NN * NRL * DHID];          // 512 MB (holds per-seg MEAN)
__device__ float g_h1[(long)NN * DHID];                 // 25.6 MB
__device__ float g_h2[(long)NN * DHID];                 // 25.6 MB
__device__ float g_B1[(NRL * DEMB + DEMB) * DHID];      // 1344 x 128
__device__ float g_B2[(NRL * DHID + DHID) * DHID];      // 2688 x 128
__device__ int   g_icnt[NSEG];                          // per-seg edge count
__device__ int   g_off[NSEG + 4];                       // seg offsets (exclusive scan)
__device__ int   g_pcur[NSEG];                          // placement cursors
__device__ int   g_bsum[1024];                          // block sums for scan
__device__ int   g_ebuf[EMAX];                          // src ids, sorted by segment

#define SCAN_ITEMS 1024                                 // items per scan block
#define SCAN_NB    ((NSEG + SCAN_ITEMS - 1) / SCAN_ITEMS)   // 977 blocks

__global__ void zero_kernel(float4* p, long n4) {
    long i = (long)blockIdx.x * blockDim.x + threadIdx.x;
    long stride = (long)gridDim.x * blockDim.x;
    float4 z = make_float4(0.f, 0.f, 0.f, 0.f);
    for (; i < n4; i += stride) p[i] = z;
}

__global__ void seg_count_kernel(const int* __restrict__ dst, const int* __restrict__ et,
                                 int E, int* __restrict__ icnt) {
    int i = blockIdx.x * blockDim.x + threadIdx.x;
    if (i < E) atomicAdd(&icnt[dst[i] * NRL + et[i]], 1);
}

// ---- 3-kernel exclusive scan over icnt -> off (1M elements) ----
__global__ void scanA_kernel(const int* __restrict__ icnt, int* __restrict__ bsum) {
    __shared__ int sd[256];
    int base = blockIdx.x * SCAN_ITEMS + threadIdx.x * 4;
    int s = 0;
#pragma unroll
    for (int t = 0; t < 4; t++) {
        int i = base + t;
        if (i < NSEG) s += icnt[i];
    }
    sd[threadIdx.x] = s;
    __syncthreads();
    for (int o = 128; o; o >>= 1) {
        if (threadIdx.x < o) sd[threadIdx.x] += sd[threadIdx.x + o];
        __syncthreads();
    }
    if (threadIdx.x == 0) bsum[blockIdx.x] = sd[0];
}

__global__ void scanB_kernel(int* __restrict__ bsum, int nb) {
    __shared__ int sm[1024];
    int v = (threadIdx.x < nb) ? bsum[threadIdx.x] : 0;
    sm[threadIdx.x] = v;
    __syncthreads();
    for (int o = 1; o < 1024; o <<= 1) {
        int t = (threadIdx.x >= o) ? sm[threadIdx.x - o] : 0;
        __syncthreads();
        sm[threadIdx.x] += t;
        __syncthreads();
    }
    if (threadIdx.x < nb) bsum[threadIdx.x] = sm[threadIdx.x] - v;  // exclusive
}

__global__ void scanC_kernel(const int* __restrict__ icnt, const int* __restrict__ bsum,
                             int* __restrict__ off, int E) {
    __shared__ int sm[256];
    int base = blockIdx.x * SCAN_ITEMS + threadIdx.x * 4;
    int v[4], ex[4];
    int s = 0;
#pragma unroll
    for (int t = 0; t < 4; t++) {
        int i = base + t;
        v[t] = (i < NSEG) ? icnt[i] : 0;
        ex[t] = s;
        s += v[t];
    }
    int mine = s;
    sm[threadIdx.x] = s;
    __syncthreads();
    for (int o = 1; o < 256; o <<= 1) {
        int t = (threadIdx.x >= o) ? sm[threadIdx.x - o] : 0;
        __syncthreads();
        sm[threadIdx.x] += t;
        __syncthreads();
    }
    int tex = sm[threadIdx.x] - mine;  // exclusive prefix of thread sums
    int b0 = bsum[blockIdx.x];
#pragma unroll
    for (int t = 0; t < 4; t++) {
        int i = base + t;
        if (i < NSEG) off[i] = b0 + tex + ex[t];
    }
    if (blockIdx.x == 0 && threadIdx.x == 0) off[NSEG] = E;
}

__global__ void place_kernel(const int* __restrict__ src, const int* __restrict__ dst,
                             const int* __restrict__ et, int E,
                             const int* __restrict__ off, int* __restrict__ pcur,
                             int* __restrict__ ebuf) {
    int i = blockIdx.x * blockDim.x + threadIdx.x;
    if (i >= E) return;
    int seg = dst[i] * NRL + et[i];
    int p = off[seg] + atomicAdd(&pcur[seg], 1);
    ebuf[p] = src[i];
}

// ---- segmented gather-reduce: write per-segment MEAN, no atomics ----
template <int DIN>
__global__ void __launch_bounds__(256)
segsum_kernel(const int* __restrict__ ebuf, const int* __restrict__ off,
              const float* __restrict__ X, float* __restrict__ agg) {
    const int L = DIN / 4;             // lanes per segment (16 or 32)
    const int SPB = 256 / L;           // segments per block
    long s = (long)blockIdx.x * SPB + threadIdx.x / L;
    if (s >= NSEG) return;
    int l = threadIdx.x % L;
    int b = off[s], e = off[s + 1];
    float4 acc = make_float4(0.f, 0.f, 0.f, 0.f);
    for (int i = b; i < e; i++) {
        int sid = __ldg(&ebuf[i]);
        float4 v = __ldg(reinterpret_cast<const float4*>(X + (long)sid * DIN) + l);
        acc.x += v.x; acc.y += v.y; acc.z += v.z; acc.w += v.w;
    }
    float sc = 1.f / fmaxf((float)(e - b), 1.f);
    acc.x *= sc; acc.y *= sc; acc.z *= sc; acc.w *= sc;
    reinterpret_cast<float4*>(agg + s * DIN)[l] = acc;
}

// Concatenate W [R*din,128] and root [din,128] into one B matrix.
__global__ void prep_kernel(const float* __restrict__ W, const float* __restrict__ root,
                            float* __restrict__ B, int wElems, int rootElems) {
    int total = wElems + rootElems;
    for (int i = blockIdx.x * blockDim.x + threadIdx.x; i < total;
         i += gridDim.x * blockDim.x) {
        B[i] = (i < wElems) ? W[i] : root[i - wElems];
    }
}

__device__ __forceinline__ unsigned pack2(__nv_bfloat16 lo, __nv_bfloat16 hi) {
    unsigned short a = *reinterpret_cast<unsigned short*>(&lo);
    unsigned short b = *reinterpret_cast<unsigned short*>(&hi);
    return (unsigned)a | ((unsigned)b << 16);
}

#define MMA_BF16(ACC, A, B0, B1)                                              \
    asm volatile(                                                             \
        "mma.sync.aligned.m16n8k16.row.col.f32.bf16.bf16.f32 "                \
        "{%0,%1,%2,%3}, {%4,%5,%6,%7}, {%8,%9}, {%0,%1,%2,%3};"               \
        : "+f"((ACC)[0]), "+f"((ACC)[1]), "+f"((ACC)[2]), "+f"((ACC)[3])      \
        : "r"((A)[0]), "r"((A)[1]), "r"((A)[2]), "r"((A)[3]),                 \
          "r"(B0), "r"(B1))

// C[NN,128] = [mean_agg | X] @ B + bias, optional ReLU.
// agg already holds means; k < KA -> agg[n*KA+k], else X[n*DIN + k-KA].
// bf16 split emulation: acc += Ah*Bh + Ah*Bl + Al*Bh (fp32 accumulate).
template <int DIN>
__global__ void __launch_bounds__(256)
gemm_mma_kernel(const float* __restrict__ Aagg, const float* __restrict__ X,
                const float* __restrict__ B, const float* __restrict__ bias,
                float* __restrict__ C, int relu) {
    const int KA = NRL * DIN;
    const int KT = KA + DIN;
    const int BK = 32;

    __shared__ __align__(16) __nv_bfloat16 Ah[128][40];
    __shared__ __align__(16) __nv_bfloat16 Al[128][40];
    __shared__ __align__(16) __nv_bfloat16 Bth[128][40];   // [n][k]
    __shared__ __align__(16) __nv_bfloat16 Btl[128][40];

    int tid = threadIdx.x;
    int wid = tid >> 5;
    int lane = tid & 31;
    int wm = wid & 3;
    int wn = wid >> 2;
    int bm = blockIdx.x * 128;

    int lg = lane >> 2;
    int lq = lane & 3;

    float acc[2][8][4];
#pragma unroll
    for (int ma = 0; ma < 2; ma++)
#pragma unroll
        for (int na = 0; na < 8; na++)
#pragma unroll
            for (int r = 0; r < 4; r++) acc[ma][na][r] = 0.f;

    for (int k0 = 0; k0 < KT; k0 += BK) {
#pragma unroll
        for (int p = 0; p < 4; p++) {
            int idx = p * 256 + tid;
            int r = idx >> 3;
            int c4 = (idx & 7) * 4;
            int n = bm + r;
            float4 av = make_float4(0.f, 0.f, 0.f, 0.f);
            if (n < NN) {
                int k = k0 + c4;
                if (k < KA)
                    av = *reinterpret_cast<const float4*>(Aagg + (long)n * KA + k);
                else
                    av = *reinterpret_cast<const float4*>(X + (long)n * DIN + (k - KA));
            }
            __nv_bfloat16 h0 = __float2bfloat16(av.x);
            __nv_bfloat16 h1 = __float2bfloat16(av.y);
            __nv_bfloat16 h2 = __float2bfloat16(av.z);
            __nv_bfloat16 h3 = __float2bfloat16(av.w);
            __nv_bfloat16 l0 = __float2bfloat16(av.x - __bfloat162float(h0));
            __nv_bfloat16 l1 = __float2bfloat16(av.y - __bfloat162float(h1));
            __nv_bfloat16 l2 = __float2bfloat16(av.z - __bfloat162float(h2));
            __nv_bfloat16 l3 = __float2bfloat16(av.w - __bfloat162float(h3));
            *reinterpret_cast<uint2*>(&Ah[r][c4]) = make_uint2(pack2(h0, h1), pack2(h2, h3));
            *reinterpret_cast<uint2*>(&Al[r][c4]) = make_uint2(pack2(l0, l1), pack2(l2, l3));
        }
#pragma unroll
        for (int p = 0; p < 8; p++) {
            int idx = p * 256 + tid;
            int n = idx & 127;
            int k = (idx >> 7) * 2;
            float b0 = B[(long)(k0 + k) * DHID + n];
            float b1 = B[(long)(k0 + k + 1) * DHID + n];
            __nv_bfloat16 h0 = __float2bfloat16(b0);
            __nv_bfloat16 h1 = __float2bfloat16(b1);
            __nv_bfloat16 L0 = __float2bfloat16(b0 - __bfloat162float(h0));
            __nv_bfloat16 L1 = __float2bfloat16(b1 - __bfloat162float(h1));
            *reinterpret_cast<unsigned*>(&Bth[n][k]) = pack2(h0, h1);
            *reinterpret_cast<unsigned*>(&Btl[n][k]) = pack2(L0, L1);
        }
        __syncthreads();

#pragma unroll
        for (int ks = 0; ks < BK; ks += 16) {
            unsigned ah[2][4], al[2][4];
#pragma unroll
            for (int ma = 0; ma < 2; ma++) {
                int r0 = wm * 32 + ma * 16 + lg;
                int kc = ks + lq * 2;
                ah[ma][0] = *reinterpret_cast<unsigned*>(&Ah[r0][kc]);
                ah[ma][1] = *reinterpret_cast<unsigned*>(&Ah[r0 + 8][kc]);
                ah[ma][2] = *reinterpret_cast<unsigned*>(&Ah[r0][kc + 8]);
                ah[ma][3] = *reinterpret_cast<unsigned*>(&Ah[r0 + 8][kc + 8]);
                al[ma][0] = *reinterpret_cast<unsigned*>(&Al[r0][kc]);
                al[ma][1] = *reinterpret_cast<unsigned*>(&Al[r0 + 8][kc]);
                al[ma][2] = *reinterpret_cast<unsigned*>(&Al[r0][kc + 8]);
                al[ma][3] = *reinterpret_cast<unsigned*>(&Al[r0 + 8][kc + 8]);
            }
            unsigned bh0[8], bh1[8], bl0[8], bl1[8];
#pragma unroll
            for (int na = 0; na < 8; na++) {
                int nb = wn * 64 + na * 8 + lg;
                int kl = ks + lq * 2;
                bh0[na] = *reinterpret_cast<unsigned*>(&Bth[nb][kl]);
                bh1[na] = *reinterpret_cast<unsigned*>(&Bth[nb][kl + 8]);
                bl0[na] = *reinterpret_cast<unsigned*>(&Btl[nb][kl]);
                bl1[na] = *reinterpret_cast<unsigned*>(&Btl[nb][kl + 8]);
            }
#pragma unroll
            for (int na = 0; na < 8; na++)
#pragma unroll
                for (int ma = 0; ma < 2; ma++)
                    MMA_BF16(acc[ma][na], ah[ma], bh0[na], bh1[na]);
#pragma unroll
            for (int na = 0; na < 8; na++)
#pragma unroll
                for (int ma = 0; ma < 2; ma++)
                    MMA_BF16(acc[ma][na], ah[ma], bl0[na], bl1[na]);
#pragma unroll
            for (int na = 0; na < 8; na++)
#pragma unroll
                for (int ma = 0; ma < 2; ma++)
                    MMA_BF16(acc[ma][na], al[ma], bh0[na], bh1[na]);
        }
        __syncthreads();
    }

#pragma unroll
    for (int ma = 0; ma < 2; ma++) {
#pragma unroll
        for (int na = 0; na < 8; na++) {
            int col = wn * 64 + na * 8 + lq * 2;
            float2 bv = *reinterpret_cast<const float2*>(&bias[col]);
            float v0 = acc[ma][na][0] + bv.x;
            float v1 = acc[ma][na][1] + bv.y;
            float v2 = acc[ma][na][2] + bv.x;
            float v3 = acc[ma][na][3] + bv.y;
            if (relu) {
                v0 = fmaxf(v0, 0.f); v1 = fmaxf(v1, 0.f);
                v2 = fmaxf(v2, 0.f); v3 = fmaxf(v3, 0.f);
            }
            int row0 = bm + wm * 32 + ma * 16 + lg;
            int row1 = row0 + 8;
            if (row0 < NN)
                *reinterpret_cast<float2*>(&C[(long)row0 * DHID + col]) = make_float2(v0, v1);
            if (row1 < NN)
                *reinterpret_cast<float2*>(&C[(long)row1 * DHID + col]) = make_float2(v2, v3);
        }
    }
}

__global__ void decoder_kernel(const int* __restrict__ head, const int* __restrict__ tail,
                               const int* __restrict__ rel, const float* __restrict__ h,
                               const float* __restrict__ rel_emb, float* __restrict__ out,
                               int Bn) {
    int warp = (blockIdx.x * blockDim.x + threadIdx.x) >> 5;
    int lane = threadIdx.x & 31;
    if (warp >= Bn) return;
    const float4* hp = reinterpret_cast<const float4*>(h + (long)head[warp] * DHID);
    const float4* tp = reinterpret_cast<const float4*>(h + (long)tail[warp] * DHID);
    const float4* rp = reinterpret_cast<const float4*>(rel_emb + (long)rel[warp] * DHID);
    float4 a = hp[lane], b = tp[lane], c = rp[lane];
    float s = a.x * b.x * c.x + a.y * b.y * c.y + a.z * b.z * c.z + a.w * b.w * c.w;
#pragma unroll
    for (int o = 16; o; o >>= 1) s += __shfl_xor_sync(0xffffffffu, s, o);
    if (lane == 0) out[warp] = s;
}

extern "C" void kernel_launch(void* const* d_in, const int* in_sizes, int n_in,
                              void* d_out, int out_size) {
    const int*   edge_index = (const int*)d_in[0];
    const int*   edge_type  = (const int*)d_in[1];
    const int*   head       = (const int*)d_in[2];
    const int*   tail       = (const int*)d_in[3];
    const int*   rel        = (const int*)d_in[4];
    const float* node_emb   = (const float*)d_in[5];
    const float* W1         = (const float*)d_in[6];
    const float* root1      = (const float*)d_in[7];
    const float* b1         = (const float*)d_in[8];
    const float* W2         = (const float*)d_in[9];
    const float* root2      = (const float*)d_in[10];
    const float* b2         = (const float*)d_in[11];
    const float* rel_emb    = (const float*)d_in[12];

    int E = in_sizes[0] / 2;
    const int* src = edge_index;
    const int* dst = edge_index + E;

    float *agg, *h1, *h2, *B1, *B2;
    int *icnt, *off, *pcur, *bsum, *ebuf;
    cudaGetSymbolAddress((void**)&agg, g_agg);
    cudaGetSymbolAddress((void**)&h1, g_h1);
    cudaGetSymbolAddress((void**)&h2, g_h2);
    cudaGetSymbolAddress((void**)&B1, g_B1);
    cudaGetSymbolAddress((void**)&B2, g_B2);
    cudaGetSymbolAddress((void**)&icnt, g_icnt);
    cudaGetSymbolAddress((void**)&off, g_off);
    cudaGetSymbolAddress((void**)&pcur, g_pcur);
    cudaGetSymbolAddress((void**)&bsum, g_bsum);
    cudaGetSymbolAddress((void**)&ebuf, g_ebuf);

    const int T = 256;

    // ---- counting sort of edges by segment (graph fixed; shared by both layers)
    zero_kernel<<<512, T>>>((float4*)icnt, NSEG / 4);
    zero_kernel<<<512, T>>>((float4*)pcur, NSEG / 4);
    seg_count_kernel<<<(E + T - 1) / T, T>>>(dst, edge_type, E, icnt);
    scanA_kernel<<<SCAN_NB, T>>>(icnt, bsum);
    scanB_kernel<<<1, 1024>>>(bsum, SCAN_NB);
    scanC_kernel<<<SCAN_NB, T>>>(icnt, bsum, off, E);
    place_kernel<<<(E + T - 1) / T, T>>>(src, dst, edge_type, E, off, pcur, ebuf);

    // ---- layer 1: segmented mean (no atomics) + GEMM
    segsum_kernel<DEMB><<<(NSEG + 15) / 16, T>>>(ebuf, off, node_emb, agg);
    prep_kernel<<<512, T>>>(W1, root1, B1, NRL * DEMB * DHID, DEMB * DHID);
    gemm_mma_kernel<DEMB><<<(NN + 127) / 128, T>>>(agg, node_emb, B1, b1, h1, 1);

    // ---- layer 2
    segsum_kernel<DHID><<<(NSEG + 7) / 8, T>>>(ebuf, off, h1, agg);
    prep_kernel<<<512, T>>>(W2, root2, B2, NRL * DHID * DHID, DHID * DHID);
    gemm_mma_kernel<DHID><<<(NN + 127) / 128, T>>>(agg, h1, B2, b2, h2, 0);

    // ---- DistMult decoder
    int Bn = in_sizes[2];
    decoder_kernel<<<(Bn * 32 + T - 1) / T, T>>>(head, tail, rel, h2, rel_emb,
                                                 (float*)d_out, Bn);
}

// round 7
// speedup vs baseline: 1.6656x; 1.4290x over previous
#include <cuda_runtime.h>
#include <cuda_bf16.h>

#define NN    50000
#define NRL   20
#define DEMB  64
#define DHID  128
#define EMAX  1600000
#define NSEG  (NN * NRL)          // 1,000,000 segments

// Static scratch (no allocations allowed). 16-byte aligned for uint4 access.
__device__ __align__(16) __nv_bfloat16 g_aggh[(long)NSEG * DHID];   // 256 MB mean hi
__device__ __align__(16) __nv_bfloat16 g_aggl[(long)NSEG * DHID];   // 256 MB mean lo
__device__ __align__(16) float g_h1[(long)NN * DHID];               // 25.6 MB
__device__ __align__(16) float g_h2[(long)NN * DHID];               // 25.6 MB
__device__ __align__(16) __nv_bfloat16 g_xh[(long)NN * DHID];       // X hi (per layer)
__device__ __align__(16) __nv_bfloat16 g_xl[(long)NN * DHID];       // X lo
__device__ __align__(16) __nv_bfloat16 g_Bth[128 * (NRL * DHID + DHID)];  // B^T hi [o][k]
__device__ __align__(16) __nv_bfloat16 g_Btl[128 * (NRL * DHID + DHID)];  // B^T lo
__device__ int   g_icnt[NSEG];
__device__ int   g_off[NSEG + 4];
__device__ int   g_pcur[NSEG];
__device__ int   g_bsum[1024];
__device__ int   g_ebuf[EMAX];

#define SCAN_ITEMS 1024
#define SCAN_NB    ((NSEG + SCAN_ITEMS - 1) / SCAN_ITEMS)   // 977

// Split a = hi + lo: hi = exact 16-bit truncation (finite fp32 -> finite bf16),
// lo = exact fp32 residual rounded to bf16 via packed intrinsic.
__device__ __forceinline__ void split2(float a, float b, unsigned& h, unsigned& l) {
    unsigned ua = __float_as_uint(a), ub = __float_as_uint(b);
    h = __byte_perm(ua, ub, 0x7632);             // low16 = hi16(a), high16 = hi16(b)
    float la = a - __uint_as_float(ua & 0xFFFF0000u);
    float lb = b - __uint_as_float(ub & 0xFFFF0000u);
    __nv_bfloat162 p = __float22bfloat162_rn(make_float2(la, lb));  // .x=la(lo16), .y=lb
    l = *reinterpret_cast<unsigned*>(&p);
}

__global__ void zero_kernel(float4* p, long n4) {
    long i = (long)blockIdx.x * blockDim.x + threadIdx.x;
    long stride = (long)gridDim.x * blockDim.x;
    float4 z = make_float4(0.f, 0.f, 0.f, 0.f);
    for (; i < n4; i += stride) p[i] = z;
}

__global__ void seg_count_kernel(const int* __restrict__ dst, const int* __restrict__ et,
                                 int E, int* __restrict__ icnt) {
    int i = blockIdx.x * blockDim.x + threadIdx.x;
    if (i < E) atomicAdd(&icnt[dst[i] * NRL + et[i]], 1);
}

// ---- 3-kernel exclusive scan over icnt -> off ----
__global__ void scanA_kernel(const int* __restrict__ icnt, int* __restrict__ bsum) {
    __shared__ int sd[256];
    int base = blockIdx.x * SCAN_ITEMS + threadIdx.x * 4;
    int s = 0;
#pragma unroll
    for (int t = 0; t < 4; t++) {
        int i = base + t;
        if (i < NSEG) s += icnt[i];
    }
    sd[threadIdx.x] = s;
    __syncthreads();
    for (int o = 128; o; o >>= 1) {
        if (threadIdx.x < o) sd[threadIdx.x] += sd[threadIdx.x + o];
        __syncthreads();
    }
    if (threadIdx.x == 0) bsum[blockIdx.x] = sd[0];
}

__global__ void scanB_kernel(int* __restrict__ bsum, int nb) {
    __shared__ int sm[1024];
    int v = (threadIdx.x < nb) ? bsum[threadIdx.x] : 0;
    sm[threadIdx.x] = v;
    __syncthreads();
    for (int o = 1; o < 1024; o <<= 1) {
        int t = (threadIdx.x >= o) ? sm[threadIdx.x - o] : 0;
        __syncthreads();
        sm[threadIdx.x] += t;
        __syncthreads();
    }
    if (threadIdx.x < nb) bsum[threadIdx.x] = sm[threadIdx.x] - v;
}

__global__ void scanC_kernel(const int* __restrict__ icnt, const int* __restrict__ bsum,
                             int* __restrict__ off, int E) {
    __shared__ int sm[256];
    int base = blockIdx.x * SCAN_ITEMS + threadIdx.x * 4;
    int v[4], ex[4];
    int s = 0;
#pragma unroll
    for (int t = 0; t < 4; t++) {
        int i = base + t;
        v[t] = (i < NSEG) ? icnt[i] : 0;
        ex[t] = s;
        s += v[t];
    }
    int mine = s;
    sm[threadIdx.x] = s;
    __syncthreads();
    for (int o = 1; o < 256; o <<= 1) {
        int t = (threadIdx.x >= o) ? sm[threadIdx.x - o] : 0;
        __syncthreads();
        sm[threadIdx.x] += t;
        __syncthreads();
    }
    int tex = sm[threadIdx.x] - mine;
    int b0 = bsum[blockIdx.x];
#pragma unroll
    for (int t = 0; t < 4; t++) {
        int i = base + t;
        if (i < NSEG) off[i] = b0 + tex + ex[t];
    }
    if (blockIdx.x == 0 && threadIdx.x == 0) off[NSEG] = E;
}

__global__ void place_kernel(const int* __restrict__ src, const int* __restrict__ dst,
                             const int* __restrict__ et, int E,
                             const int* __restrict__ off, int* __restrict__ pcur,
                             int* __restrict__ ebuf) {
    int i = blockIdx.x * blockDim.x + threadIdx.x;
    if (i >= E) return;
    int seg = dst[i] * NRL + et[i];
    int p = off[seg] + atomicAdd(&pcur[seg], 1);
    ebuf[p] = src[i];
}

// ---- X fp32 -> bf16 hi/lo planes ----
__global__ void convx_kernel(const float* __restrict__ X, __nv_bfloat16* __restrict__ xh,
                             __nv_bfloat16* __restrict__ xl, long n2) {
    long i = (long)blockIdx.x * blockDim.x + threadIdx.x;
    if (i >= n2) return;
    float2 v = reinterpret_cast<const float2*>(X)[i];
    unsigned h, l;
    split2(v.x, v.y, h, l);
    reinterpret_cast<unsigned*>(xh)[i] = h;
    reinterpret_cast<unsigned*>(xl)[i] = l;
}

// ---- B = [W ; root] transposed to [o][k] bf16 hi/lo planes ----
__global__ void prepB_kernel(const float* __restrict__ W, const float* __restrict__ root,
                             int KA, int KT,
                             __nv_bfloat16* __restrict__ Bth, __nv_bfloat16* __restrict__ Btl) {
    int i = blockIdx.x * blockDim.x + threadIdx.x;
    int tot = 128 * (KT / 2);
    if (i >= tot) return;
    int o = i / (KT / 2);
    int k = (i % (KT / 2)) * 2;
    float b0 = (k < KA) ? W[(long)k * 128 + o] : root[(long)(k - KA) * 128 + o];
    float b1 = (k + 1 < KA) ? W[(long)(k + 1) * 128 + o] : root[(long)(k + 1 - KA) * 128 + o];
    unsigned h, l;
    split2(b0, b1, h, l);
    *reinterpret_cast<unsigned*>(&Bth[(long)o * KT + k]) = h;
    *reinterpret_cast<unsigned*>(&Btl[(long)o * KT + k]) = l;
}

// ---- segmented mean -> bf16 hi/lo planes, no atomics, fast paths by count ----
template <int DIN>
__global__ void __launch_bounds__(256)
segsum_kernel(const int* __restrict__ ebuf, const int* __restrict__ off,
              const float* __restrict__ X,
              const __nv_bfloat16* __restrict__ xh, const __nv_bfloat16* __restrict__ xl,
              __nv_bfloat16* __restrict__ aggh, __nv_bfloat16* __restrict__ aggl) {
    const int L = DIN / 4;
    const int SPB = 256 / L;
    long s = (long)blockIdx.x * SPB + threadIdx.x / L;
    if (s >= NSEG) return;
    int l = threadIdx.x % L;
    int b = off[s], e = off[s + 1];
    int n = e - b;
    uint2* ph = reinterpret_cast<uint2*>(aggh + s * DIN) + l;
    uint2* pl = reinterpret_cast<uint2*>(aggl + s * DIN) + l;
    if (n == 0) {
        *ph = make_uint2(0u, 0u);
        *pl = make_uint2(0u, 0u);
        return;
    }
    if (n == 1) {
        long sid = __ldg(&ebuf[b]);
        *ph = __ldg(reinterpret_cast<const uint2*>(xh + sid * DIN) + l);
        *pl = __ldg(reinterpret_cast<const uint2*>(xl + sid * DIN) + l);
        return;
    }
    float4 acc = make_float4(0.f, 0.f, 0.f, 0.f);
    for (int i = b; i < e; i++) {
        long sid = __ldg(&ebuf[i]);
        float4 v = __ldg(reinterpret_cast<const float4*>(X + sid * DIN) + l);
        acc.x += v.x; acc.y += v.y; acc.z += v.z; acc.w += v.w;
    }
    float sc = 1.f / (float)n;
    acc.x *= sc; acc.y *= sc; acc.z *= sc; acc.w *= sc;
    uint2 h, lo;
    split2(acc.x, acc.y, h.x, lo.x);
    split2(acc.z, acc.w, h.y, lo.y);
    *ph = h;
    *pl = lo;
}

#define MMA_BF16(ACC, A, B0, B1)                                              \
    asm volatile(                                                             \
        "mma.sync.aligned.m16n8k16.row.col.f32.bf16.bf16.f32 "                \
        "{%0,%1,%2,%3}, {%4,%5,%6,%7}, {%8,%9}, {%0,%1,%2,%3};"               \
        : "+f"((ACC)[0]), "+f"((ACC)[1]), "+f"((ACC)[2]), "+f"((ACC)[3])      \
        : "r"((A)[0]), "r"((A)[1]), "r"((A)[2]), "r"((A)[3]),                 \
          "r"(B0), "r"(B1))

// C[NN,128] = [mean | X] @ B + bias; all operands pre-split bf16 hi/lo.
// 3-pass emulation: acc += Ah*Bh + Ah*Bl + Al*Bh (fp32 accumulate).
template <int DIN>
__global__ void __launch_bounds__(256)
gemm_mma_kernel(const __nv_bfloat16* __restrict__ aggh, const __nv_bfloat16* __restrict__ aggl,
                const __nv_bfloat16* __restrict__ xh, const __nv_bfloat16* __restrict__ xl,
                const __nv_bfloat16* __restrict__ Btgh, const __nv_bfloat16* __restrict__ Btgl,
                const float* __restrict__ bias, float* __restrict__ C, int relu) {
    const int KA = NRL * DIN;
    const int KT = KA + DIN;
    const int BK = 32;

    __shared__ __align__(16) __nv_bfloat16 Ah[128][40];
    __shared__ __align__(16) __nv_bfloat16 Al[128][40];
    __shared__ __align__(16) __nv_bfloat16 Bth[128][40];   // [n][k]
    __shared__ __align__(16) __nv_bfloat16 Btl[128][40];

    int tid = threadIdx.x;
    int wid = tid >> 5;
    int lane = tid & 31;
    int wm = wid & 3;
    int wn = wid >> 2;
    int bm = blockIdx.x * 128;

    int lg = lane >> 2;
    int lq = lane & 3;

    float acc[2][8][4];
#pragma unroll
    for (int ma = 0; ma < 2; ma++)
#pragma unroll
        for (int na = 0; na < 8; na++)
#pragma unroll
            for (int r = 0; r < 4; r++) acc[ma][na][r] = 0.f;

    for (int k0 = 0; k0 < KT; k0 += BK) {
        // A tile: uint4 = 8 bf16 per global load (matches the 8-element stride),
        // stored as two 8-byte halves (row pad 40 els keeps 8B alignment).
#pragma unroll
        for (int p = 0; p < 2; p++) {
            int idx = p * 256 + tid;
            int r = idx >> 2;
            int c8 = (idx & 3) * 8;
            int n = bm + r;
            int k = k0 + c8;
            uint4 vh = make_uint4(0u, 0u, 0u, 0u), vl = make_uint4(0u, 0u, 0u, 0u);
            if (n < NN) {
                if (k < KA) {
                    vh = *reinterpret_cast<const uint4*>(aggh + (long)n * KA + k);
                    vl = *reinterpret_cast<const uint4*>(aggl + (long)n * KA + k);
                } else {
                    vh = *reinterpret_cast<const uint4*>(xh + (long)n * DIN + (k - KA));
                    vl = *reinterpret_cast<const uint4*>(xl + (long)n * DIN + (k - KA));
                }
            }
            *reinterpret_cast<uint2*>(&Ah[r][c8])     = make_uint2(vh.x, vh.y);
            *reinterpret_cast<uint2*>(&Ah[r][c8 + 4]) = make_uint2(vh.z, vh.w);
            *reinterpret_cast<uint2*>(&Al[r][c8])     = make_uint2(vl.x, vl.y);
            *reinterpret_cast<uint2*>(&Al[r][c8 + 4]) = make_uint2(vl.z, vl.w);
        }
        // B tile from pre-transposed planes (same width fix)
#pragma unroll
        for (int p = 0; p < 2; p++) {
            int idx = p * 256 + tid;
            int nr = idx >> 2;
            int k8 = (idx & 3) * 8;
            uint4 vh = *reinterpret_cast<const uint4*>(Btgh + (long)nr * KT + k0 + k8);
            uint4 vl = *reinterpret_cast<const uint4*>(Btgl + (long)nr * KT + k0 + k8);
            *reinterpret_cast<uint2*>(&Bth[nr][k8])     = make_uint2(vh.x, vh.y);
            *reinterpret_cast<uint2*>(&Bth[nr][k8 + 4]) = make_uint2(vh.z, vh.w);
            *reinterpret_cast<uint2*>(&Btl[nr][k8])     = make_uint2(vl.x, vl.y);
            *reinterpret_cast<uint2*>(&Btl[nr][k8 + 4]) = make_uint2(vl.z, vl.w);
        }
        __syncthreads();

#pragma unroll
        for (int ks = 0; ks < BK; ks += 16) {
            unsigned ah[2][4], al[2][4];
#pragma unroll
            for (int ma = 0; ma < 2; ma++) {
                int r0 = wm * 32 + ma * 16 + lg;
                int kc = ks + lq * 2;
                ah[ma][0] = *reinterpret_cast<unsigned*>(&Ah[r0][kc]);
                ah[ma][1] = *reinterpret_cast<unsigned*>(&Ah[r0 + 8][kc]);
                ah[ma][2] = *reinterpret_cast<unsigned*>(&Ah[r0][kc + 8]);
                ah[ma][3] = *reinterpret_cast<unsigned*>(&Ah[r0 + 8][kc + 8]);
                al[ma][0] = *reinterpret_cast<unsigned*>(&Al[r0][kc]);
                al[ma][1] = *reinterpret_cast<unsigned*>(&Al[r0 + 8][kc]);
                al[ma][2] = *reinterpret_cast<unsigned*>(&Al[r0][kc + 8]);
                al[ma][3] = *reinterpret_cast<unsigned*>(&Al[r0 + 8][kc + 8]);
            }
            unsigned bh0[8], bh1[8], bl0[8], bl1[8];
#pragma unroll
            for (int na = 0; na < 8; na++) {
                int nb = wn * 64 + na * 8 + lg;
                int kl = ks + lq * 2;
                bh0[na] = *reinterpret_cast<unsigned*>(&Bth[nb][kl]);
                bh1[na] = *reinterpret_cast<unsigned*>(&Bth[nb][kl + 8]);
                bl0[na] = *reinterpret_cast<unsigned*>(&Btl[nb][kl]);
                bl1[na] = *reinterpret_cast<unsigned*>(&Btl[nb][kl + 8]);
            }
#pragma unroll
            for (int na = 0; na < 8; na++)
#pragma unroll
                for (int ma = 0; ma < 2; ma++)
                    MMA_BF16(acc[ma][na], ah[ma], bh0[na], bh1[na]);
#pragma unroll
            for (int na = 0; na < 8; na++)
#pragma unroll
                for (int ma = 0; ma < 2; ma++)
                    MMA_BF16(acc[ma][na], ah[ma], bl0[na], bl1[na]);
#pragma unroll
            for (int na = 0; na < 8; na++)
#pragma unroll
                for (int ma = 0; ma < 2; ma++)
                    MMA_BF16(acc[ma][na], al[ma], bh0[na], bh1[na]);
        }
        __syncthreads();
    }

#pragma unroll
    for (int ma = 0; ma < 2; ma++) {
#pragma unroll
        for (int na = 0; na < 8; na++) {
            int col = wn * 64 + na * 8 + lq * 2;
            float2 bv = *reinterpret_cast<const float2*>(&bias[col]);
            float v0 = acc[ma][na][0] + bv.x;
            float v1 = acc[ma][na][1] + bv.y;
            float v2 = acc[ma][na][2] + bv.x;
            float v3 = acc[ma][na][3] + bv.y;
            if (relu) {
                v0 = fmaxf(v0, 0.f); v1 = fmaxf(v1, 0.f);
                v2 = fmaxf(v2, 0.f); v3 = fmaxf(v3, 0.f);
            }
            int row0 = bm + wm * 32 + ma * 16 + lg;
            int row1 = row0 + 8;
            if (row0 < NN)
                *reinterpret_cast<float2*>(&C[(long)row0 * DHID + col]) = make_float2(v0, v1);
            if (row1 < NN)
                *reinterpret_cast<float2*>(&C[(long)row1 * DHID + col]) = make_float2(v2, v3);
        }
    }
}

__global__ void decoder_kernel(const int* __restrict__ head, const int* __restrict__ tail,
                               const int* __restrict__ rel, const float* __restrict__ h,
                               const float* __restrict__ rel_emb, float* __restrict__ out,
                               int Bn) {
    int warp = (blockIdx.x * blockDim.x + threadIdx.x) >> 5;
    int lane = threadIdx.x & 31;
    if (warp >= Bn) return;
    const float4* hp = reinterpret_cast<const float4*>(h + (long)head[warp] * DHID);
    const float4* tp = reinterpret_cast<const float4*>(h + (long)tail[warp] * DHID);
    const float4* rp = reinterpret_cast<const float4*>(rel_emb + (long)rel[warp] * DHID);
    float4 a = hp[lane], b = tp[lane], c = rp[lane];
    float s = a.x * b.x * c.x + a.y * b.y * c.y + a.z * b.z * c.z + a.w * b.w * c.w;
#pragma unroll
    for (int o = 16; o; o >>= 1) s += __shfl_xor_sync(0xffffffffu, s, o);
    if (lane == 0) out[warp] = s;
}

extern "C" void kernel_launch(void* const* d_in, const int* in_sizes, int n_in,
                              void* d_out, int out_size) {
    const int*   edge_index = (const int*)d_in[0];
    const int*   edge_type  = (const int*)d_in[1];
    const int*   head       = (const int*)d_in[2];
    const int*   tail       = (const int*)d_in[3];
    const int*   rel        = (const int*)d_in[4];
    const float* node_emb   = (const float*)d_in[5];
    const float* W1         = (const float*)d_in[6];
    const float* root1      = (const float*)d_in[7];
    const float* b1         = (const float*)d_in[8];
    const float* W2         = (const float*)d_in[9];
    const float* root2      = (const float*)d_in[10];
    const float* b2         = (const float*)d_in[11];
    const float* rel_emb    = (const float*)d_in[12];

    int E = in_sizes[0] / 2;
    const int* src = edge_index;
    const int* dst = edge_index + E;

    __nv_bfloat16 *aggh, *aggl, *xh, *xl, *Bth, *Btl;
    float *h1, *h2;
    int *icnt, *off, *pcur, *bsum, *ebuf;
    cudaGetSymbolAddress((void**)&aggh, g_aggh);
    cudaGetSymbolAddress((void**)&aggl, g_aggl);
    cudaGetSymbolAddress((void**)&xh, g_xh);
    cudaGetSymbolAddress((void**)&xl, g_xl);
    cudaGetSymbolAddress((void**)&Bth, g_Bth);
    cudaGetSymbolAddress((void**)&Btl, g_Btl);
    cudaGetSymbolAddress((void**)&h1, g_h1);
    cudaGetSymbolAddress((void**)&h2, g_h2);
    cudaGetSymbolAddress((void**)&icnt, g_icnt);
    cudaGetSymbolAddress((void**)&off, g_off);
    cudaGetSymbolAddress((void**)&pcur, g_pcur);
    cudaGetSymbolAddress((void**)&bsum, g_bsum);
    cudaGetSymbolAddress((void**)&ebuf, g_ebuf);

    const int T = 256;
    const int KA1 = NRL * DEMB, KT1 = KA1 + DEMB;
    const int KA2 = NRL * DHID, KT2 = KA2 + DHID;

    // ---- counting sort of edges by segment (graph fixed; shared by both layers)
    zero_kernel<<<512, T>>>((float4*)icnt, NSEG / 4);
    zero_kernel<<<512, T>>>((float4*)pcur, NSEG / 4);
    seg_count_kernel<<<(E + T - 1) / T, T>>>(dst, edge_type, E, icnt);
    scanA_kernel<<<SCAN_NB, T>>>(icnt, bsum);
    scanB_kernel<<<1, 1024>>>(bsum, SCAN_NB);
    scanC_kernel<<<SCAN_NB, T>>>(icnt, bsum, off, E);
    place_kernel<<<(E + T - 1) / T, T>>>(src, dst, edge_type, E, off, pcur, ebuf);

    // ---- layer 1
    {
        long n2 = (long)NN * DEMB / 2;
        convx_kernel<<<(unsigned)((n2 + T - 1) / T), T>>>(node_emb, xh, xl, n2);
    }
    prepB_kernel<<<(128 * KT1 / 2 + T - 1) / T, T>>>(W1, root1, KA1, KT1, Bth, Btl);
    segsum_kernel<DEMB><<<(NSEG + 15) / 16, T>>>(ebuf, off, node_emb, xh, xl, aggh, aggl);
    gemm_mma_kernel<DEMB><<<(NN + 127) / 128, T>>>(aggh, aggl, xh, xl, Bth, Btl, b1, h1, 1);

    // ---- layer 2
    {
        long n2 = (long)NN * DHID / 2;
        convx_kernel<<<(unsigned)((n2 + T - 1) / T), T>>>(h1, xh, xl, n2);
    }
    prepB_kernel<<<(128 * KT2 / 2 + T - 1) / T, T>>>(W2, root2, KA2, KT2, Bth, Btl);
    segsum_kernel<DHID><<<(NSEG + 7) / 8, T>>>(ebuf, off, h1, xh, xl, aggh, aggl);
    gemm_mma_kernel<DHID><<<(NN + 127) / 128, T>>>(aggh, aggl, xh, xl, Bth, Btl, b2, h2, 0);

    // ---- DistMult decoder
    int Bn = in_sizes[2];
    decoder_kernel<<<(Bn * 32 + T - 1) / T, T>>>(head, tail, rel, h2, rel_emb,
                                                 (float*)d_out, Bn);
}

// round 8
// speedup vs baseline: 1.9207x; 1.1532x over previous
#include <cuda_runtime.h>
#include <cuda_bf16.h>

#define NN    50000
#define NRL   20
#define DEMB  64
#define DHID  128
#define EMAX  1600000
#define NSEG  (NN * NRL)          // 1,000,000 segments

// Static scratch (no allocations allowed). 16-byte aligned for uint4 access.
__device__ __align__(16) float g_h1[(long)NN * DHID];               // 25.6 MB
__device__ __align__(16) float g_h2[(long)NN * DHID];               // 25.6 MB
__device__ __align__(16) __nv_bfloat16 g_xh[(long)NN * DHID];       // X hi (per layer)
__device__ __align__(16) __nv_bfloat16 g_xl[(long)NN * DHID];       // X lo
__device__ __align__(16) __nv_bfloat16 g_Bth[128 * (NRL * DHID + DHID)];  // B^T hi [o][k]
__device__ __align__(16) __nv_bfloat16 g_Btl[128 * (NRL * DHID + DHID)];  // B^T lo
__device__ int   g_icnt[NSEG];
__device__ int   g_off[NSEG + 4];
__device__ int   g_pcur[NSEG];
__device__ int   g_bsum[1024];
__device__ int   g_ebuf[EMAX];

#define SCAN_ITEMS 1024
#define SCAN_NB    ((NSEG + SCAN_ITEMS - 1) / SCAN_ITEMS)   // 977

// Split a = hi + lo: hi = exact 16-bit truncation, lo = residual rounded to bf16.
__device__ __forceinline__ void split2(float a, float b, unsigned& h, unsigned& l) {
    unsigned ua = __float_as_uint(a), ub = __float_as_uint(b);
    h = __byte_perm(ua, ub, 0x7632);             // low16 = hi16(a), high16 = hi16(b)
    float la = a - __uint_as_float(ua & 0xFFFF0000u);
    float lb = b - __uint_as_float(ub & 0xFFFF0000u);
    __nv_bfloat162 p = __float22bfloat162_rn(make_float2(la, lb));
    l = *reinterpret_cast<unsigned*>(&p);
}

__global__ void zero_kernel(float4* p, long n4) {
    long i = (long)blockIdx.x * blockDim.x + threadIdx.x;
    long stride = (long)gridDim.x * blockDim.x;
    float4 z = make_float4(0.f, 0.f, 0.f, 0.f);
    for (; i < n4; i += stride) p[i] = z;
}

__global__ void seg_count_kernel(const int* __restrict__ dst, const int* __restrict__ et,
                                 int E, int* __restrict__ icnt) {
    int i = blockIdx.x * blockDim.x + threadIdx.x;
    if (i < E) atomicAdd(&icnt[dst[i] * NRL + et[i]], 1);
}

// ---- 3-kernel exclusive scan over icnt -> off ----
__global__ void scanA_kernel(const int* __restrict__ icnt, int* __restrict__ bsum) {
    __shared__ int sd[256];
    int base = blockIdx.x * SCAN_ITEMS + threadIdx.x * 4;
    int s = 0;
#pragma unroll
    for (int t = 0; t < 4; t++) {
        int i = base + t;
        if (i < NSEG) s += icnt[i];
    }
    sd[threadIdx.x] = s;
    __syncthreads();
    for (int o = 128; o; o >>= 1) {
        if (threadIdx.x < o) sd[threadIdx.x] += sd[threadIdx.x + o];
        __syncthreads();
    }
    if (threadIdx.x == 0) bsum[blockIdx.x] = sd[0];
}

__global__ void scanB_kernel(int* __restrict__ bsum, int nb) {
    __shared__ int sm[1024];
    int v = (threadIdx.x < nb) ? bsum[threadIdx.x] : 0;
    sm[threadIdx.x] = v;
    __syncthreads();
    for (int o = 1; o < 1024; o <<= 1) {
        int t = (threadIdx.x >= o) ? sm[threadIdx.x - o] : 0;
        __syncthreads();
        sm[threadIdx.x] += t;
        __syncthreads();
    }
    if (threadIdx.x < nb) bsum[threadIdx.x] = sm[threadIdx.x] - v;
}

__global__ void scanC_kernel(const int* __restrict__ icnt, const int* __restrict__ bsum,
                             int* __restrict__ off, int E) {
    __shared__ int sm[256];
    int base = blockIdx.x * SCAN_ITEMS + threadIdx.x * 4;
    int v[4], ex[4];
    int s = 0;
#pragma unroll
    for (int t = 0; t < 4; t++) {
        int i = base + t;
        v[t] = (i < NSEG) ? icnt[i] : 0;
        ex[t] = s;
        s += v[t];
    }
    int mine = s;
    sm[threadIdx.x] = s;
    __syncthreads();
    for (int o = 1; o < 256; o <<= 1) {
        int t = (threadIdx.x >= o) ? sm[threadIdx.x - o] : 0;
        __syncthreads();
        sm[threadIdx.x] += t;
        __syncthreads();
    }
    int tex = sm[threadIdx.x] - mine;
    int b0 = bsum[blockIdx.x];
#pragma unroll
    for (int t = 0; t < 4; t++) {
        int i = base + t;
        if (i < NSEG) off[i] = b0 + tex + ex[t];
    }
    if (blockIdx.x == 0 && threadIdx.x == 0) off[NSEG] = E;
}

__global__ void place_kernel(const int* __restrict__ src, const int* __restrict__ dst,
                             const int* __restrict__ et, int E,
                             const int* __restrict__ off, int* __restrict__ pcur,
                             int* __restrict__ ebuf) {
    int i = blockIdx.x * blockDim.x + threadIdx.x;
    if (i >= E) return;
    int seg = dst[i] * NRL + et[i];
    int p = off[seg] + atomicAdd(&pcur[seg], 1);
    ebuf[p] = src[i];
}

// ---- X fp32 -> bf16 hi/lo planes ----
__global__ void convx_kernel(const float* __restrict__ X, __nv_bfloat16* __restrict__ xh,
                             __nv_bfloat16* __restrict__ xl, long n2) {
    long i = (long)blockIdx.x * blockDim.x + threadIdx.x;
    if (i >= n2) return;
    float2 v = reinterpret_cast<const float2*>(X)[i];
    unsigned h, l;
    split2(v.x, v.y, h, l);
    reinterpret_cast<unsigned*>(xh)[i] = h;
    reinterpret_cast<unsigned*>(xl)[i] = l;
}

// ---- B = [W ; root] transposed to [o][k] bf16 hi/lo planes ----
__global__ void prepB_kernel(const float* __restrict__ W, const float* __restrict__ root,
                             int KA, int KT,
                             __nv_bfloat16* __restrict__ Bth, __nv_bfloat16* __restrict__ Btl) {
    int i = blockIdx.x * blockDim.x + threadIdx.x;
    int tot = 128 * (KT / 2);
    if (i >= tot) return;
    int o = i / (KT / 2);
    int k = (i % (KT / 2)) * 2;
    float b0 = (k < KA) ? W[(long)k * 128 + o] : root[(long)(k - KA) * 128 + o];
    float b1 = (k + 1 < KA) ? W[(long)(k + 1) * 128 + o] : root[(long)(k + 1 - KA) * 128 + o];
    unsigned h, l;
    split2(b0, b1, h, l);
    *reinterpret_cast<unsigned*>(&Bth[(long)o * KT + k]) = h;
    *reinterpret_cast<unsigned*>(&Btl[(long)o * KT + k]) = l;
}

#define MMA_BF16(ACC, A, B0, B1)                                              \
    asm volatile(                                                             \
        "mma.sync.aligned.m16n8k16.row.col.f32.bf16.bf16.f32 "                \
        "{%0,%1,%2,%3}, {%4,%5,%6,%7}, {%8,%9}, {%0,%1,%2,%3};"               \
        : "+f"((ACC)[0]), "+f"((ACC)[1]), "+f"((ACC)[2]), "+f"((ACC)[3])      \
        : "r"((A)[0]), "r"((A)[1]), "r"((A)[2]), "r"((A)[3]),                 \
          "r"(B0), "r"(B1))

// FUSED: per 128-node block, for each rel chunk r=0..20 gather+mean the A tile
// directly into shared (no agg materialization), then MMA that DIN-wide chunk.
// 3-pass bf16 split emulation accumulating fp32 across all 21 chunks.
template <int DIN>
__global__ void __launch_bounds__(512, 1)
fused_gemm_kernel(const int* __restrict__ ebuf, const int* __restrict__ off,
                  const float* __restrict__ X,
                  const __nv_bfloat16* __restrict__ xh, const __nv_bfloat16* __restrict__ xl,
                  const __nv_bfloat16* __restrict__ Btgh, const __nv_bfloat16* __restrict__ Btgl,
                  const float* __restrict__ bias, float* __restrict__ C, int relu) {
    const int KT = NRL * DIN + DIN;
    const int PITCH = DIN + 8;

    extern __shared__ __align__(16) char smraw[];
    __nv_bfloat16* Ah  = reinterpret_cast<__nv_bfloat16*>(smraw);
    __nv_bfloat16* Al  = Ah  + 128 * PITCH;
    __nv_bfloat16* Bth = Al  + 128 * PITCH;
    __nv_bfloat16* Btl = Bth + 128 * PITCH;

    int tid = threadIdx.x;
    int wid = tid >> 5;
    int lane = tid & 31;
    int wm = wid & 3;        // warp row tile (32 rows)
    int wn = wid >> 2;       // warp col tile (32 cols)
    int bm = blockIdx.x * 128;
    int lg = lane >> 2;
    int lq = lane & 3;

    float acc[2][4][4];
#pragma unroll
    for (int ma = 0; ma < 2; ma++)
#pragma unroll
        for (int na = 0; na < 4; na++)
#pragma unroll
            for (int r = 0; r < 4; r++) acc[ma][na][r] = 0.f;

    for (int rel = 0; rel <= NRL; rel++) {
        // ---- load B chunk [128 out][DIN k] from pre-transposed planes
        {
            const int ELS = 128 * (DIN / 8);
            for (int idx = tid; idx < ELS; idx += 512) {
                int nr = idx / (DIN / 8);
                int c8 = (idx % (DIN / 8)) * 8;
                long go = (long)nr * KT + rel * DIN + c8;
                uint4 vh = *reinterpret_cast<const uint4*>(Btgh + go);
                uint4 vl = *reinterpret_cast<const uint4*>(Btgl + go);
                __nv_bfloat16* ph = Bth + nr * PITCH + c8;
                __nv_bfloat16* pl = Btl + nr * PITCH + c8;
                *reinterpret_cast<uint2*>(ph)     = make_uint2(vh.x, vh.y);
                *reinterpret_cast<uint2*>(ph + 4) = make_uint2(vh.z, vh.w);
                *reinterpret_cast<uint2*>(pl)     = make_uint2(vl.x, vl.y);
                *reinterpret_cast<uint2*>(pl + 4) = make_uint2(vl.z, vl.w);
            }
        }
        // ---- build A chunk: rel<NRL -> gathered mean; rel==NRL -> X rows (root)
        if (rel < NRL) {
            const int L = DIN / 4;            // lanes per node (16 or 32)
            const int G = 512 / L;            // nodes in parallel
            int g = tid / L, l = tid % L;
#pragma unroll
            for (int it = 0; it < 128 / G; it++) {
                int node = it * G + g;
                int gn = bm + node;
                uint2 h = make_uint2(0u, 0u), lo = make_uint2(0u, 0u);
                if (gn < NN) {
                    int s = gn * NRL + rel;
                    int b = __ldg(&off[s]), e = __ldg(&off[s + 1]);
                    int n = e - b;
                    if (n == 1) {
                        long sid = __ldg(&ebuf[b]);
                        h  = __ldg(reinterpret_cast<const uint2*>(xh + sid * DIN) + l);
                        lo = __ldg(reinterpret_cast<const uint2*>(xl + sid * DIN) + l);
                    } else if (n >= 2) {
                        float4 a = make_float4(0.f, 0.f, 0.f, 0.f);
                        for (int i = b; i < e; i++) {
                            long sid = __ldg(&ebuf[i]);
                            float4 v = __ldg(reinterpret_cast<const float4*>(X + sid * DIN) + l);
                            a.x += v.x; a.y += v.y; a.z += v.z; a.w += v.w;
                        }
                        float sc = 1.f / (float)n;
                        a.x *= sc; a.y *= sc; a.z *= sc; a.w *= sc;
                        split2(a.x, a.y, h.x, lo.x);
                        split2(a.z, a.w, h.y, lo.y);
                    }
                }
                *reinterpret_cast<uint2*>(Ah + node * PITCH + l * 4) = h;
                *reinterpret_cast<uint2*>(Al + node * PITCH + l * 4) = lo;
            }
        } else {
            const int ELS = 128 * (DIN / 8);
            for (int idx = tid; idx < ELS; idx += 512) {
                int node = idx / (DIN / 8);
                int c8 = (idx % (DIN / 8)) * 8;
                int gn = bm + node;
                uint4 vh = make_uint4(0u, 0u, 0u, 0u), vl = make_uint4(0u, 0u, 0u, 0u);
                if (gn < NN) {
                    vh = *reinterpret_cast<const uint4*>(xh + (long)gn * DIN + c8);
                    vl = *reinterpret_cast<const uint4*>(xl + (long)gn * DIN + c8);
                }
                __nv_bfloat16* ph = Ah + node * PITCH + c8;
                __nv_bfloat16* pl = Al + node * PITCH + c8;
                *reinterpret_cast<uint2*>(ph)     = make_uint2(vh.x, vh.y);
                *reinterpret_cast<uint2*>(ph + 4) = make_uint2(vh.z, vh.w);
                *reinterpret_cast<uint2*>(pl)     = make_uint2(vl.x, vl.y);
                *reinterpret_cast<uint2*>(pl + 4) = make_uint2(vl.z, vl.w);
            }
        }
        __syncthreads();

        // ---- MMA over this DIN-wide chunk
#pragma unroll
        for (int ks = 0; ks < DIN; ks += 16) {
            unsigned ah[2][4], al[2][4];
#pragma unroll
            for (int ma = 0; ma < 2; ma++) {
                int r0 = wm * 32 + ma * 16 + lg;
                int kc = ks + lq * 2;
                const __nv_bfloat16* pa = Ah + r0 * PITCH + kc;
                const __nv_bfloat16* pb = Al + r0 * PITCH + kc;
                ah[ma][0] = *reinterpret_cast<const unsigned*>(pa);
                ah[ma][1] = *reinterpret_cast<const unsigned*>(pa + 8 * PITCH);
                ah[ma][2] = *reinterpret_cast<const unsigned*>(pa + 8);
                ah[ma][3] = *reinterpret_cast<const unsigned*>(pa + 8 * PITCH + 8);
                al[ma][0] = *reinterpret_cast<const unsigned*>(pb);
                al[ma][1] = *reinterpret_cast<const unsigned*>(pb + 8 * PITCH);
                al[ma][2] = *reinterpret_cast<const unsigned*>(pb + 8);
                al[ma][3] = *reinterpret_cast<const unsigned*>(pb + 8 * PITCH + 8);
            }
            unsigned bh0[4], bh1[4], bl0[4], bl1[4];
#pragma unroll
            for (int na = 0; na < 4; na++) {
                int nb = wn * 32 + na * 8 + lg;
                int kl = ks + lq * 2;
                const __nv_bfloat16* ph = Bth + nb * PITCH + kl;
                const __nv_bfloat16* pl = Btl + nb * PITCH + kl;
                bh0[na] = *reinterpret_cast<const unsigned*>(ph);
                bh1[na] = *reinterpret_cast<const unsigned*>(ph + 8);
                bl0[na] = *reinterpret_cast<const unsigned*>(pl);
                bl1[na] = *reinterpret_cast<const unsigned*>(pl + 8);
            }
#pragma unroll
            for (int na = 0; na < 4; na++)
#pragma unroll
                for (int ma = 0; ma < 2; ma++)
                    MMA_BF16(acc[ma][na], ah[ma], bh0[na], bh1[na]);
#pragma unroll
            for (int na = 0; na < 4; na++)
#pragma unroll
                for (int ma = 0; ma < 2; ma++)
                    MMA_BF16(acc[ma][na], ah[ma], bl0[na], bl1[na]);
#pragma unroll
            for (int na = 0; na < 4; na++)
#pragma unroll
                for (int ma = 0; ma < 2; ma++)
                    MMA_BF16(acc[ma][na], al[ma], bh0[na], bh1[na]);
        }
        __syncthreads();
    }

    // ---- epilogue
#pragma unroll
    for (int ma = 0; ma < 2; ma++) {
#pragma unroll
        for (int na = 0; na < 4; na++) {
            int col = wn * 32 + na * 8 + lq * 2;
            float2 bv = *reinterpret_cast<const float2*>(&bias[col]);
            float v0 = acc[ma][na][0] + bv.x;
            float v1 = acc[ma][na][1] + bv.y;
            float v2 = acc[ma][na][2] + bv.x;
            float v3 = acc[ma][na][3] + bv.y;
            if (relu) {
                v0 = fmaxf(v0, 0.f); v1 = fmaxf(v1, 0.f);
                v2 = fmaxf(v2, 0.f); v3 = fmaxf(v3, 0.f);
            }
            int row0 = bm + wm * 32 + ma * 16 + lg;
            int row1 = row0 + 8;
            if (row0 < NN)
                *reinterpret_cast<float2*>(&C[(long)row0 * DHID + col]) = make_float2(v0, v1);
            if (row1 < NN)
                *reinterpret_cast<float2*>(&C[(long)row1 * DHID + col]) = make_float2(v2, v3);
        }
    }
}

__global__ void decoder_kernel(const int* __restrict__ head, const int* __restrict__ tail,
                               const int* __restrict__ rel, const float* __restrict__ h,
                               const float* __restrict__ rel_emb, float* __restrict__ out,
                               int Bn) {
    int warp = (blockIdx.x * blockDim.x + threadIdx.x) >> 5;
    int lane = threadIdx.x & 31;
    if (warp >= Bn) return;
    const float4* hp = reinterpret_cast<const float4*>(h + (long)head[warp] * DHID);
    const float4* tp = reinterpret_cast<const float4*>(h + (long)tail[warp] * DHID);
    const float4* rp = reinterpret_cast<const float4*>(rel_emb + (long)rel[warp] * DHID);
    float4 a = hp[lane], b = tp[lane], c = rp[lane];
    float s = a.x * b.x * c.x + a.y * b.y * c.y + a.z * b.z * c.z + a.w * b.w * c.w;
#pragma unroll
    for (int o = 16; o; o >>= 1) s += __shfl_xor_sync(0xffffffffu, s, o);
    if (lane == 0) out[warp] = s;
}

extern "C" void kernel_launch(void* const* d_in, const int* in_sizes, int n_in,
                              void* d_out, int out_size) {
    const int*   edge_index = (const int*)d_in[0];
    const int*   edge_type  = (const int*)d_in[1];
    const int*   head       = (const int*)d_in[2];
    const int*   tail       = (const int*)d_in[3];
    const int*   rel        = (const int*)d_in[4];
    const float* node_emb   = (const float*)d_in[5];
    const float* W1         = (const float*)d_in[6];
    const float* root1      = (const float*)d_in[7];
    const float* b1         = (const float*)d_in[8];
    const float* W2         = (const float*)d_in[9];
    const float* root2      = (const float*)d_in[10];
    const float* b2         = (const float*)d_in[11];
    const float* rel_emb    = (const float*)d_in[12];

    int E = in_sizes[0] / 2;
    const int* src = edge_index;
    const int* dst = edge_index + E;

    __nv_bfloat16 *xh, *xl, *Bth, *Btl;
    float *h1, *h2;
    int *icnt, *off, *pcur, *bsum, *ebuf;
    cudaGetSymbolAddress((void**)&xh, g_xh);
    cudaGetSymbolAddress((void**)&xl, g_xl);
    cudaGetSymbolAddress((void**)&Bth, g_Bth);
    cudaGetSymbolAddress((void**)&Btl, g_Btl);
    cudaGetSymbolAddress((void**)&h1, g_h1);
    cudaGetSymbolAddress((void**)&h2, g_h2);
    cudaGetSymbolAddress((void**)&icnt, g_icnt);
    cudaGetSymbolAddress((void**)&off, g_off);
    cudaGetSymbolAddress((void**)&pcur, g_pcur);
    cudaGetSymbolAddress((void**)&bsum, g_bsum);
    cudaGetSymbolAddress((void**)&ebuf, g_ebuf);

    const int T = 256;
    const int KA1 = NRL * DEMB, KT1 = KA1 + DEMB;
    const int KA2 = NRL * DHID, KT2 = KA2 + DHID;
    const int SM1 = 1024 * (DEMB + 8);   // 73728 B
    const int SM2 = 1024 * (DHID + 8);   // 139264 B

    cudaFuncSetAttribute(fused_gemm_kernel<DEMB>,
                         cudaFuncAttributeMaxDynamicSharedMemorySize, SM1);
    cudaFuncSetAttribute(fused_gemm_kernel<DHID>,
                         cudaFuncAttributeMaxDynamicSharedMemorySize, SM2);

    // ---- counting sort of edges by segment (graph fixed; shared by both layers)
    zero_kernel<<<512, T>>>((float4*)icnt, NSEG / 4);
    zero_kernel<<<512, T>>>((float4*)pcur, NSEG / 4);
    seg_count_kernel<<<(E + T - 1) / T, T>>>(dst, edge_type, E, icnt);
    scanA_kernel<<<SCAN_NB, T>>>(icnt, bsum);
    scanB_kernel<<<1, 1024>>>(bsum, SCAN_NB);
    scanC_kernel<<<SCAN_NB, T>>>(icnt, bsum, off, E);
    place_kernel<<<(E + T - 1) / T, T>>>(src, dst, edge_type, E, off, pcur, ebuf);

    // ---- layer 1 (fused gather+GEMM)
    {
        long n2 = (long)NN * DEMB / 2;
        convx_kernel<<<(unsigned)((n2 + T - 1) / T), T>>>(node_emb, xh, xl, n2);
    }
    prepB_kernel<<<(128 * KT1 / 2 + T - 1) / T, T>>>(W1, root1, KA1, KT1, Bth, Btl);
    fused_gemm_kernel<DEMB><<<(NN + 127) / 128, 512, SM1>>>(
        ebuf, off, node_emb, xh, xl, Bth, Btl, b1, h1, 1);

    // ---- layer 2
    {
        long n2 = (long)NN * DHID / 2;
        convx_kernel<<<(unsigned)((n2 + T - 1) / T), T>>>(h1, xh, xl, n2);
    }
    prepB_kernel<<<(128 * KT2 / 2 + T - 1) / T, T>>>(W2, root2, KA2, KT2, Bth, Btl);
    fused_gemm_kernel<DHID><<<(NN + 127) / 128, 512, SM2>>>(
        ebuf, off, h1, xh, xl, Bth, Btl, b2, h2, 0);

    // ---- DistMult decoder
    int Bn = in_sizes[2];
    decoder_kernel<<<(Bn * 32 + T - 1) / T, T>>>(head, tail, rel, h2, rel_emb,
                                                 (float*)d_out, Bn);
}

// round 10
// speedup vs baseline: 2.1652x; 1.1273x over previous
#include <cuda_runtime.h>
#include <cuda_bf16.h>
#include <cstdint>

#define NN    50000
#define NRL   20
#define DEMB  64
#define DHID  128
#define EMAX  1600000
#define NSEG  (NN * NRL)

// Static scratch (no allocations allowed). 16-byte aligned for uint4 access.
__device__ __align__(16) float g_h1[(long)NN * DHID];
__device__ __align__(16) float g_h2[(long)NN * DHID];
__device__ __align__(16) __nv_bfloat16 g_xh[(long)NN * DHID];    // layer-1 input planes
__device__ __align__(16) __nv_bfloat16 g_xl[(long)NN * DHID];
__device__ __align__(16) __nv_bfloat16 g_yh[(long)NN * DHID];    // layer-2 input planes (h1)
__device__ __align__(16) __nv_bfloat16 g_yl[(long)NN * DHID];
__device__ __align__(16) __nv_bfloat16 g_Bth[128 * (NRL * DHID + DHID)];  // B^T hi [o][k]
__device__ __align__(16) __nv_bfloat16 g_Btl[128 * (NRL * DHID + DHID)];  // B^T lo
__device__ int   g_icnt[NSEG];
__device__ int   g_off[NSEG + 4];
__device__ int   g_pcur[NSEG];
__device__ int   g_bsum[1024];
__device__ int   g_ebuf[EMAX];

#define SCAN_ITEMS 1024
#define SCAN_NB    ((NSEG + SCAN_ITEMS - 1) / SCAN_ITEMS)

// Split a = hi + lo: hi = exact truncation to bf16, lo = residual rounded.
__device__ __forceinline__ void split2(float a, float b, unsigned& h, unsigned& l) {
    unsigned ua = __float_as_uint(a), ub = __float_as_uint(b);
    h = __byte_perm(ua, ub, 0x7632);
    float la = a - __uint_as_float(ua & 0xFFFF0000u);
    float lb = b - __uint_as_float(ub & 0xFFFF0000u);
    __nv_bfloat162 p = __float22bfloat162_rn(make_float2(la, lb));
    l = *reinterpret_cast<unsigned*>(&p);
}

__global__ void zero_kernel(float4* p, long n4) {
    long i = (long)blockIdx.x * blockDim.x + threadIdx.x;
    long stride = (long)gridDim.x * blockDim.x;
    float4 z = make_float4(0.f, 0.f, 0.f, 0.f);
    for (; i < n4; i += stride) p[i] = z;
}

__global__ void seg_count_kernel(const int* __restrict__ dst, const int* __restrict__ et,
                                 int E, int* __restrict__ icnt) {
    int i = blockIdx.x * blockDim.x + threadIdx.x;
    if (i < E) atomicAdd(&icnt[dst[i] * NRL + et[i]], 1);
}

__global__ void scanA_kernel(const int* __restrict__ icnt, int* __restrict__ bsum) {
    __shared__ int sd[256];
    int base = blockIdx.x * SCAN_ITEMS + threadIdx.x * 4;
    int s = 0;
#pragma unroll
    for (int t = 0; t < 4; t++) { int i = base + t; if (i < NSEG) s += icnt[i]; }
    sd[threadIdx.x] = s;
    __syncthreads();
    for (int o = 128; o; o >>= 1) {
        if (threadIdx.x < o) sd[threadIdx.x] += sd[threadIdx.x + o];
        __syncthreads();
    }
    if (threadIdx.x == 0) bsum[blockIdx.x] = sd[0];
}

__global__ void scanB_kernel(int* __restrict__ bsum, int nb) {
    __shared__ int sm[1024];
    int v = (threadIdx.x < nb) ? bsum[threadIdx.x] : 0;
    sm[threadIdx.x] = v;
    __syncthreads();
    for (int o = 1; o < 1024; o <<= 1) {
        int t = (threadIdx.x >= o) ? sm[threadIdx.x - o] : 0;
        __syncthreads();
        sm[threadIdx.x] += t;
        __syncthreads();
    }
    if (threadIdx.x < nb) bsum[threadIdx.x] = sm[threadIdx.x] - v;
}

__global__ void scanC_kernel(const int* __restrict__ icnt, const int* __restrict__ bsum,
                             int* __restrict__ off, int E) {
    __shared__ int sm[256];
    int base = blockIdx.x * SCAN_ITEMS + threadIdx.x * 4;
    int v[4], ex[4];
    int s = 0;
#pragma unroll
    for (int t = 0; t < 4; t++) {
        int i = base + t;
        v[t] = (i < NSEG) ? icnt[i] : 0;
        ex[t] = s;
        s += v[t];
    }
    int mine = s;
    sm[threadIdx.x] = s;
    __syncthreads();
    for (int o = 1; o < 256; o <<= 1) {
        int t = (threadIdx.x >= o) ? sm[threadIdx.x - o] : 0;
        __syncthreads();
        sm[threadIdx.x] += t;
        __syncthreads();
    }
    int tex = sm[threadIdx.x] - mine;
    int b0 = bsum[blockIdx.x];
#pragma unroll
    for (int t = 0; t < 4; t++) {
        int i = base + t;
        if (i < NSEG) off[i] = b0 + tex + ex[t];
    }
    if (blockIdx.x == 0 && threadIdx.x == 0) off[NSEG] = E;
}

__global__ void place_kernel(const int* __restrict__ src, const int* __restrict__ dst,
                             const int* __restrict__ et, int E,
                             const int* __restrict__ off, int* __restrict__ pcur,
                             int* __restrict__ ebuf) {
    int i = blockIdx.x * blockDim.x + threadIdx.x;
    if (i >= E) return;
    int seg = dst[i] * NRL + et[i];
    int p = off[seg] + atomicAdd(&pcur[seg], 1);
    ebuf[p] = src[i];
}

__global__ void convx_kernel(const float* __restrict__ X, __nv_bfloat16* __restrict__ xh,
                             __nv_bfloat16* __restrict__ xl, long n2) {
    long i = (long)blockIdx.x * blockDim.x + threadIdx.x;
    if (i >= n2) return;
    float2 v = reinterpret_cast<const float2*>(X)[i];
    unsigned h, l;
    split2(v.x, v.y, h, l);
    reinterpret_cast<unsigned*>(xh)[i] = h;
    reinterpret_cast<unsigned*>(xl)[i] = l;
}

__global__ void prepB_kernel(const float* __restrict__ W, const float* __restrict__ root,
                             int KA, int KT,
                             __nv_bfloat16* __restrict__ Bth, __nv_bfloat16* __restrict__ Btl) {
    int i = blockIdx.x * blockDim.x + threadIdx.x;
    int tot = 128 * (KT / 2);
    if (i >= tot) return;
    int o = i / (KT / 2);
    int k = (i % (KT / 2)) * 2;
    float b0 = (k < KA) ? W[(long)k * 128 + o] : root[(long)(k - KA) * 128 + o];
    float b1 = (k + 1 < KA) ? W[(long)(k + 1) * 128 + o] : root[(long)(k + 1 - KA) * 128 + o];
    unsigned h, l;
    split2(b0, b1, h, l);
    *reinterpret_cast<unsigned*>(&Bth[(long)o * KT + k]) = h;
    *reinterpret_cast<unsigned*>(&Btl[(long)o * KT + k]) = l;
}

#define MMA_BF16(ACC, A, B0, B1)                                              \
    asm volatile(                                                             \
        "mma.sync.aligned.m16n8k16.row.col.f32.bf16.bf16.f32 "                \
        "{%0,%1,%2,%3}, {%4,%5,%6,%7}, {%8,%9}, {%0,%1,%2,%3};"               \
        : "+f"((ACC)[0]), "+f"((ACC)[1]), "+f"((ACC)[2]), "+f"((ACC)[3])      \
        : "r"((A)[0]), "r"((A)[1]), "r"((A)[2]), "r"((A)[3]),                 \
          "r"(B0), "r"(B1))

// FUSED gather+GEMM, M-tile = 64 rows, 256 threads, ~55/104 KB smem ->
// 2+ blocks per SM so one block's gather overlaps another's MMA phase.
// WS=1: epilogue also writes bf16 hi/lo planes of the output (layer-2 input).
template <int DIN, int WS>
__global__ void __launch_bounds__(256)
fused_gemm_kernel(const int* __restrict__ ebuf, const int* __restrict__ off,
                  const float* __restrict__ X,
                  const __nv_bfloat16* __restrict__ xh, const __nv_bfloat16* __restrict__ xl,
                  const __nv_bfloat16* __restrict__ Btgh, const __nv_bfloat16* __restrict__ Btgl,
                  const float* __restrict__ bias, float* __restrict__ C,
                  __nv_bfloat16* __restrict__ Ch, __nv_bfloat16* __restrict__ Cl, int relu) {
    const int KT = NRL * DIN + DIN;
    const int PITCH = DIN + 8;

    extern __shared__ __align__(16) char smraw[];
    __nv_bfloat16* Ah  = reinterpret_cast<__nv_bfloat16*>(smraw);
    __nv_bfloat16* Al  = Ah  + 64 * PITCH;
    __nv_bfloat16* Bth = Al  + 64 * PITCH;
    __nv_bfloat16* Btl = Bth + 128 * PITCH;

    int tid = threadIdx.x;
    int wid = tid >> 5;
    int lane = tid & 31;
    int wm = wid & 1;        // warp row tile (32 rows)
    int wn = wid >> 1;       // warp col tile (32 cols)
    int bm = blockIdx.x * 64;
    int lg = lane >> 2;
    int lq = lane & 3;

    float acc[2][4][4];
#pragma unroll
    for (int ma = 0; ma < 2; ma++)
#pragma unroll
        for (int na = 0; na < 4; na++)
#pragma unroll
            for (int r = 0; r < 4; r++) acc[ma][na][r] = 0.f;

    for (int rel = 0; rel <= NRL; rel++) {
        // ---- B chunk [128 out][DIN] from pre-transposed planes
        {
            const int ELS = 128 * (DIN / 8);
            for (int idx = tid; idx < ELS; idx += 256) {
                int nr = idx / (DIN / 8);
                int c8 = (idx % (DIN / 8)) * 8;
                long go = (long)nr * KT + rel * DIN + c8;
                uint4 vh = *reinterpret_cast<const uint4*>(Btgh + go);
                uint4 vl = *reinterpret_cast<const uint4*>(Btgl + go);
                __nv_bfloat16* ph = Bth + nr * PITCH + c8;
                __nv_bfloat16* pl = Btl + nr * PITCH + c8;
                *reinterpret_cast<uint2*>(ph)     = make_uint2(vh.x, vh.y);
                *reinterpret_cast<uint2*>(ph + 4) = make_uint2(vh.z, vh.w);
                *reinterpret_cast<uint2*>(pl)     = make_uint2(vl.x, vl.y);
                *reinterpret_cast<uint2*>(pl + 4) = make_uint2(vl.z, vl.w);
            }
        }
        // ---- A chunk: rel<NRL gathered mean; rel==NRL X rows (root term)
        if (rel < NRL) {
            const int L = DIN / 4;            // lanes per node (16 or 32)
            const int G = 256 / L;            // nodes in parallel (16 or 8)
            int g = tid / L, l = tid % L;
#pragma unroll
            for (int it = 0; it < 64 / G; it++) {
                int node = it * G + g;
                int gn = bm + node;
                uint2 h = make_uint2(0u, 0u), lo = make_uint2(0u, 0u);
                if (gn < NN) {
                    int s = gn * NRL + rel;
                    int b = __ldg(&off[s]), e = __ldg(&off[s + 1]);
                    int n = e - b;
                    if (n == 1) {
                        long sid = __ldg(&ebuf[b]);
                        h  = __ldg(reinterpret_cast<const uint2*>(xh + sid * DIN) + l);
                        lo = __ldg(reinterpret_cast<const uint2*>(xl + sid * DIN) + l);
                    } else if (n >= 2) {
                        float4 a = make_float4(0.f, 0.f, 0.f, 0.f);
                        int i = b;
                        for (; i + 1 < e; i += 2) {        // 2-way MLP
                            long s0 = __ldg(&ebuf[i]);
                            long s1 = __ldg(&ebuf[i + 1]);
                            float4 v0 = __ldg(reinterpret_cast<const float4*>(X + s0 * DIN) + l);
                            float4 v1 = __ldg(reinterpret_cast<const float4*>(X + s1 * DIN) + l);
                            a.x += v0.x + v1.x; a.y += v0.y + v1.y;
                            a.z += v0.z + v1.z; a.w += v0.w + v1.w;
                        }
                        if (i < e) {
                            long s0 = __ldg(&ebuf[i]);
                            float4 v0 = __ldg(reinterpret_cast<const float4*>(X + s0 * DIN) + l);
                            a.x += v0.x; a.y += v0.y; a.z += v0.z; a.w += v0.w;
                        }
                        float sc = 1.f / (float)n;
                        a.x *= sc; a.y *= sc; a.z *= sc; a.w *= sc;
                        split2(a.x, a.y, h.x, lo.x);
                        split2(a.z, a.w, h.y, lo.y);
                    }
                }
                *reinterpret_cast<uint2*>(Ah + node * PITCH + l * 4) = h;
                *reinterpret_cast<uint2*>(Al + node * PITCH + l * 4) = lo;
            }
        } else {
            const int ELS = 64 * (DIN / 8);
            for (int idx = tid; idx < ELS; idx += 256) {
                int node = idx / (DIN / 8);
                int c8 = (idx % (DIN / 8)) * 8;
                int gn = bm + node;
                uint4 vh = make_uint4(0u, 0u, 0u, 0u), vl = make_uint4(0u, 0u, 0u, 0u);
                if (gn < NN) {
                    vh = *reinterpret_cast<const uint4*>(xh + (long)gn * DIN + c8);
                    vl = *reinterpret_cast<const uint4*>(xl + (long)gn * DIN + c8);
                }
                __nv_bfloat16* ph = Ah + node * PITCH + c8;
                __nv_bfloat16* pl = Al + node * PITCH + c8;
                *reinterpret_cast<uint2*>(ph)     = make_uint2(vh.x, vh.y);
                *reinterpret_cast<uint2*>(ph + 4) = make_uint2(vh.z, vh.w);
                *reinterpret_cast<uint2*>(pl)     = make_uint2(vl.x, vl.y);
                *reinterpret_cast<uint2*>(pl + 4) = make_uint2(vl.z, vl.w);
            }
        }
        __syncthreads();

        // ---- MMA over this DIN-wide chunk (3-pass bf16 split)
#pragma unroll
        for (int ks = 0; ks < DIN; ks += 16) {
            unsigned ah[2][4], al[2][4];
#pragma unroll
            for (int ma = 0; ma < 2; ma++) {
                int r0 = wm * 32 + ma * 16 + lg;
                int kc = ks + lq * 2;
                const __nv_bfloat16* pa = Ah + r0 * PITCH + kc;
                const __nv_bfloat16* pb = Al + r0 * PITCH + kc;
                ah[ma][0] = *reinterpret_cast<const unsigned*>(pa);
                ah[ma][1] = *reinterpret_cast<const unsigned*>(pa + 8 * PITCH);
                ah[ma][2] = *reinterpret_cast<const unsigned*>(pa + 8);
                ah[ma][3] = *reinterpret_cast<const unsigned*>(pa + 8 * PITCH + 8);
                al[ma][0] = *reinterpret_cast<const unsigned*>(pb);
                al[ma][1] = *reinterpret_cast<const unsigned*>(pb + 8 * PITCH);
                al[ma][2] = *reinterpret_cast<const unsigned*>(pb + 8);
                al[ma][3] = *reinterpret_cast<const unsigned*>(pb + 8 * PITCH + 8);
            }
            unsigned bh0[4], bh1[4], bl0[4], bl1[4];
#pragma unroll
            for (int na = 0; na < 4; na++) {
                int nb = wn * 32 + na * 8 + lg;
                int kl = ks + lq * 2;
                const __nv_bfloat16* ph = Bth + nb * PITCH + kl;
                const __nv_bfloat16* pl = Btl + nb * PITCH + kl;
                bh0[na] = *reinterpret_cast<const unsigned*>(ph);
                bh1[na] = *reinterpret_cast<const unsigned*>(ph + 8);
                bl0[na] = *reinterpret_cast<const unsigned*>(pl);
                bl1[na] = *reinterpret_cast<const unsigned*>(pl + 8);
            }
#pragma unroll
            for (int na = 0; na < 4; na++)
#pragma unroll
                for (int ma = 0; ma < 2; ma++)
                    MMA_BF16(acc[ma][na], ah[ma], bh0[na], bh1[na]);
#pragma unroll
            for (int na = 0; na < 4; na++)
#pragma unroll
                for (int ma = 0; ma < 2; ma++)
                    MMA_BF16(acc[ma][na], ah[ma], bl0[na], bl1[na]);
#pragma unroll
            for (int na = 0; na < 4; na++)
#pragma unroll
                for (int ma = 0; ma < 2; ma++)
                    MMA_BF16(acc[ma][na], al[ma], bh0[na], bh1[na]);
        }
        __syncthreads();
    }

    // ---- epilogue: bias(+ReLU), store C; WS=1 also stores bf16 split planes
#pragma unroll
    for (int ma = 0; ma < 2; ma++) {
#pragma unroll
        for (int na = 0; na < 4; na++) {
            int col = wn * 32 + na * 8 + lq * 2;
            float2 bv = *reinterpret_cast<const float2*>(&bias[col]);
            float v0 = acc[ma][na][0] + bv.x;
            float v1 = acc[ma][na][1] + bv.y;
            float v2 = acc[ma][na][2] + bv.x;
            float v3 = acc[ma][na][3] + bv.y;
            if (relu) {
                v0 = fmaxf(v0, 0.f); v1 = fmaxf(v1, 0.f);
                v2 = fmaxf(v2, 0.f); v3 = fmaxf(v3, 0.f);
            }
            int row0 = bm + wm * 32 + ma * 16 + lg;
            int row1 = row0 + 8;
            if (row0 < NN) {
                *reinterpret_cast<float2*>(&C[(long)row0 * DHID + col]) = make_float2(v0, v1);
                if (WS) {
                    unsigned h, l;
                    split2(v0, v1, h, l);
                    *reinterpret_cast<unsigned*>(&Ch[(long)row0 * DHID + col]) = h;
                    *reinterpret_cast<unsigned*>(&Cl[(long)row0 * DHID + col]) = l;
                }
            }
            if (row1 < NN) {
                *reinterpret_cast<float2*>(&C[(long)row1 * DHID + col]) = make_float2(v2, v3);
                if (WS) {
                    unsigned h, l;
                    split2(v2, v3, h, l);
                    *reinterpret_cast<unsigned*>(&Ch[(long)row1 * DHID + col]) = h;
                    *reinterpret_cast<unsigned*>(&Cl[(long)row1 * DHID + col]) = l;
                }
            }
        }
    }
}

__global__ void decoder_kernel(const int* __restrict__ head, const int* __restrict__ tail,
                               const int* __restrict__ rel, const float* __restrict__ h,
                               const float* __restrict__ rel_emb, float* __restrict__ out,
                               int Bn) {
    int warp = (blockIdx.x * blockDim.x + threadIdx.x) >> 5;
    int lane = threadIdx.x & 31;
    if (warp >= Bn) return;
    const float4* hp = reinterpret_cast<const float4*>(h + (long)head[warp] * DHID);
    const float4* tp = reinterpret_cast<const float4*>(h + (long)tail[warp] * DHID);
    const float4* rp = reinterpret_cast<const float4*>(rel_emb + (long)rel[warp] * DHID);
    float4 a = hp[lane], b = tp[lane], c = rp[lane];
    float s = a.x * b.x * c.x + a.y * b.y * c.y + a.z * b.z * c.z + a.w * b.w * c.w;
#pragma unroll
    for (int o = 16; o; o >>= 1) s += __shfl_xor_sync(0xffffffffu, s, o);
    if (lane == 0) out[warp] = s;
}

extern "C" void kernel_launch(void* const* d_in, const int* in_sizes, int n_in,
                              void* d_out, int out_size) {
    const int*   edge_index = (const int*)d_in[0];
    const int*   edge_type  = (const int*)d_in[1];
    const int*   head       = (const int*)d_in[2];
    const int*   tail       = (const int*)d_in[3];
    const int*   rel        = (const int*)d_in[4];
    const float* node_emb   = (const float*)d_in[5];
    const float* W1         = (const float*)d_in[6];
    const float* root1      = (const float*)d_in[7];
    const float* b1         = (const float*)d_in[8];
    const float* W2         = (const float*)d_in[9];
    const float* root2      = (const float*)d_in[10];
    const float* b2         = (const float*)d_in[11];
    const float* rel_emb    = (const float*)d_in[12];

    int E = in_sizes[0] / 2;
    const int* src = edge_index;
    const int* dst = edge_index + E;

    __nv_bfloat16 *xh, *xl, *yh, *yl, *Bth, *Btl;
    float *h1, *h2;
    int *icnt, *off, *pcur, *bsum, *ebuf;
    cudaGetSymbolAddress((void**)&xh, g_xh);
    cudaGetSymbolAddress((void**)&xl, g_xl);
    cudaGetSymbolAddress((void**)&yh, g_yh);
    cudaGetSymbolAddress((void**)&yl, g_yl);
    cudaGetSymbolAddress((void**)&Bth, g_Bth);
    cudaGetSymbolAddress((void**)&Btl, g_Btl);
    cudaGetSymbolAddress((void**)&h1, g_h1);
    cudaGetSymbolAddress((void**)&h2, g_h2);
    cudaGetSymbolAddress((void**)&icnt, g_icnt);
    cudaGetSymbolAddress((void**)&off, g_off);
    cudaGetSymbolAddress((void**)&pcur, g_pcur);
    cudaGetSymbolAddress((void**)&bsum, g_bsum);
    cudaGetSymbolAddress((void**)&ebuf, g_ebuf);

    const int T = 256;
    const int KA1 = NRL * DEMB, KT1 = KA1 + DEMB;
    const int KA2 = NRL * DHID, KT2 = KA2 + DHID;
    // smem: (64 + 64 + 128 + 128) rows x PITCH x 2B
    const int SM1 = 384 * (DEMB + 8) * 2;    // 55296 B  -> 3-4 blocks/SM
    const int SM2 = 384 * (DHID + 8) * 2;    // 104448 B -> 2 blocks/SM

    cudaFuncSetAttribute((const void*)fused_gemm_kernel<DEMB, 1>,
                         cudaFuncAttributeMaxDynamicSharedMemorySize, SM1);
    cudaFuncSetAttribute((const void*)fused_gemm_kernel<DHID, 0>,
                         cudaFuncAttributeMaxDynamicSharedMemorySize, SM2);

    // ---- counting sort of edges by segment (graph fixed; shared by both layers)
    zero_kernel<<<512, T>>>((float4*)icnt, NSEG / 4);
    zero_kernel<<<512, T>>>((float4*)pcur, NSEG / 4);
    seg_count_kernel<<<(E + T - 1) / T, T>>>(dst, edge_type, E, icnt);
    scanA_kernel<<<SCAN_NB, T>>>(icnt, bsum);
    scanB_kernel<<<1, 1024>>>(bsum, SCAN_NB);
    scanC_kernel<<<SCAN_NB, T>>>(icnt, bsum, off, E);
    place_kernel<<<(E + T - 1) / T, T>>>(src, dst, edge_type, E, off, pcur, ebuf);

    // ---- layer 1 (fused gather+GEMM; epilogue emits h1 planes for layer 2)
    {
        long n2 = (long)NN * DEMB / 2;
        convx_kernel<<<(unsigned)((n2 + T - 1) / T), T>>>(node_emb, xh, xl, n2);
    }
    prepB_kernel<<<(128 * KT1 / 2 + T - 1) / T, T>>>(W1, root1, KA1, KT1, Bth, Btl);
    fused_gemm_kernel<DEMB, 1><<<(NN + 63) / 64, 256, SM1>>>(
        ebuf, off, node_emb, xh, xl, Bth, Btl, b1, h1, yh, yl, 1);

    // ---- layer 2
    prepB_kernel<<<(128 * KT2 / 2 + T - 1) / T, T>>>(W2, root2, KA2, KT2, Bth, Btl);
    fused_gemm_kernel<DHID, 0><<<(NN + 63) / 64, 256, SM2>>>(
        ebuf, off, h1, yh, yl, Bth, Btl, b2, h2, nullptr, nullptr, 0);

    // ---- DistMult decoder
    int Bn = in_sizes[2];
    decoder_kernel<<<(Bn * 32 + T - 1) / T, T>>>(head, tail, rel, h2, rel_emb,
                                                 (float*)d_out, Bn);
}

// round 11
// speedup vs baseline: 2.2109x; 1.0211x over previous
#include <cuda_runtime.h>
#include <cuda_bf16.h>
#include <cstdint>

#define NN    50000
#define NRL   20
#define DEMB  64
#define DHID  128
#define EMAX  1600000
#define NSEG  (NN * NRL)

// Static scratch (no allocations allowed). 16-byte aligned for uint4 access.
__device__ __align__(16) float g_h1[(long)NN * DHID];
__device__ __align__(16) float g_h2[(long)NN * DHID];
__device__ __align__(16) __nv_bfloat16 g_xh[(long)NN * DHID];    // layer-1 input planes
__device__ __align__(16) __nv_bfloat16 g_xl[(long)NN * DHID];
__device__ __align__(16) __nv_bfloat16 g_yh[(long)NN * DHID];    // layer-2 input planes (h1)
__device__ __align__(16) __nv_bfloat16 g_yl[(long)NN * DHID];
__device__ __align__(16) __nv_bfloat16 g_Bth[128 * (NRL * DHID + DHID)];  // B^T hi [o][k]
__device__ __align__(16) __nv_bfloat16 g_Btl[128 * (NRL * DHID + DHID)];  // B^T lo
__device__ int   g_icnt[NSEG];
__device__ int   g_off[NSEG + 4];
__device__ int   g_pcur[NSEG];
__device__ int   g_bsum[1024];
__device__ int   g_ebuf[EMAX];

#define SCAN_ITEMS 1024
#define SCAN_NB    ((NSEG + SCAN_ITEMS - 1) / SCAN_ITEMS)

// Split a = hi + lo: hi = exact truncation to bf16, lo = residual rounded.
__device__ __forceinline__ void split2(float a, float b, unsigned& h, unsigned& l) {
    unsigned ua = __float_as_uint(a), ub = __float_as_uint(b);
    h = __byte_perm(ua, ub, 0x7632);
    float la = a - __uint_as_float(ua & 0xFFFF0000u);
    float lb = b - __uint_as_float(ub & 0xFFFF0000u);
    __nv_bfloat162 p = __float22bfloat162_rn(make_float2(la, lb));
    l = *reinterpret_cast<unsigned*>(&p);
}

__global__ void zero_kernel(float4* p, long n4) {
    long i = (long)blockIdx.x * blockDim.x + threadIdx.x;
    long stride = (long)gridDim.x * blockDim.x;
    float4 z = make_float4(0.f, 0.f, 0.f, 0.f);
    for (; i < n4; i += stride) p[i] = z;
}

__global__ void seg_count_kernel(const int* __restrict__ dst, const int* __restrict__ et,
                                 int E, int* __restrict__ icnt) {
    int i = blockIdx.x * blockDim.x + threadIdx.x;
    if (i < E) atomicAdd(&icnt[dst[i] * NRL + et[i]], 1);
}

__global__ void scanA_kernel(const int* __restrict__ icnt, int* __restrict__ bsum) {
    __shared__ int sd[256];
    int base = blockIdx.x * SCAN_ITEMS + threadIdx.x * 4;
    int s = 0;
#pragma unroll
    for (int t = 0; t < 4; t++) { int i = base + t; if (i < NSEG) s += icnt[i]; }
    sd[threadIdx.x] = s;
    __syncthreads();
    for (int o = 128; o; o >>= 1) {
        if (threadIdx.x < o) sd[threadIdx.x] += sd[threadIdx.x + o];
        __syncthreads();
    }
    if (threadIdx.x == 0) bsum[blockIdx.x] = sd[0];
}

__global__ void scanB_kernel(int* __restrict__ bsum, int nb) {
    __shared__ int sm[1024];
    int v = (threadIdx.x < nb) ? bsum[threadIdx.x] : 0;
    sm[threadIdx.x] = v;
    __syncthreads();
    for (int o = 1; o < 1024; o <<= 1) {
        int t = (threadIdx.x >= o) ? sm[threadIdx.x - o] : 0;
        __syncthreads();
        sm[threadIdx.x] += t;
        __syncthreads();
    }
    if (threadIdx.x < nb) bsum[threadIdx.x] = sm[threadIdx.x] - v;
}

__global__ void scanC_kernel(const int* __restrict__ icnt, const int* __restrict__ bsum,
                             int* __restrict__ off, int E) {
    __shared__ int sm[256];
    int base = blockIdx.x * SCAN_ITEMS + threadIdx.x * 4;
    int v[4], ex[4];
    int s = 0;
#pragma unroll
    for (int t = 0; t < 4; t++) {
        int i = base + t;
        v[t] = (i < NSEG) ? icnt[i] : 0;
        ex[t] = s;
        s += v[t];
    }
    int mine = s;
    sm[threadIdx.x] = s;
    __syncthreads();
    for (int o = 1; o < 256; o <<= 1) {
        int t = (threadIdx.x >= o) ? sm[threadIdx.x - o] : 0;
        __syncthreads();
        sm[threadIdx.x] += t;
        __syncthreads();
    }
    int tex = sm[threadIdx.x] - mine;
    int b0 = bsum[blockIdx.x];
#pragma unroll
    for (int t = 0; t < 4; t++) {
        int i = base + t;
        if (i < NSEG) off[i] = b0 + tex + ex[t];
    }
    if (blockIdx.x == 0 && threadIdx.x == 0) off[NSEG] = E;
}

__global__ void place_kernel(const int* __restrict__ src, const int* __restrict__ dst,
                             const int* __restrict__ et, int E,
                             const int* __restrict__ off, int* __restrict__ pcur,
                             int* __restrict__ ebuf) {
    int i = blockIdx.x * blockDim.x + threadIdx.x;
    if (i >= E) return;
    int seg = dst[i] * NRL + et[i];
    int p = off[seg] + atomicAdd(&pcur[seg], 1);
    ebuf[p] = src[i];
}

__global__ void convx_kernel(const float* __restrict__ X, __nv_bfloat16* __restrict__ xh,
                             __nv_bfloat16* __restrict__ xl, long n2) {
    long i = (long)blockIdx.x * blockDim.x + threadIdx.x;
    if (i >= n2) return;
    float2 v = reinterpret_cast<const float2*>(X)[i];
    unsigned h, l;
    split2(v.x, v.y, h, l);
    reinterpret_cast<unsigned*>(xh)[i] = h;
    reinterpret_cast<unsigned*>(xl)[i] = l;
}

__global__ void prepB_kernel(const float* __restrict__ W, const float* __restrict__ root,
                             int KA, int KT,
                             __nv_bfloat16* __restrict__ Bth, __nv_bfloat16* __restrict__ Btl) {
    int i = blockIdx.x * blockDim.x + threadIdx.x;
    int tot = 128 * (KT / 2);
    if (i >= tot) return;
    int o = i / (KT / 2);
    int k = (i % (KT / 2)) * 2;
    float b0 = (k < KA) ? W[(long)k * 128 + o] : root[(long)(k - KA) * 128 + o];
    float b1 = (k + 1 < KA) ? W[(long)(k + 1) * 128 + o] : root[(long)(k + 1 - KA) * 128 + o];
    unsigned h, l;
    split2(b0, b1, h, l);
    *reinterpret_cast<unsigned*>(&Bth[(long)o * KT + k]) = h;
    *reinterpret_cast<unsigned*>(&Btl[(long)o * KT + k]) = l;
}

#define MMA_BF16(ACC, A, B0, B1)                                              \
    asm volatile(                                                             \
        "mma.sync.aligned.m16n8k16.row.col.f32.bf16.bf16.f32 "                \
        "{%0,%1,%2,%3}, {%4,%5,%6,%7}, {%8,%9}, {%0,%1,%2,%3};"               \
        : "+f"((ACC)[0]), "+f"((ACC)[1]), "+f"((ACC)[2]), "+f"((ACC)[3])      \
        : "r"((A)[0]), "r"((A)[1]), "r"((A)[2]), "r"((A)[3]),                 \
          "r"(B0), "r"(B1))

// FUSED gather+GEMM, M-tile = 64 rows, 256 threads, 2 blocks/SM for overlap.
// Gather latency chain broken by: smem-cached off[], register-staged segment
// bounds, next-segment ebuf prefetch, and 1-ahead ebuf lookahead in edge loop.
template <int DIN, int WS>
__global__ void __launch_bounds__(256, 2)
fused_gemm_kernel(const int* __restrict__ ebuf, const int* __restrict__ off,
                  const float* __restrict__ X,
                  const __nv_bfloat16* __restrict__ xh, const __nv_bfloat16* __restrict__ xl,
                  const __nv_bfloat16* __restrict__ Btgh, const __nv_bfloat16* __restrict__ Btgl,
                  const float* __restrict__ bias, float* __restrict__ C,
                  __nv_bfloat16* __restrict__ Ch, __nv_bfloat16* __restrict__ Cl, int relu) {
    const int KT = NRL * DIN + DIN;
    const int PITCH = DIN + 8;
    const int L = DIN / 4;            // lanes per node (16 or 32)
    const int G = 256 / L;            // nodes gathered in parallel (16 or 8)
    const int NIT = 64 / G;           // segments per thread per chunk (4 or 8)

    extern __shared__ __align__(16) char smraw[];
    __nv_bfloat16* Ah  = reinterpret_cast<__nv_bfloat16*>(smraw);
    __nv_bfloat16* Al  = Ah  + 64 * PITCH;
    __nv_bfloat16* Bth = Al  + 64 * PITCH;
    __nv_bfloat16* Btl = Bth + 128 * PITCH;
    int* s_off = reinterpret_cast<int*>(Btl + 128 * PITCH);   // 64*NRL+1 ints

    int tid = threadIdx.x;
    int wid = tid >> 5;
    int lane = tid & 31;
    int wm = wid & 1;        // warp row tile (32 rows)
    int wn = wid >> 1;       // warp col tile (32 cols)
    int bm = blockIdx.x * 64;
    int lg = lane >> 2;
    int lq = lane & 3;

    // ---- cache this block's off[] slice (contiguous, coalesced)
    {
        int nvalid = (NN - bm < 64) ? (NN - bm) : 64;
        int cnt = nvalid * NRL + 1;
        int base = bm * NRL;
        for (int i = tid; i < cnt; i += 256) s_off[i] = off[base + i];
    }
    __syncthreads();

    float acc[2][4][4];
#pragma unroll
    for (int ma = 0; ma < 2; ma++)
#pragma unroll
        for (int na = 0; na < 4; na++)
#pragma unroll
            for (int r = 0; r < 4; r++) acc[ma][na][r] = 0.f;

    for (int rel = 0; rel <= NRL; rel++) {
        // ---- B chunk [128 out][DIN] from pre-transposed planes
        {
            const int ELS = 128 * (DIN / 8);
            for (int idx = tid; idx < ELS; idx += 256) {
                int nr = idx / (DIN / 8);
                int c8 = (idx % (DIN / 8)) * 8;
                long go = (long)nr * KT + rel * DIN + c8;
                uint4 vh = *reinterpret_cast<const uint4*>(Btgh + go);
                uint4 vl = *reinterpret_cast<const uint4*>(Btgl + go);
                __nv_bfloat16* ph = Bth + nr * PITCH + c8;
                __nv_bfloat16* pl = Btl + nr * PITCH + c8;
                *reinterpret_cast<uint2*>(ph)     = make_uint2(vh.x, vh.y);
                *reinterpret_cast<uint2*>(ph + 4) = make_uint2(vh.z, vh.w);
                *reinterpret_cast<uint2*>(pl)     = make_uint2(vl.x, vl.y);
                *reinterpret_cast<uint2*>(pl + 4) = make_uint2(vl.z, vl.w);
            }
        }
        // ---- A chunk: rel<NRL gathered mean; rel==NRL X rows (root term)
        if (rel < NRL) {
            int g = tid / L, l = tid % L;
            // stage segment bounds from smem (cheap LDS)
            int bs[NIT], ns[NIT];
#pragma unroll
            for (int it = 0; it < NIT; it++) {
                int node = it * G + g;
                int gn = bm + node;
                int s = node * NRL + rel;
                int bb = s_off[s];
                int ee = s_off[s + 1];
                bs[it] = bb;
                ns[it] = (gn < NN) ? (ee - bb) : 0;
            }
            // prefetch first ebuf index of segment 0
            int pre = (ns[0] > 0) ? __ldg(&ebuf[bs[0]]) : 0;
#pragma unroll
            for (int it = 0; it < NIT; it++) {
                int node = it * G + g;
                int first = pre;
                if (it + 1 < NIT)
                    pre = (ns[it + 1] > 0) ? __ldg(&ebuf[bs[it + 1]]) : 0;
                int n = ns[it];
                uint2 h = make_uint2(0u, 0u), lo = make_uint2(0u, 0u);
                if (n == 1) {
                    long sid = first;
                    h  = __ldg(reinterpret_cast<const uint2*>(xh + sid * DIN) + l);
                    lo = __ldg(reinterpret_cast<const uint2*>(xl + sid * DIN) + l);
                } else if (n >= 2) {
                    int b = bs[it], e = b + n;
                    float4 a = make_float4(0.f, 0.f, 0.f, 0.f);
                    long sid = first;
                    for (int i = b; i < e; i++) {
                        int nxt = (i + 1 < e) ? __ldg(&ebuf[i + 1]) : 0;   // lookahead
                        float4 v = __ldg(reinterpret_cast<const float4*>(X + sid * DIN) + l);
                        a.x += v.x; a.y += v.y; a.z += v.z; a.w += v.w;
                        sid = nxt;
                    }
                    float sc = 1.f / (float)n;
                    a.x *= sc; a.y *= sc; a.z *= sc; a.w *= sc;
                    split2(a.x, a.y, h.x, lo.x);
                    split2(a.z, a.w, h.y, lo.y);
                }
                *reinterpret_cast<uint2*>(Ah + node * PITCH + l * 4) = h;
                *reinterpret_cast<uint2*>(Al + node * PITCH + l * 4) = lo;
            }
        } else {
            const int ELS = 64 * (DIN / 8);
            for (int idx = tid; idx < ELS; idx += 256) {
                int node = idx / (DIN / 8);
                int c8 = (idx % (DIN / 8)) * 8;
                int gn = bm + node;
                uint4 vh = make_uint4(0u, 0u, 0u, 0u), vl = make_uint4(0u, 0u, 0u, 0u);
                if (gn < NN) {
                    vh = *reinterpret_cast<const uint4*>(xh + (long)gn * DIN + c8);
                    vl = *reinterpret_cast<const uint4*>(xl + (long)gn * DIN + c8);
                }
                __nv_bfloat16* ph = Ah + node * PITCH + c8;
                __nv_bfloat16* pl = Al + node * PITCH + c8;
                *reinterpret_cast<uint2*>(ph)     = make_uint2(vh.x, vh.y);
                *reinterpret_cast<uint2*>(ph + 4) = make_uint2(vh.z, vh.w);
                *reinterpret_cast<uint2*>(pl)     = make_uint2(vl.x, vl.y);
                *reinterpret_cast<uint2*>(pl + 4) = make_uint2(vl.z, vl.w);
            }
        }
        __syncthreads();

        // ---- MMA over this DIN-wide chunk (3-pass bf16 split)
#pragma unroll
        for (int ks = 0; ks < DIN; ks += 16) {
            unsigned ah[2][4], al[2][4];
#pragma unroll
            for (int ma = 0; ma < 2; ma++) {
                int r0 = wm * 32 + ma * 16 + lg;
                int kc = ks + lq * 2;
                const __nv_bfloat16* pa = Ah + r0 * PITCH + kc;
                const __nv_bfloat16* pb = Al + r0 * PITCH + kc;
                ah[ma][0] = *reinterpret_cast<const unsigned*>(pa);
                ah[ma][1] = *reinterpret_cast<const unsigned*>(pa + 8 * PITCH);
                ah[ma][2] = *reinterpret_cast<const unsigned*>(pa + 8);
                ah[ma][3] = *reinterpret_cast<const unsigned*>(pa + 8 * PITCH + 8);
                al[ma][0] = *reinterpret_cast<const unsigned*>(pb);
                al[ma][1] = *reinterpret_cast<const unsigned*>(pb + 8 * PITCH);
                al[ma][2] = *reinterpret_cast<const unsigned*>(pb + 8);
                al[ma][3] = *reinterpret_cast<const unsigned*>(pb + 8 * PITCH + 8);
            }
            unsigned bh0[4], bh1[4], bl0[4], bl1[4];
#pragma unroll
            for (int na = 0; na < 4; na++) {
                int nb = wn * 32 + na * 8 + lg;
                int kl = ks + lq * 2;
                const __nv_bfloat16* ph = Bth + nb * PITCH + kl;
                const __nv_bfloat16* pl = Btl + nb * PITCH + kl;
                bh0[na] = *reinterpret_cast<const unsigned*>(ph);
                bh1[na] = *reinterpret_cast<const unsigned*>(ph + 8);
                bl0[na] = *reinterpret_cast<const unsigned*>(pl);
                bl1[na] = *reinterpret_cast<const unsigned*>(pl + 8);
            }
#pragma unroll
            for (int na = 0; na < 4; na++)
#pragma unroll
                for (int ma = 0; ma < 2; ma++)
                    MMA_BF16(acc[ma][na], ah[ma], bh0[na], bh1[na]);
#pragma unroll
            for (int na = 0; na < 4; na++)
#pragma unroll
                for (int ma = 0; ma < 2; ma++)
                    MMA_BF16(acc[ma][na], ah[ma], bl0[na], bl1[na]);
#pragma unroll
            for (int na = 0; na < 4; na++)
#pragma unroll
                for (int ma = 0; ma < 2; ma++)
                    MMA_BF16(acc[ma][na], al[ma], bh0[na], bh1[na]);
        }
        __syncthreads();
    }

    // ---- epilogue: bias(+ReLU), store C; WS=1 also stores bf16 split planes
#pragma unroll
    for (int ma = 0; ma < 2; ma++) {
#pragma unroll
        for (int na = 0; na < 4; na++) {
            int col = wn * 32 + na * 8 + lq * 2;
            float2 bv = *reinterpret_cast<const float2*>(&bias[col]);
            float v0 = acc[ma][na][0] + bv.x;
            float v1 = acc[ma][na][1] + bv.y;
            float v2 = acc[ma][na][2] + bv.x;
            float v3 = acc[ma][na][3] + bv.y;
            if (relu) {
                v0 = fmaxf(v0, 0.f); v1 = fmaxf(v1, 0.f);
                v2 = fmaxf(v2, 0.f); v3 = fmaxf(v3, 0.f);
            }
            int row0 = bm + wm * 32 + ma * 16 + lg;
            int row1 = row0 + 8;
            if (row0 < NN) {
                *reinterpret_cast<float2*>(&C[(long)row0 * DHID + col]) = make_float2(v0, v1);
                if (WS) {
                    unsigned h, l;
                    split2(v0, v1, h, l);
                    *reinterpret_cast<unsigned*>(&Ch[(long)row0 * DHID + col]) = h;
                    *reinterpret_cast<unsigned*>(&Cl[(long)row0 * DHID + col]) = l;
                }
            }
            if (row1 < NN) {
                *reinterpret_cast<float2*>(&C[(long)row1 * DHID + col]) = make_float2(v2, v3);
                if (WS) {
                    unsigned h, l;
                    split2(v2, v3, h, l);
                    *reinterpret_cast<unsigned*>(&Ch[(long)row1 * DHID + col]) = h;
                    *reinterpret_cast<unsigned*>(&Cl[(long)row1 * DHID + col]) = l;
                }
            }
        }
    }
}

__global__ void decoder_kernel(const int* __restrict__ head, const int* __restrict__ tail,
                               const int* __restrict__ rel, const float* __restrict__ h,
                               const float* __restrict__ rel_emb, float* __restrict__ out,
                               int Bn) {
    int warp = (blockIdx.x * blockDim.x + threadIdx.x) >> 5;
    int lane = threadIdx.x & 31;
    if (warp >= Bn) return;
    const float4* hp = reinterpret_cast<const float4*>(h + (long)head[warp] * DHID);
    const float4* tp = reinterpret_cast<const float4*>(h + (long)tail[warp] * DHID);
    const float4* rp = reinterpret_cast<const float4*>(rel_emb + (long)rel[warp] * DHID);
    float4 a = hp[lane], b = tp[lane], c = rp[lane];
    float s = a.x * b.x * c.x + a.y * b.y * c.y + a.z * b.z * c.z + a.w * b.w * c.w;
#pragma unroll
    for (int o = 16; o; o >>= 1) s += __shfl_xor_sync(0xffffffffu, s, o);
    if (lane == 0) out[warp] = s;
}

extern "C" void kernel_launch(void* const* d_in, const int* in_sizes, int n_in,
                              void* d_out, int out_size) {
    const int*   edge_index = (const int*)d_in[0];
    const int*   edge_type  = (const int*)d_in[1];
    const int*   head       = (const int*)d_in[2];
    const int*   tail       = (const int*)d_in[3];
    const int*   rel        = (const int*)d_in[4];
    const float* node_emb   = (const float*)d_in[5];
    const float* W1         = (const float*)d_in[6];
    const float* root1      = (const float*)d_in[7];
    const float* b1         = (const float*)d_in[8];
    const float* W2         = (const float*)d_in[9];
    const float* root2      = (const float*)d_in[10];
    const float* b2         = (const float*)d_in[11];
    const float* rel_emb    = (const float*)d_in[12];

    int E = in_sizes[0] / 2;
    const int* src = edge_index;
    const int* dst = edge_index + E;

    __nv_bfloat16 *xh, *xl, *yh, *yl, *Bth, *Btl;
    float *h1, *h2;
    int *icnt, *off, *pcur, *bsum, *ebuf;
    cudaGetSymbolAddress((void**)&xh, g_xh);
    cudaGetSymbolAddress((void**)&xl, g_xl);
    cudaGetSymbolAddress((void**)&yh, g_yh);
    cudaGetSymbolAddress((void**)&yl, g_yl);
    cudaGetSymbolAddress((void**)&Bth, g_Bth);
    cudaGetSymbolAddress((void**)&Btl, g_Btl);
    cudaGetSymbolAddress((void**)&h1, g_h1);
    cudaGetSymbolAddress((void**)&h2, g_h2);
    cudaGetSymbolAddress((void**)&icnt, g_icnt);
    cudaGetSymbolAddress((void**)&off, g_off);
    cudaGetSymbolAddress((void**)&pcur, g_pcur);
    cudaGetSymbolAddress((void**)&bsum, g_bsum);
    cudaGetSymbolAddress((void**)&ebuf, g_ebuf);

    const int T = 256;
    const int KA1 = NRL * DEMB, KT1 = KA1 + DEMB;
    const int KA2 = NRL * DHID, KT2 = KA2 + DHID;
    const int OFFB = (64 * NRL + 1 + 3) / 4 * 4 * 4;   // 5136 B, 16B-aligned count
    const int SM1 = 384 * (DEMB + 8) * 2 + OFFB;   // 60432 B
    const int SM2 = 384 * (DHID + 8) * 2 + OFFB;   // 109584 B -> 2 blocks/SM

    cudaFuncSetAttribute((const void*)fused_gemm_kernel<DEMB, 1>,
                         cudaFuncAttributeMaxDynamicSharedMemorySize, SM1);
    cudaFuncSetAttribute((const void*)fused_gemm_kernel<DHID, 0>,
                         cudaFuncAttributeMaxDynamicSharedMemorySize, SM2);

    // ---- counting sort of edges by segment (graph fixed; shared by both layers)
    zero_kernel<<<512, T>>>((float4*)icnt, NSEG / 4);
    zero_kernel<<<512, T>>>((float4*)pcur, NSEG / 4);
    seg_count_kernel<<<(E + T - 1) / T, T>>>(dst, edge_type, E, icnt);
    scanA_kernel<<<SCAN_NB, T>>>(icnt, bsum);
    scanB_kernel<<<1, 1024>>>(bsum, SCAN_NB);
    scanC_kernel<<<SCAN_NB, T>>>(icnt, bsum, off, E);
    place_kernel<<<(E + T - 1) / T, T>>>(src, dst, edge_type, E, off, pcur, ebuf);

    // ---- layer 1 (fused gather+GEMM; epilogue emits h1 planes for layer 2)
    {
        long n2 = (long)NN * DEMB / 2;
        convx_kernel<<<(unsigned)((n2 + T - 1) / T), T>>>(node_emb, xh, xl, n2);
    }
    prepB_kernel<<<(128 * KT1 / 2 + T - 1) / T, T>>>(W1, root1, KA1, KT1, Bth, Btl);
    fused_gemm_kernel<DEMB, 1><<<(NN + 63) / 64, 256, SM1>>>(
        ebuf, off, node_emb, xh, xl, Bth, Btl, b1, h1, yh, yl, 1);

    // ---- layer 2
    prepB_kernel<<<(128 * KT2 / 2 + T - 1) / T, T>>>(W2, root2, KA2, KT2, Bth, Btl);
    fused_gemm_kernel<DHID, 0><<<(NN + 63) / 64, 256, SM2>>>(
        ebuf, off, h1, yh, yl, Bth, Btl, b2, h2, nullptr, nullptr, 0);

    // ---- DistMult decoder
    int Bn = in_sizes[2];
    decoder_kernel<<<(Bn * 32 + T - 1) / T, T>>>(head, tail, rel, h2, rel_emb,
                                                 (float*)d_out, Bn);
}

// round 12
// speedup vs baseline: 2.3847x; 1.0786x over previous
#include <cuda_runtime.h>
#include <cuda_bf16.h>
#include <cstdint>

#define NN    50000
#define NRL   20
#define DEMB  64
#define DHID  128
#define EMAX  1600000
#define NSEG  (NN * NRL)

// Static scratch (no allocations allowed). 16-byte aligned for uint4 access.
__device__ __align__(16) float g_h1[(long)NN * DHID];
__device__ __align__(16) float g_h2[(long)NN * DHID];
__device__ __align__(16) __nv_bfloat16 g_xh[(long)NN * DHID];    // layer-1 input planes
__device__ __align__(16) __nv_bfloat16 g_xl[(long)NN * DHID];
__device__ __align__(16) __nv_bfloat16 g_yh[(long)NN * DHID];    // layer-2 input planes (h1)
__device__ __align__(16) __nv_bfloat16 g_yl[(long)NN * DHID];
__device__ __align__(16) __nv_bfloat16 g_Bth[128 * (NRL * DHID + DHID)];  // B^T hi [o][k]
__device__ __align__(16) __nv_bfloat16 g_Btl[128 * (NRL * DHID + DHID)];  // B^T lo
__device__ int   g_icnt[NSEG];
__device__ int   g_off[NSEG + 4];
__device__ int   g_pcur[NSEG];
__device__ int   g_bsum[1024];
__device__ int   g_ebuf[EMAX];

#define SCAN_ITEMS 1024
#define SCAN_NB    ((NSEG + SCAN_ITEMS - 1) / SCAN_ITEMS)

// Split a = hi + lo: hi = exact truncation to bf16, lo = residual rounded.
__device__ __forceinline__ void split2(float a, float b, unsigned& h, unsigned& l) {
    unsigned ua = __float_as_uint(a), ub = __float_as_uint(b);
    h = __byte_perm(ua, ub, 0x7632);
    float la = a - __uint_as_float(ua & 0xFFFF0000u);
    float lb = b - __uint_as_float(ub & 0xFFFF0000u);
    __nv_bfloat162 p = __float22bfloat162_rn(make_float2(la, lb));
    l = *reinterpret_cast<unsigned*>(&p);
}

__global__ void zero_kernel(float4* p, long n4) {
    long i = (long)blockIdx.x * blockDim.x + threadIdx.x;
    long stride = (long)gridDim.x * blockDim.x;
    float4 z = make_float4(0.f, 0.f, 0.f, 0.f);
    for (; i < n4; i += stride) p[i] = z;
}

__global__ void seg_count_kernel(const int* __restrict__ dst, const int* __restrict__ et,
                                 int E, int* __restrict__ icnt) {
    int i = blockIdx.x * blockDim.x + threadIdx.x;
    if (i < E) atomicAdd(&icnt[dst[i] * NRL + et[i]], 1);
}

__global__ void scanA_kernel(const int* __restrict__ icnt, int* __restrict__ bsum) {
    __shared__ int sd[256];
    int base = blockIdx.x * SCAN_ITEMS + threadIdx.x * 4;
    int s = 0;
#pragma unroll
    for (int t = 0; t < 4; t++) { int i = base + t; if (i < NSEG) s += icnt[i]; }
    sd[threadIdx.x] = s;
    __syncthreads();
    for (int o = 128; o; o >>= 1) {
        if (threadIdx.x < o) sd[threadIdx.x] += sd[threadIdx.x + o];
        __syncthreads();
    }
    if (threadIdx.x == 0) bsum[blockIdx.x] = sd[0];
}

__global__ void scanB_kernel(int* __restrict__ bsum, int nb) {
    __shared__ int sm[1024];
    int v = (threadIdx.x < nb) ? bsum[threadIdx.x] : 0;
    sm[threadIdx.x] = v;
    __syncthreads();
    for (int o = 1; o < 1024; o <<= 1) {
        int t = (threadIdx.x >= o) ? sm[threadIdx.x - o] : 0;
        __syncthreads();
        sm[threadIdx.x] += t;
        __syncthreads();
    }
    if (threadIdx.x < nb) bsum[threadIdx.x] = sm[threadIdx.x] - v;
}

__global__ void scanC_kernel(const int* __restrict__ icnt, const int* __restrict__ bsum,
                             int* __restrict__ off, int E) {
    __shared__ int sm[256];
    int base = blockIdx.x * SCAN_ITEMS + threadIdx.x * 4;
    int v[4], ex[4];
    int s = 0;
#pragma unroll
    for (int t = 0; t < 4; t++) {
        int i = base + t;
        v[t] = (i < NSEG) ? icnt[i] : 0;
        ex[t] = s;
        s += v[t];
    }
    int mine = s;
    sm[threadIdx.x] = s;
    __syncthreads();
    for (int o = 1; o < 256; o <<= 1) {
        int t = (threadIdx.x >= o) ? sm[threadIdx.x - o] : 0;
        __syncthreads();
        sm[threadIdx.x] += t;
        __syncthreads();
    }
    int tex = sm[threadIdx.x] - mine;
    int b0 = bsum[blockIdx.x];
#pragma unroll
    for (int t = 0; t < 4; t++) {
        int i = base + t;
        if (i < NSEG) off[i] = b0 + tex + ex[t];
    }
    if (blockIdx.x == 0 && threadIdx.x == 0) off[NSEG] = E;
}

__global__ void place_kernel(const int* __restrict__ src, const int* __restrict__ dst,
                             const int* __restrict__ et, int E,
                             const int* __restrict__ off, int* __restrict__ pcur,
                             int* __restrict__ ebuf) {
    int i = blockIdx.x * blockDim.x + threadIdx.x;
    if (i >= E) return;
    int seg = dst[i] * NRL + et[i];
    int p = off[seg] + atomicAdd(&pcur[seg], 1);
    ebuf[p] = src[i];
}

__global__ void convx_kernel(const float* __restrict__ X, __nv_bfloat16* __restrict__ xh,
                             __nv_bfloat16* __restrict__ xl, long n2) {
    long i = (long)blockIdx.x * blockDim.x + threadIdx.x;
    if (i >= n2) return;
    float2 v = reinterpret_cast<const float2*>(X)[i];
    unsigned h, l;
    split2(v.x, v.y, h, l);
    reinterpret_cast<unsigned*>(xh)[i] = h;
    reinterpret_cast<unsigned*>(xl)[i] = l;
}

__global__ void prepB_kernel(const float* __restrict__ W, const float* __restrict__ root,
                             int KA, int KT,
                             __nv_bfloat16* __restrict__ Bth, __nv_bfloat16* __restrict__ Btl) {
    int i = blockIdx.x * blockDim.x + threadIdx.x;
    int tot = 128 * (KT / 2);
    if (i >= tot) return;
    int o = i / (KT / 2);
    int k = (i % (KT / 2)) * 2;
    float b0 = (k < KA) ? W[(long)k * 128 + o] : root[(long)(k - KA) * 128 + o];
    float b1 = (k + 1 < KA) ? W[(long)(k + 1) * 128 + o] : root[(long)(k + 1 - KA) * 128 + o];
    unsigned h, l;
    split2(b0, b1, h, l);
    *reinterpret_cast<unsigned*>(&Bth[(long)o * KT + k]) = h;
    *reinterpret_cast<unsigned*>(&Btl[(long)o * KT + k]) = l;
}

#define MMA_BF16(ACC, A, B0, B1)                                              \
    asm volatile(                                                             \
        "mma.sync.aligned.m16n8k16.row.col.f32.bf16.bf16.f32 "                \
        "{%0,%1,%2,%3}, {%4,%5,%6,%7}, {%8,%9}, {%0,%1,%2,%3};"               \
        : "+f"((ACC)[0]), "+f"((ACC)[1]), "+f"((ACC)[2]), "+f"((ACC)[3])      \
        : "r"((A)[0]), "r"((A)[1]), "r"((A)[2]), "r"((A)[3]),                 \
          "r"(B0), "r"(B1))

// FUSED gather+GEMM, M-tile = 64 rows, 256 threads, 2 blocks/SM for overlap.
// Gather: L=16 lanes/node (VEC=DIN/64 float4s per lane), G=16 parallel nodes,
// 4 serial segments/thread; edges processed pairwise with fully independent
// index+row loads (MLP 2*VEC per pair) — no sequential pointer chain.
template <int DIN, int WS>
__global__ void __launch_bounds__(256, 2)
fused_gemm_kernel(const int* __restrict__ ebuf, const int* __restrict__ off,
                  const float* __restrict__ X,
                  const __nv_bfloat16* __restrict__ xh, const __nv_bfloat16* __restrict__ xl,
                  const __nv_bfloat16* __restrict__ Btgh, const __nv_bfloat16* __restrict__ Btgl,
                  const float* __restrict__ bias, float* __restrict__ C,
                  __nv_bfloat16* __restrict__ Ch, __nv_bfloat16* __restrict__ Cl, int relu) {
    const int KT = NRL * DIN + DIN;
    const int PITCH = DIN + 8;
    const int VEC = DIN / 64;         // float4s per lane per edge (1 or 2)

    extern __shared__ __align__(16) char smraw[];
    __nv_bfloat16* Ah  = reinterpret_cast<__nv_bfloat16*>(smraw);
    __nv_bfloat16* Al  = Ah  + 64 * PITCH;
    __nv_bfloat16* Bth = Al  + 64 * PITCH;
    __nv_bfloat16* Btl = Bth + 128 * PITCH;
    int* s_off = reinterpret_cast<int*>(Btl + 128 * PITCH);   // 64*NRL+1 ints

    int tid = threadIdx.x;
    int wid = tid >> 5;
    int lane = tid & 31;
    int wm = wid & 1;        // warp row tile (32 rows)
    int wn = wid >> 1;       // warp col tile (32 cols)
    int bm = blockIdx.x * 64;
    int lg = lane >> 2;
    int lq = lane & 3;

    // ---- cache this block's off[] slice (contiguous, coalesced)
    {
        int nvalid = (NN - bm < 64) ? (NN - bm) : 64;
        int cnt = nvalid * NRL + 1;
        int base = bm * NRL;
        for (int i = tid; i < cnt; i += 256) s_off[i] = off[base + i];
    }
    __syncthreads();

    float acc[2][4][4];
#pragma unroll
    for (int ma = 0; ma < 2; ma++)
#pragma unroll
        for (int na = 0; na < 4; na++)
#pragma unroll
            for (int r = 0; r < 4; r++) acc[ma][na][r] = 0.f;

    for (int rel = 0; rel <= NRL; rel++) {
        // ---- B chunk [128 out][DIN] from pre-transposed planes
        {
            const int ELS = 128 * (DIN / 8);
            for (int idx = tid; idx < ELS; idx += 256) {
                int nr = idx / (DIN / 8);
                int c8 = (idx % (DIN / 8)) * 8;
                long go = (long)nr * KT + rel * DIN + c8;
                uint4 vh = *reinterpret_cast<const uint4*>(Btgh + go);
                uint4 vl = *reinterpret_cast<const uint4*>(Btgl + go);
                __nv_bfloat16* ph = Bth + nr * PITCH + c8;
                __nv_bfloat16* pl = Btl + nr * PITCH + c8;
                *reinterpret_cast<uint2*>(ph)     = make_uint2(vh.x, vh.y);
                *reinterpret_cast<uint2*>(ph + 4) = make_uint2(vh.z, vh.w);
                *reinterpret_cast<uint2*>(pl)     = make_uint2(vl.x, vl.y);
                *reinterpret_cast<uint2*>(pl + 4) = make_uint2(vl.z, vl.w);
            }
        }
        // ---- A chunk: rel<NRL gathered mean; rel==NRL X rows (root term)
        if (rel < NRL) {
            int g = tid >> 4;            // 16 nodes in parallel
            int l = tid & 15;            // 16 lanes per node, VEC float4s each
            int bs[4], ns[4];
#pragma unroll
            for (int it = 0; it < 4; it++) {
                int node = it * 16 + g;
                int gn = bm + node;
                int s = node * NRL + rel;
                int bb = s_off[s];
                bs[it] = bb;
                ns[it] = (gn < NN) ? (s_off[s + 1] - bb) : 0;
            }
#pragma unroll
            for (int it = 0; it < 4; it++) {
                int node = it * 16 + g;
                int n = ns[it];
                uint2 h[VEC], lo[VEC];
#pragma unroll
                for (int v = 0; v < VEC; v++) {
                    h[v] = make_uint2(0u, 0u);
                    lo[v] = make_uint2(0u, 0u);
                }
                if (n == 1) {
                    long sid = __ldg(&ebuf[bs[it]]);
#pragma unroll
                    for (int v = 0; v < VEC; v++) {
                        h[v]  = __ldg(reinterpret_cast<const uint2*>(xh + sid * DIN) + l * VEC + v);
                        lo[v] = __ldg(reinterpret_cast<const uint2*>(xl + sid * DIN) + l * VEC + v);
                    }
                } else if (n >= 2) {
                    float4 a[VEC];
#pragma unroll
                    for (int v = 0; v < VEC; v++) a[v] = make_float4(0.f, 0.f, 0.f, 0.f);
                    int b = bs[it], e = b + n, i = b;
                    for (; i + 2 <= e; i += 2) {      // pairwise independent loads
                        long s0 = __ldg(&ebuf[i]);
                        long s1 = __ldg(&ebuf[i + 1]);
#pragma unroll
                        for (int v = 0; v < VEC; v++) {
                            float4 v0 = __ldg(reinterpret_cast<const float4*>(X + s0 * DIN) + l * VEC + v);
                            float4 v1 = __ldg(reinterpret_cast<const float4*>(X + s1 * DIN) + l * VEC + v);
                            a[v].x += v0.x + v1.x; a[v].y += v0.y + v1.y;
                            a[v].z += v0.z + v1.z; a[v].w += v0.w + v1.w;
                        }
                    }
                    if (i < e) {
                        long s0 = __ldg(&ebuf[i]);
#pragma unroll
                        for (int v = 0; v < VEC; v++) {
                            float4 v0 = __ldg(reinterpret_cast<const float4*>(X + s0 * DIN) + l * VEC + v);
                            a[v].x += v0.x; a[v].y += v0.y; a[v].z += v0.z; a[v].w += v0.w;
                        }
                    }
                    float sc = 1.f / (float)n;
#pragma unroll
                    for (int v = 0; v < VEC; v++) {
                        a[v].x *= sc; a[v].y *= sc; a[v].z *= sc; a[v].w *= sc;
                        split2(a[v].x, a[v].y, h[v].x, lo[v].x);
                        split2(a[v].z, a[v].w, h[v].y, lo[v].y);
                    }
                }
#pragma unroll
                for (int v = 0; v < VEC; v++) {
                    *reinterpret_cast<uint2*>(Ah + node * PITCH + (l * VEC + v) * 4) = h[v];
                    *reinterpret_cast<uint2*>(Al + node * PITCH + (l * VEC + v) * 4) = lo[v];
                }
            }
        } else {
            const int ELS = 64 * (DIN / 8);
            for (int idx = tid; idx < ELS; idx += 256) {
                int node = idx / (DIN / 8);
                int c8 = (idx % (DIN / 8)) * 8;
                int gn = bm + node;
                uint4 vh = make_uint4(0u, 0u, 0u, 0u), vl = make_uint4(0u, 0u, 0u, 0u);
                if (gn < NN) {
                    vh = *reinterpret_cast<const uint4*>(xh + (long)gn * DIN + c8);
                    vl = *reinterpret_cast<const uint4*>(xl + (long)gn * DIN + c8);
                }
                __nv_bfloat16* ph = Ah + node * PITCH + c8;
                __nv_bfloat16* pl = Al + node * PITCH + c8;
                *reinterpret_cast<uint2*>(ph)     = make_uint2(vh.x, vh.y);
                *reinterpret_cast<uint2*>(ph + 4) = make_uint2(vh.z, vh.w);
                *reinterpret_cast<uint2*>(pl)     = make_uint2(vl.x, vl.y);
                *reinterpret_cast<uint2*>(pl + 4) = make_uint2(vl.z, vl.w);
            }
        }
        __syncthreads();

        // ---- MMA over this DIN-wide chunk (3-pass bf16 split)
#pragma unroll
        for (int ks = 0; ks < DIN; ks += 16) {
            unsigned ah[2][4], al[2][4];
#pragma unroll
            for (int ma = 0; ma < 2; ma++) {
                int r0 = wm * 32 + ma * 16 + lg;
                int kc = ks + lq * 2;
                const __nv_bfloat16* pa = Ah + r0 * PITCH + kc;
                const __nv_bfloat16* pb = Al + r0 * PITCH + kc;
                ah[ma][0] = *reinterpret_cast<const unsigned*>(pa);
                ah[ma][1] = *reinterpret_cast<const unsigned*>(pa + 8 * PITCH);
                ah[ma][2] = *reinterpret_cast<const unsigned*>(pa + 8);
                ah[ma][3] = *reinterpret_cast<const unsigned*>(pa + 8 * PITCH + 8);
                al[ma][0] = *reinterpret_cast<const unsigned*>(pb);
                al[ma][1] = *reinterpret_cast<const unsigned*>(pb + 8 * PITCH);
                al[ma][2] = *reinterpret_cast<const unsigned*>(pb + 8);
                al[ma][3] = *reinterpret_cast<const unsigned*>(pb + 8 * PITCH + 8);
            }
            unsigned bh0[4], bh1[4], bl0[4], bl1[4];
#pragma unroll
            for (int na = 0; na < 4; na++) {
                int nb = wn * 32 + na * 8 + lg;
                int kl = ks + lq * 2;
                const __nv_bfloat16* ph = Bth + nb * PITCH + kl;
                const __nv_bfloat16* pl = Btl + nb * PITCH + kl;
                bh0[na] = *reinterpret_cast<const unsigned*>(ph);
                bh1[na] = *reinterpret_cast<const unsigned*>(ph + 8);
                bl0[na] = *reinterpret_cast<const unsigned*>(pl);
                bl1[na] = *reinterpret_cast<const unsigned*>(pl + 8);
            }
#pragma unroll
            for (int na = 0; na < 4; na++)
#pragma unroll
                for (int ma = 0; ma < 2; ma++)
                    MMA_BF16(acc[ma][na], ah[ma], bh0[na], bh1[na]);
#pragma unroll
            for (int na = 0; na < 4; na++)
#pragma unroll
                for (int ma = 0; ma < 2; ma++)
                    MMA_BF16(acc[ma][na], ah[ma], bl0[na], bl1[na]);
#pragma unroll
            for (int na = 0; na < 4; na++)
#pragma unroll
                for (int ma = 0; ma < 2; ma++)
                    MMA_BF16(acc[ma][na], al[ma], bh0[na], bh1[na]);
        }
        __syncthreads();
    }

    // ---- epilogue: bias(+ReLU), store C; WS=1 also stores bf16 split planes
#pragma unroll
    for (int ma = 0; ma < 2; ma++) {
#pragma unroll
        for (int na = 0; na < 4; na++) {
            int col = wn * 32 + na * 8 + lq * 2;
            float2 bv = *reinterpret_cast<const float2*>(&bias[col]);
            float v0 = acc[ma][na][0] + bv.x;
            float v1 = acc[ma][na][1] + bv.y;
            float v2 = acc[ma][na][2] + bv.x;
            float v3 = acc[ma][na][3] + bv.y;
            if (relu) {
                v0 = fmaxf(v0, 0.f); v1 = fmaxf(v1, 0.f);
                v2 = fmaxf(v2, 0.f); v3 = fmaxf(v3, 0.f);
            }
            int row0 = bm + wm * 32 + ma * 16 + lg;
            int row1 = row0 + 8;
            if (row0 < NN) {
                *reinterpret_cast<float2*>(&C[(long)row0 * DHID + col]) = make_float2(v0, v1);
                if (WS) {
                    unsigned h, l;
                    split2(v0, v1, h, l);
                    *reinterpret_cast<unsigned*>(&Ch[(long)row0 * DHID + col]) = h;
                    *reinterpret_cast<unsigned*>(&Cl[(long)row0 * DHID + col]) = l;
                }
            }
            if (row1 < NN) {
                *reinterpret_cast<float2*>(&C[(long)row1 * DHID + col]) = make_float2(v2, v3);
                if (WS) {
                    unsigned h, l;
                    split2(v2, v3, h, l);
                    *reinterpret_cast<unsigned*>(&Ch[(long)row1 * DHID + col]) = h;
                    *reinterpret_cast<unsigned*>(&Cl[(long)row1 * DHID + col]) = l;
                }
            }
        }
    }
}

__global__ void decoder_kernel(const int* __restrict__ head, const int* __restrict__ tail,
                               const int* __restrict__ rel, const float* __restrict__ h,
                               const float* __restrict__ rel_emb, float* __restrict__ out,
                               int Bn) {
    int warp = (blockIdx.x * blockDim.x + threadIdx.x) >> 5;
    int lane = threadIdx.x & 31;
    if (warp >= Bn) return;
    const float4* hp = reinterpret_cast<const float4*>(h + (long)head[warp] * DHID);
    const float4* tp = reinterpret_cast<const float4*>(h + (long)tail[warp] * DHID);
    const float4* rp = reinterpret_cast<const float4*>(rel_emb + (long)rel[warp] * DHID);
    float4 a = hp[lane], b = tp[lane], c = rp[lane];
    float s = a.x * b.x * c.x + a.y * b.y * c.y + a.z * b.z * c.z + a.w * b.w * c.w;
#pragma unroll
    for (int o = 16; o; o >>= 1) s += __shfl_xor_sync(0xffffffffu, s, o);
    if (lane == 0) out[warp] = s;
}

extern "C" void kernel_launch(void* const* d_in, const int* in_sizes, int n_in,
                              void* d_out, int out_size) {
    const int*   edge_index = (const int*)d_in[0];
    const int*   edge_type  = (const int*)d_in[1];
    const int*   head       = (const int*)d_in[2];
    const int*   tail       = (const int*)d_in[3];
    const int*   rel        = (const int*)d_in[4];
    const float* node_emb   = (const float*)d_in[5];
    const float* W1         = (const float*)d_in[6];
    const float* root1      = (const float*)d_in[7];
    const float* b1         = (const float*)d_in[8];
    const float* W2         = (const float*)d_in[9];
    const float* root2      = (const float*)d_in[10];
    const float* b2         = (const float*)d_in[11];
    const float* rel_emb    = (const float*)d_in[12];

    int E = in_sizes[0] / 2;
    const int* src = edge_index;
    const int* dst = edge_index + E;

    __nv_bfloat16 *xh, *xl, *yh, *yl, *Bth, *Btl;
    float *h1, *h2;
    int *icnt, *off, *pcur, *bsum, *ebuf;
    cudaGetSymbolAddress((void**)&xh, g_xh);
    cudaGetSymbolAddress((void**)&xl, g_xl);
    cudaGetSymbolAddress((void**)&yh, g_yh);
    cudaGetSymbolAddress((void**)&yl, g_yl);
    cudaGetSymbolAddress((void**)&Bth, g_Bth);
    cudaGetSymbolAddress((void**)&Btl, g_Btl);
    cudaGetSymbolAddress((void**)&h1, g_h1);
    cudaGetSymbolAddress((void**)&h2, g_h2);
    cudaGetSymbolAddress((void**)&icnt, g_icnt);
    cudaGetSymbolAddress((void**)&off, g_off);
    cudaGetSymbolAddress((void**)&pcur, g_pcur);
    cudaGetSymbolAddress((void**)&bsum, g_bsum);
    cudaGetSymbolAddress((void**)&ebuf, g_ebuf);

    const int T = 256;
    const int KA1 = NRL * DEMB, KT1 = KA1 + DEMB;
    const int KA2 = NRL * DHID, KT2 = KA2 + DHID;
    const int OFFB = (64 * NRL + 1 + 3) / 4 * 4 * 4;
    const int SM1 = 384 * (DEMB + 8) * 2 + OFFB;   // 60432 B
    const int SM2 = 384 * (DHID + 8) * 2 + OFFB;   // 109584 B -> 2 blocks/SM

    cudaFuncSetAttribute((const void*)fused_gemm_kernel<DEMB, 1>,
                         cudaFuncAttributeMaxDynamicSharedMemorySize, SM1);
    cudaFuncSetAttribute((const void*)fused_gemm_kernel<DHID, 0>,
                         cudaFuncAttributeMaxDynamicSharedMemorySize, SM2);

    // ---- counting sort of edges by segment (graph fixed; shared by both layers)
    zero_kernel<<<512, T>>>((float4*)icnt, NSEG / 4);
    zero_kernel<<<512, T>>>((float4*)pcur, NSEG / 4);
    seg_count_kernel<<<(E + T - 1) / T, T>>>(dst, edge_type, E, icnt);
    scanA_kernel<<<SCAN_NB, T>>>(icnt, bsum);
    scanB_kernel<<<1, 1024>>>(bsum, SCAN_NB);
    scanC_kernel<<<SCAN_NB, T>>>(icnt, bsum, off, E);
    place_kernel<<<(E + T - 1) / T, T>>>(src, dst, edge_type, E, off, pcur, ebuf);

    // ---- layer 1 (fused gather+GEMM; epilogue emits h1 planes for layer 2)
    {
        long n2 = (long)NN * DEMB / 2;
        convx_kernel<<<(unsigned)((n2 + T - 1) / T), T>>>(node_emb, xh, xl, n2);
    }
    prepB_kernel<<<(128 * KT1 / 2 + T - 1) / T, T>>>(W1, root1, KA1, KT1, Bth, Btl);
    fused_gemm_kernel<DEMB, 1><<<(NN + 63) / 64, 256, SM1>>>(
        ebuf, off, node_emb, xh, xl, Bth, Btl, b1, h1, yh, yl, 1);

    // ---- layer 2
    prepB_kernel<<<(128 * KT2 / 2 + T - 1) / T, T>>>(W2, root2, KA2, KT2, Bth, Btl);
    fused_gemm_kernel<DHID, 0><<<(NN + 63) / 64, 256, SM2>>>(
        ebuf, off, h1, yh, yl, Bth, Btl, b2, h2, nullptr, nullptr, 0);

    // ---- DistMult decoder
    int Bn = in_sizes[2];
    decoder_kernel<<<(Bn * 32 + T - 1) / T, T>>>(head, tail, rel, h2, rel_emb,
                                                 (float*)d_out, Bn);
}

// round 13
// speedup vs baseline: 2.4580x; 1.0307x over previous
#include <cuda_runtime.h>
#include <cuda_bf16.h>
#include <cstdint>

#define NN    50000
#define NRL   20
#define DEMB  64
#define DHID  128
#define EMAX  1600000
#define NSEG  (NN * NRL)
#define KT1   (NRL * DEMB + DEMB)
#define KT2   (NRL * DHID + DHID)

// Static scratch (no allocations allowed). 16-byte aligned for uint4 access.
__device__ __align__(16) float g_h1[(long)NN * DHID];
__device__ __align__(16) float g_h2[(long)NN * DHID];
__device__ __align__(16) __nv_bfloat16 g_xh[(long)NN * DHID];    // layer-1 input planes
__device__ __align__(16) __nv_bfloat16 g_xl[(long)NN * DHID];
__device__ __align__(16) __nv_bfloat16 g_yh[(long)NN * DHID];    // layer-2 input planes (h1)
__device__ __align__(16) __nv_bfloat16 g_yl[(long)NN * DHID];
__device__ __align__(16) __nv_bfloat16 g_B1h[128 * KT1];         // layer-1 B^T hi [o][k]
__device__ __align__(16) __nv_bfloat16 g_B1l[128 * KT1];
__device__ __align__(16) __nv_bfloat16 g_B2h[128 * KT2];         // layer-2 B^T hi [o][k]
__device__ __align__(16) __nv_bfloat16 g_B2l[128 * KT2];
__device__ int   g_icnt[NSEG];
__device__ int   g_off[NSEG + 4];
__device__ int   g_pcur[NSEG];
__device__ int   g_bsum[1024];
__device__ int   g_ebuf[EMAX];
__device__ volatile int g_barcnt;
__device__ volatile int g_barsense;

#define SORT_NB   512
#define SORT_IT   2048                // segments per block in scan phases (8/thread)

// Split a = hi + lo: hi = exact truncation to bf16, lo = residual rounded.
__device__ __forceinline__ void split2(float a, float b, unsigned& h, unsigned& l) {
    unsigned ua = __float_as_uint(a), ub = __float_as_uint(b);
    h = __byte_perm(ua, ub, 0x7632);
    float la = a - __uint_as_float(ua & 0xFFFF0000u);
    float lb = b - __uint_as_float(ub & 0xFFFF0000u);
    __nv_bfloat162 p = __float22bfloat162_rn(make_float2(la, lb));
    l = *reinterpret_cast<unsigned*>(&p);
}

// Sense-reversing grid barrier; all SORT_NB blocks guaranteed resident.
__device__ __forceinline__ void grid_bar() {
    __syncthreads();
    if (threadIdx.x == 0) {
        __threadfence();
        int my = g_barsense;
        int t = atomicAdd((int*)&g_barcnt, 1);
        if (t == SORT_NB - 1) {
            g_barcnt = 0;
            __threadfence();
            atomicAdd((int*)&g_barsense, 1);
        } else {
            while (g_barsense == my) { }
        }
        __threadfence();
    }
    __syncthreads();
}

// prep1: X fp32 -> bf16 planes AND layer-1 B^T hi/lo planes (independent work).
__global__ void prep1_kernel(const float* __restrict__ X,
                             __nv_bfloat16* __restrict__ xh, __nv_bfloat16* __restrict__ xl,
                             const float* __restrict__ W, const float* __restrict__ root,
                             __nv_bfloat16* __restrict__ Bth, __nv_bfloat16* __restrict__ Btl) {
    const long n2 = (long)NN * DEMB / 2;
    const int KA = NRL * DEMB;
    const long tot = n2 + 128 * (KT1 / 2);
    for (long i = (long)blockIdx.x * blockDim.x + threadIdx.x; i < tot;
         i += (long)gridDim.x * blockDim.x) {
        if (i < n2) {
            float2 v = reinterpret_cast<const float2*>(X)[i];
            unsigned h, l;
            split2(v.x, v.y, h, l);
            reinterpret_cast<unsigned*>(xh)[i] = h;
            reinterpret_cast<unsigned*>(xl)[i] = l;
        } else {
            long j = i - n2;
            int o = (int)(j / (KT1 / 2));
            int k = (int)(j % (KT1 / 2)) * 2;
            float b0 = (k < KA) ? W[(long)k * 128 + o] : root[(long)(k - KA) * 128 + o];
            float b1 = (k + 1 < KA) ? W[(long)(k + 1) * 128 + o]
                                    : root[(long)(k + 1 - KA) * 128 + o];
            unsigned h, l;
            split2(b0, b1, h, l);
            *reinterpret_cast<unsigned*>(&Bth[(long)o * KT1 + k]) = h;
            *reinterpret_cast<unsigned*>(&Btl[(long)o * KT1 + k]) = l;
        }
    }
}

__global__ void prepB_kernel(const float* __restrict__ W, const float* __restrict__ root,
                             int KA, int KT,
                             __nv_bfloat16* __restrict__ Bth, __nv_bfloat16* __restrict__ Btl) {
    int i = blockIdx.x * blockDim.x + threadIdx.x;
    int tot = 128 * (KT / 2);
    if (i >= tot) return;
    int o = i / (KT / 2);
    int k = (i % (KT / 2)) * 2;
    float b0 = (k < KA) ? W[(long)k * 128 + o] : root[(long)(k - KA) * 128 + o];
    float b1 = (k + 1 < KA) ? W[(long)(k + 1) * 128 + o] : root[(long)(k + 1 - KA) * 128 + o];
    unsigned h, l;
    split2(b0, b1, h, l);
    *reinterpret_cast<unsigned*>(&Bth[(long)o * KT + k]) = h;
    *reinterpret_cast<unsigned*>(&Btl[(long)o * KT + k]) = l;
}

// ONE-kernel counting sort: zero -> count -> block sums -> offsets -> place.
__global__ void __launch_bounds__(256)
sort_all_kernel(const int* __restrict__ src, const int* __restrict__ dst,
                const int* __restrict__ et, int E,
                int* __restrict__ icnt, int* __restrict__ off, int* __restrict__ pcur,
                int* __restrict__ bsum, int* __restrict__ ebuf) {
    __shared__ int sm[256];
    int tid = threadIdx.x;
    long gt = (long)blockIdx.x * 256 + tid;
    const long gstride = (long)SORT_NB * 256;

    // P0: zero counts + cursors
    for (long i = gt; i < NSEG; i += gstride) { icnt[i] = 0; pcur[i] = 0; }
    grid_bar();
    // P1: histogram
    for (long i = gt; i < E; i += gstride)
        atomicAdd(&icnt[dst[i] * NRL + et[i]], 1);
    grid_bar();
    // P2: per-block segment sums (block b owns segments [b*SORT_IT, ...))
    {
        int base = blockIdx.x * SORT_IT + tid * 8;
        int s = 0;
#pragma unroll
        for (int t = 0; t < 8; t++) {
            int i = base + t;
            if (i < NSEG) s += icnt[i];
        }
        sm[tid] = s;
        __syncthreads();
        for (int o = 128; o; o >>= 1) {
            if (tid < o) sm[tid] += sm[tid + o];
            __syncthreads();
        }
        if (tid == 0) bsum[blockIdx.x] = sm[0];
    }
    grid_bar();
    // P3: offsets = global exclusive scan (block prefix computed locally)
    {
        int partial = 0;
        for (int j = tid; j < blockIdx.x; j += 256) partial += bsum[j];
        sm[tid] = partial;
        __syncthreads();
        for (int o = 128; o; o >>= 1) {
            if (tid < o) sm[tid] += sm[tid + o];
            __syncthreads();
        }
        int b0 = sm[0];
        __syncthreads();

        int base = blockIdx.x * SORT_IT + tid * 8;
        int v[8], ex[8];
        int s = 0;
#pragma unroll
        for (int t = 0; t < 8; t++) {
            int i = base + t;
            v[t] = (i < NSEG) ? icnt[i] : 0;
            ex[t] = s;
            s += v[t];
        }
        int mine = s;
        sm[tid] = s;
        __syncthreads();
        for (int o = 1; o < 256; o <<= 1) {
            int t = (tid >= o) ? sm[tid - o] : 0;
            __syncthreads();
            sm[tid] += t;
            __syncthreads();
        }
        int tex = sm[tid] - mine;
#pragma unroll
        for (int t = 0; t < 8; t++) {
            int i = base + t;
            if (i < NSEG) off[i] = b0 + tex + ex[t];
        }
        if (blockIdx.x == 0 && tid == 0) off[NSEG] = E;
    }
    grid_bar();
    // P4: place src ids sorted by segment
    for (long i = gt; i < E; i += gstride) {
        int seg = dst[i] * NRL + et[i];
        int p = off[seg] + atomicAdd(&pcur[seg], 1);
        ebuf[p] = src[i];
    }
}

#define MMA_BF16(ACC, A, B0, B1)                                              \
    asm volatile(                                                             \
        "mma.sync.aligned.m16n8k16.row.col.f32.bf16.bf16.f32 "                \
        "{%0,%1,%2,%3}, {%4,%5,%6,%7}, {%8,%9}, {%0,%1,%2,%3};"               \
        : "+f"((ACC)[0]), "+f"((ACC)[1]), "+f"((ACC)[2]), "+f"((ACC)[3])      \
        : "r"((A)[0]), "r"((A)[1]), "r"((A)[2]), "r"((A)[3]),                 \
          "r"(B0), "r"(B1))

// FUSED gather+GEMM, M-tile 64 rows, 256 threads, 2 blocks/SM.
// Segment startups batched: first two ebuf indices of ALL 4 segments prefetched
// upfront (8 LDGs in flight), so n<=2 segments (~75%) gather in one X-load batch.
template <int DIN, int WS>
__global__ void __launch_bounds__(256, 2)
fused_gemm_kernel(const int* __restrict__ ebuf, const int* __restrict__ off,
                  const float* __restrict__ X,
                  const __nv_bfloat16* __restrict__ xh, const __nv_bfloat16* __restrict__ xl,
                  const __nv_bfloat16* __restrict__ Btgh, const __nv_bfloat16* __restrict__ Btgl,
                  const float* __restrict__ bias, float* __restrict__ C,
                  __nv_bfloat16* __restrict__ Ch, __nv_bfloat16* __restrict__ Cl, int relu) {
    const int KT = NRL * DIN + DIN;
    const int PITCH = DIN + 8;
    const int VEC = DIN / 64;         // float4s per lane per edge (1 or 2)

    extern __shared__ __align__(16) char smraw[];
    __nv_bfloat16* Ah  = reinterpret_cast<__nv_bfloat16*>(smraw);
    __nv_bfloat16* Al  = Ah  + 64 * PITCH;
    __nv_bfloat16* Bth = Al  + 64 * PITCH;
    __nv_bfloat16* Btl = Bth + 128 * PITCH;
    int* s_off = reinterpret_cast<int*>(Btl + 128 * PITCH);   // 64*NRL+1 ints

    int tid = threadIdx.x;
    int wid = tid >> 5;
    int lane = tid & 31;
    int wm = wid & 1;        // warp row tile (32 rows)
    int wn = wid >> 1;       // warp col tile (32 cols)
    int bm = blockIdx.x * 64;
    int lg = lane >> 2;
    int lq = lane & 3;

    // ---- cache this block's off[] slice (contiguous, coalesced)
    {
        int nvalid = (NN - bm < 64) ? (NN - bm) : 64;
        int cnt = nvalid * NRL + 1;
        int base = bm * NRL;
        for (int i = tid; i < cnt; i += 256) s_off[i] = off[base + i];
    }
    __syncthreads();

    float acc[2][4][4];
#pragma unroll
    for (int ma = 0; ma < 2; ma++)
#pragma unroll
        for (int na = 0; na < 4; na++)
#pragma unroll
            for (int r = 0; r < 4; r++) acc[ma][na][r] = 0.f;

    for (int rel = 0; rel <= NRL; rel++) {
        // ---- B chunk [128 out][DIN] from pre-transposed planes
        {
            const int ELS = 128 * (DIN / 8);
            for (int idx = tid; idx < ELS; idx += 256) {
                int nr = idx / (DIN / 8);
                int c8 = (idx % (DIN / 8)) * 8;
                long go = (long)nr * KT + rel * DIN + c8;
                uint4 vh = *reinterpret_cast<const uint4*>(Btgh + go);
                uint4 vl = *reinterpret_cast<const uint4*>(Btgl + go);
                __nv_bfloat16* ph = Bth + nr * PITCH + c8;
                __nv_bfloat16* pl = Btl + nr * PITCH + c8;
                *reinterpret_cast<uint2*>(ph)     = make_uint2(vh.x, vh.y);
                *reinterpret_cast<uint2*>(ph + 4) = make_uint2(vh.z, vh.w);
                *reinterpret_cast<uint2*>(pl)     = make_uint2(vl.x, vl.y);
                *reinterpret_cast<uint2*>(pl + 4) = make_uint2(vl.z, vl.w);
            }
        }
        // ---- A chunk: rel<NRL gathered mean; rel==NRL X rows (root term)
        if (rel < NRL) {
            int g = tid >> 4;            // 16 nodes in parallel
            int l = tid & 15;            // 16 lanes per node, VEC float4s each
            int bs[4], ns[4];
#pragma unroll
            for (int it = 0; it < 4; it++) {
                int node = it * 16 + g;
                int gn = bm + node;
                int s = node * NRL + rel;
                int bb = s_off[s];
                bs[it] = bb;
                ns[it] = (gn < NN) ? (s_off[s + 1] - bb) : 0;
            }
            // batch segment startups: first two ebuf ids of all 4 segments
            int fe0[4], fe1[4];
#pragma unroll
            for (int it = 0; it < 4; it++) {
                fe0[it] = (ns[it] > 0) ? __ldg(&ebuf[bs[it]]) : 0;
                fe1[it] = (ns[it] > 1) ? __ldg(&ebuf[bs[it] + 1]) : 0;
            }
#pragma unroll
            for (int it = 0; it < 4; it++) {
                int node = it * 16 + g;
                int n = ns[it];
                uint2 h[VEC], lo[VEC];
#pragma unroll
                for (int v = 0; v < VEC; v++) {
                    h[v] = make_uint2(0u, 0u);
                    lo[v] = make_uint2(0u, 0u);
                }
                if (n == 1) {
                    long sid = fe0[it];
#pragma unroll
                    for (int v = 0; v < VEC; v++) {
                        h[v]  = __ldg(reinterpret_cast<const uint2*>(xh + sid * DIN) + l * VEC + v);
                        lo[v] = __ldg(reinterpret_cast<const uint2*>(xl + sid * DIN) + l * VEC + v);
                    }
                } else if (n >= 2) {
                    float4 a[VEC];
                    long s0 = fe0[it], s1 = fe1[it];
#pragma unroll
                    for (int v = 0; v < VEC; v++) {
                        float4 v0 = __ldg(reinterpret_cast<const float4*>(X + s0 * DIN) + l * VEC + v);
                        float4 v1 = __ldg(reinterpret_cast<const float4*>(X + s1 * DIN) + l * VEC + v);
                        a[v] = make_float4(v0.x + v1.x, v0.y + v1.y, v0.z + v1.z, v0.w + v1.w);
                    }
                    int b = bs[it], e = b + n, i = b + 2;
                    for (; i + 2 <= e; i += 2) {      // pairwise independent loads
                        long t0 = __ldg(&ebuf[i]);
                        long t1 = __ldg(&ebuf[i + 1]);
#pragma unroll
                        for (int v = 0; v < VEC; v++) {
                            float4 v0 = __ldg(reinterpret_cast<const float4*>(X + t0 * DIN) + l * VEC + v);
                            float4 v1 = __ldg(reinterpret_cast<const float4*>(X + t1 * DIN) + l * VEC + v);
                            a[v].x += v0.x + v1.x; a[v].y += v0.y + v1.y;
                            a[v].z += v0.z + v1.z; a[v].w += v0.w + v1.w;
                        }
                    }
                    if (i < e) {
                        long t0 = __ldg(&ebuf[i]);
#pragma unroll
                        for (int v = 0; v < VEC; v++) {
                            float4 v0 = __ldg(reinterpret_cast<const float4*>(X + t0 * DIN) + l * VEC + v);
                            a[v].x += v0.x; a[v].y += v0.y; a[v].z += v0.z; a[v].w += v0.w;
                        }
                    }
                    float sc = 1.f / (float)n;
#pragma unroll
                    for (int v = 0; v < VEC; v++) {
                        a[v].x *= sc; a[v].y *= sc; a[v].z *= sc; a[v].w *= sc;
                        split2(a[v].x, a[v].y, h[v].x, lo[v].x);
                        split2(a[v].z, a[v].w, h[v].y, lo[v].y);
                    }
                }
#pragma unroll
                for (int v = 0; v < VEC; v++) {
                    *reinterpret_cast<uint2*>(Ah + node * PITCH + (l * VEC + v) * 4) = h[v];
                    *reinterpret_cast<uint2*>(Al + node * PITCH + (l * VEC + v) * 4) = lo[v];
                }
            }
        } else {
            const int ELS = 64 * (DIN / 8);
            for (int idx = tid; idx < ELS; idx += 256) {
                int node = idx / (DIN / 8);
                int c8 = (idx % (DIN / 8)) * 8;
                int gn = bm + node;
                uint4 vh = make_uint4(0u, 0u, 0u, 0u), vl = make_uint4(0u, 0u, 0u, 0u);
                if (gn < NN) {
                    vh = *reinterpret_cast<const uint4*>(xh + (long)gn * DIN + c8);
                    vl = *reinterpret_cast<const uint4*>(xl + (long)gn * DIN + c8);
                }
                __nv_bfloat16* ph = Ah + node * PITCH + c8;
                __nv_bfloat16* pl = Al + node * PITCH + c8;
                *reinterpret_cast<uint2*>(ph)     = make_uint2(vh.x, vh.y);
                *reinterpret_cast<uint2*>(ph + 4) = make_uint2(vh.z, vh.w);
                *reinterpret_cast<uint2*>(pl)     = make_uint2(vl.x, vl.y);
                *reinterpret_cast<uint2*>(pl + 4) = make_uint2(vl.z, vl.w);
            }
        }
        __syncthreads();

        // ---- MMA over this DIN-wide chunk (3-pass bf16 split)
#pragma unroll
        for (int ks = 0; ks < DIN; ks += 16) {
            unsigned ah[2][4], al[2][4];
#pragma unroll
            for (int ma = 0; ma < 2; ma++) {
                int r0 = wm * 32 + ma * 16 + lg;
                int kc = ks + lq * 2;
                const __nv_bfloat16* pa = Ah + r0 * PITCH + kc;
                const __nv_bfloat16* pb = Al + r0 * PITCH + kc;
                ah[ma][0] = *reinterpret_cast<const unsigned*>(pa);
                ah[ma][1] = *reinterpret_cast<const unsigned*>(pa + 8 * PITCH);
                ah[ma][2] = *reinterpret_cast<const unsigned*>(pa + 8);
                ah[ma][3] = *reinterpret_cast<const unsigned*>(pa + 8 * PITCH + 8);
                al[ma][0] = *reinterpret_cast<const unsigned*>(pb);
                al[ma][1] = *reinterpret_cast<const unsigned*>(pb + 8 * PITCH);
                al[ma][2] = *reinterpret_cast<const unsigned*>(pb + 8);
                al[ma][3] = *reinterpret_cast<const unsigned*>(pb + 8 * PITCH + 8);
            }
            unsigned bh0[4], bh1[4], bl0[4], bl1[4];
#pragma unroll
            for (int na = 0; na < 4; na++) {
                int nb = wn * 32 + na * 8 + lg;
                int kl = ks + lq * 2;
                const __nv_bfloat16* ph = Bth + nb * PITCH + kl;
                const __nv_bfloat16* pl = Btl + nb * PITCH + kl;
                bh0[na] = *reinterpret_cast<const unsigned*>(ph);
                bh1[na] = *reinterpret_cast<const unsigned*>(ph + 8);
                bl0[na] = *reinterpret_cast<const unsigned*>(pl);
                bl1[na] = *reinterpret_cast<const unsigned*>(pl + 8);
            }
#pragma unroll
            for (int na = 0; na < 4; na++)
#pragma unroll
                for (int ma = 0; ma < 2; ma++)
                    MMA_BF16(acc[ma][na], ah[ma], bh0[na], bh1[na]);
#pragma unroll
            for (int na = 0; na < 4; na++)
#pragma unroll
                for (int ma = 0; ma < 2; ma++)
                    MMA_BF16(acc[ma][na], ah[ma], bl0[na], bl1[na]);
#pragma unroll
            for (int na = 0; na < 4; na++)
#pragma unroll
                for (int ma = 0; ma < 2; ma++)
                    MMA_BF16(acc[ma][na], al[ma], bh0[na], bh1[na]);
        }
        __syncthreads();
    }

    // ---- epilogue: bias(+ReLU), store C; WS=1 also stores bf16 split planes
#pragma unroll
    for (int ma = 0; ma < 2; ma++) {
#pragma unroll
        for (int na = 0; na < 4; na++) {
            int col = wn * 32 + na * 8 + lq * 2;
            float2 bv = *reinterpret_cast<const float2*>(&bias[col]);
            float v0 = acc[ma][na][0] + bv.x;
            float v1 = acc[ma][na][1] + bv.y;
            float v2 = acc[ma][na][2] + bv.x;
            float v3 = acc[ma][na][3] + bv.y;
            if (relu) {
                v0 = fmaxf(v0, 0.f); v1 = fmaxf(v1, 0.f);
                v2 = fmaxf(v2, 0.f); v3 = fmaxf(v3, 0.f);
            }
            int row0 = bm + wm * 32 + ma * 16 + lg;
            int row1 = row0 + 8;
            if (row0 < NN) {
                *reinterpret_cast<float2*>(&C[(long)row0 * DHID + col]) = make_float2(v0, v1);
                if (WS) {
                    unsigned h, l;
                    split2(v0, v1, h, l);
                    *reinterpret_cast<unsigned*>(&Ch[(long)row0 * DHID + col]) = h;
                    *reinterpret_cast<unsigned*>(&Cl[(long)row0 * DHID + col]) = l;
                }
            }
            if (row1 < NN) {
                *reinterpret_cast<float2*>(&C[(long)row1 * DHID + col]) = make_float2(v2, v3);
                if (WS) {
                    unsigned h, l;
                    split2(v2, v3, h, l);
                    *reinterpret_cast<unsigned*>(&Ch[(long)row1 * DHID + col]) = h;
                    *reinterpret_cast<unsigned*>(&Cl[(long)row1 * DHID + col]) = l;
                }
            }
        }
    }
}

__global__ void decoder_kernel(const int* __restrict__ head, const int* __restrict__ tail,
                               const int* __restrict__ rel, const float* __restrict__ h,
                               const float* __restrict__ rel_emb, float* __restrict__ out,
                               int Bn) {
    int warp = (blockIdx.x * blockDim.x + threadIdx.x) >> 5;
    int lane = threadIdx.x & 31;
    if (warp >= Bn) return;
    const float4* hp = reinterpret_cast<const float4*>(h + (long)head[warp] * DHID);
    const float4* tp = reinterpret_cast<const float4*>(h + (long)tail[warp] * DHID);
    const float4* rp = reinterpret_cast<const float4*>(rel_emb + (long)rel[warp] * DHID);
    float4 a = hp[lane], b = tp[lane], c = rp[lane];
    float s = a.x * b.x * c.x + a.y * b.y * c.y + a.z * b.z * c.z + a.w * b.w * c.w;
#pragma unroll
    for (int o = 16; o; o >>= 1) s += __shfl_xor_sync(0xffffffffu, s, o);
    if (lane == 0) out[warp] = s;
}

extern "C" void kernel_launch(void* const* d_in, const int* in_sizes, int n_in,
                              void* d_out, int out_size) {
    const int*   edge_index = (const int*)d_in[0];
    const int*   edge_type  = (const int*)d_in[1];
    const int*   head       = (const int*)d_in[2];
    const int*   tail       = (const int*)d_in[3];
    const int*   rel        = (const int*)d_in[4];
    const float* node_emb   = (const float*)d_in[5];
    const float* W1         = (const float*)d_in[6];
    const float* root1      = (const float*)d_in[7];
    const float* b1         = (const float*)d_in[8];
    const float* W2         = (const float*)d_in[9];
    const float* root2      = (const float*)d_in[10];
    const float* b2         = (const float*)d_in[11];
    const float* rel_emb    = (const float*)d_in[12];

    int E = in_sizes[0] / 2;
    const int* src = edge_index;
    const int* dst = edge_index + E;

    __nv_bfloat16 *xh, *xl, *yh, *yl, *B1h, *B1l, *B2h, *B2l;
    float *h1, *h2;
    int *icnt, *off, *pcur, *bsum, *ebuf;
    cudaGetSymbolAddress((void**)&xh, g_xh);
    cudaGetSymbolAddress((void**)&xl, g_xl);
    cudaGetSymbolAddress((void**)&yh, g_yh);
    cudaGetSymbolAddress((void**)&yl, g_yl);
    cudaGetSymbolAddress((void**)&B1h, g_B1h);
    cudaGetSymbolAddress((void**)&B1l, g_B1l);
    cudaGetSymbolAddress((void**)&B2h, g_B2h);
    cudaGetSymbolAddress((void**)&B2l, g_B2l);
    cudaGetSymbolAddress((void**)&h1, g_h1);
    cudaGetSymbolAddress((void**)&h2, g_h2);
    cudaGetSymbolAddress((void**)&icnt, g_icnt);
    cudaGetSymbolAddress((void**)&off, g_off);
    cudaGetSymbolAddress((void**)&pcur, g_pcur);
    cudaGetSymbolAddress((void**)&bsum, g_bsum);
    cudaGetSymbolAddress((void**)&ebuf, g_ebuf);

    const int T = 256;
    const int KA2 = NRL * DHID;
    const int OFFB = (64 * NRL + 1 + 3) / 4 * 4 * 4;
    const int SM1 = 384 * (DEMB + 8) * 2 + OFFB;   // 60432 B
    const int SM2 = 384 * (DHID + 8) * 2 + OFFB;   // 109584 B -> 2 blocks/SM

    cudaFuncSetAttribute((const void*)fused_gemm_kernel<DEMB, 1>,
                         cudaFuncAttributeMaxDynamicSharedMemorySize, SM1);
    cudaFuncSetAttribute((const void*)fused_gemm_kernel<DHID, 0>,
                         cudaFuncAttributeMaxDynamicSharedMemorySize, SM2);

    // 1) independent prep: X planes + layer-1 B planes
    prep1_kernel<<<592, T>>>(node_emb, xh, xl, W1, root1, B1h, B1l);
    // 2) one-kernel counting sort (grid-resident barrier)
    sort_all_kernel<<<SORT_NB, T>>>(src, dst, edge_type, E, icnt, off, pcur, bsum, ebuf);
    // 3) layer-2 B planes (independent buffers; before fused1 for ncu slotting)
    prepB_kernel<<<(128 * KT2 / 2 + T - 1) / T, T>>>(W2, root2, KA2, KT2, B2h, B2l);
    // 4) layer 1 fused gather+GEMM (epilogue emits h1 planes)
    fused_gemm_kernel<DEMB, 1><<<(NN + 63) / 64, 256, SM1>>>(
        ebuf, off, node_emb, xh, xl, B1h, B1l, b1, h1, yh, yl, 1);
    // 5) layer 2
    fused_gemm_kernel<DHID, 0><<<(NN + 63) / 64, 256, SM2>>>(
        ebuf, off, h1, yh, yl, B2h, B2l, b2, h2, nullptr, nullptr, 0);
    // 6) DistMult decoder
    int Bn = in_sizes[2];
    decoder_kernel<<<(Bn * 32 + T - 1) / T, T>>>(head, tail, rel, h2, rel_emb,
                                                 (float*)d_out, Bn);
}

// round 14
// speedup vs baseline: 2.4870x; 1.0118x over previous
#include <cuda_runtime.h>
#include <cuda_bf16.h>
#include <cstdint>

#define NN    50000
#define NRL   20
#define DEMB  64
#define DHID  128
#define EMAX  1600000
#define NSEG  (NN * NRL)
#define KT1   (NRL * DEMB + DEMB)
#define KT2   (NRL * DHID + DHID)

// Static scratch (no allocations allowed). 16-byte aligned for uint4 access.
__device__ __align__(16) float g_h1[(long)NN * DHID];
__device__ __align__(16) float g_h2[(long)NN * DHID];
__device__ __align__(16) __nv_bfloat16 g_xh[(long)NN * DHID];    // layer-1 input planes
__device__ __align__(16) __nv_bfloat16 g_xl[(long)NN * DHID];
__device__ __align__(16) __nv_bfloat16 g_yh[(long)NN * DHID];    // layer-2 input planes (h1)
__device__ __align__(16) __nv_bfloat16 g_yl[(long)NN * DHID];
__device__ __align__(16) __nv_bfloat16 g_B1h[128 * KT1];         // layer-1 B^T hi [o][k]
__device__ __align__(16) __nv_bfloat16 g_B1l[128 * KT1];
__device__ __align__(16) __nv_bfloat16 g_B2h[128 * KT2];         // layer-2 B^T hi [o][k]
__device__ __align__(16) __nv_bfloat16 g_B2l[128 * KT2];
__device__ int   g_icnt[NSEG];
__device__ int   g_off[NSEG + 4];
__device__ int   g_pcur[NSEG];
__device__ int   g_bsum[1024];
__device__ int   g_ebuf[EMAX];
__device__ volatile int g_barcnt;
__device__ volatile int g_barsense;

#define SORT_NB   512
#define SORT_IT   2048

// Split a = hi + lo: hi = exact truncation to bf16, lo = residual rounded.
__device__ __forceinline__ void split2(float a, float b, unsigned& h, unsigned& l) {
    unsigned ua = __float_as_uint(a), ub = __float_as_uint(b);
    h = __byte_perm(ua, ub, 0x7632);
    float la = a - __uint_as_float(ua & 0xFFFF0000u);
    float lb = b - __uint_as_float(ub & 0xFFFF0000u);
    __nv_bfloat162 p = __float22bfloat162_rn(make_float2(la, lb));
    l = *reinterpret_cast<unsigned*>(&p);
}

// Sense-reversing grid barrier; all SORT_NB blocks guaranteed resident.
__device__ __forceinline__ void grid_bar() {
    __syncthreads();
    if (threadIdx.x == 0) {
        __threadfence();
        int my = g_barsense;
        int t = atomicAdd((int*)&g_barcnt, 1);
        if (t == SORT_NB - 1) {
            g_barcnt = 0;
            __threadfence();
            atomicAdd((int*)&g_barsense, 1);
        } else {
            while (g_barsense == my) { }
        }
        __threadfence();
    }
    __syncthreads();
}

// prep1: X fp32 -> bf16 planes AND layer-1 B^T hi/lo planes (independent work).
__global__ void prep1_kernel(const float* __restrict__ X,
                             __nv_bfloat16* __restrict__ xh, __nv_bfloat16* __restrict__ xl,
                             const float* __restrict__ W, const float* __restrict__ root,
                             __nv_bfloat16* __restrict__ Bth, __nv_bfloat16* __restrict__ Btl) {
    const long n2 = (long)NN * DEMB / 2;
    const int KA = NRL * DEMB;
    const long tot = n2 + 128 * (KT1 / 2);
    for (long i = (long)blockIdx.x * blockDim.x + threadIdx.x; i < tot;
         i += (long)gridDim.x * blockDim.x) {
        if (i < n2) {
            float2 v = reinterpret_cast<const float2*>(X)[i];
            unsigned h, l;
            split2(v.x, v.y, h, l);
            reinterpret_cast<unsigned*>(xh)[i] = h;
            reinterpret_cast<unsigned*>(xl)[i] = l;
        } else {
            long j = i - n2;
            int o = (int)(j / (KT1 / 2));
            int k = (int)(j % (KT1 / 2)) * 2;
            float b0 = (k < KA) ? W[(long)k * 128 + o] : root[(long)(k - KA) * 128 + o];
            float b1 = (k + 1 < KA) ? W[(long)(k + 1) * 128 + o]
                                    : root[(long)(k + 1 - KA) * 128 + o];
            unsigned h, l;
            split2(b0, b1, h, l);
            *reinterpret_cast<unsigned*>(&Bth[(long)o * KT1 + k]) = h;
            *reinterpret_cast<unsigned*>(&Btl[(long)o * KT1 + k]) = l;
        }
    }
}

__global__ void prepB_kernel(const float* __restrict__ W, const float* __restrict__ root,
                             int KA, int KT,
                             __nv_bfloat16* __restrict__ Bth, __nv_bfloat16* __restrict__ Btl) {
    int i = blockIdx.x * blockDim.x + threadIdx.x;
    int tot = 128 * (KT / 2);
    if (i >= tot) return;
    int o = i / (KT / 2);
    int k = (i % (KT / 2)) * 2;
    float b0 = (k < KA) ? W[(long)k * 128 + o] : root[(long)(k - KA) * 128 + o];
    float b1 = (k + 1 < KA) ? W[(long)(k + 1) * 128 + o] : root[(long)(k + 1 - KA) * 128 + o];
    unsigned h, l;
    split2(b0, b1, h, l);
    *reinterpret_cast<unsigned*>(&Bth[(long)o * KT + k]) = h;
    *reinterpret_cast<unsigned*>(&Btl[(long)o * KT + k]) = l;
}

// ONE-kernel counting sort: zero -> count -> block sums -> offsets -> place.
__global__ void __launch_bounds__(256)
sort_all_kernel(const int* __restrict__ src, const int* __restrict__ dst,
                const int* __restrict__ et, int E,
                int* __restrict__ icnt, int* __restrict__ off, int* __restrict__ pcur,
                int* __restrict__ bsum, int* __restrict__ ebuf) {
    __shared__ int sm[256];
    int tid = threadIdx.x;
    long gt = (long)blockIdx.x * 256 + tid;
    const long gstride = (long)SORT_NB * 256;

    for (long i = gt; i < NSEG; i += gstride) { icnt[i] = 0; pcur[i] = 0; }
    grid_bar();
    for (long i = gt; i < E; i += gstride)
        atomicAdd(&icnt[dst[i] * NRL + et[i]], 1);
    grid_bar();
    {
        int base = blockIdx.x * SORT_IT + tid * 8;
        int s = 0;
#pragma unroll
        for (int t = 0; t < 8; t++) {
            int i = base + t;
            if (i < NSEG) s += icnt[i];
        }
        sm[tid] = s;
        __syncthreads();
        for (int o = 128; o; o >>= 1) {
            if (tid < o) sm[tid] += sm[tid + o];
            __syncthreads();
        }
        if (tid == 0) bsum[blockIdx.x] = sm[0];
    }
    grid_bar();
    {
        int partial = 0;
        for (int j = tid; j < blockIdx.x; j += 256) partial += bsum[j];
        sm[tid] = partial;
        __syncthreads();
        for (int o = 128; o; o >>= 1) {
            if (tid < o) sm[tid] += sm[tid + o];
            __syncthreads();
        }
        int b0 = sm[0];
        __syncthreads();

        int base = blockIdx.x * SORT_IT + tid * 8;
        int v[8], ex[8];
        int s = 0;
#pragma unroll
        for (int t = 0; t < 8; t++) {
            int i = base + t;
            v[t] = (i < NSEG) ? icnt[i] : 0;
            ex[t] = s;
            s += v[t];
        }
        int mine = s;
        sm[tid] = s;
        __syncthreads();
        for (int o = 1; o < 256; o <<= 1) {
            int t = (tid >= o) ? sm[tid - o] : 0;
            __syncthreads();
            sm[tid] += t;
            __syncthreads();
        }
        int tex = sm[tid] - mine;
#pragma unroll
        for (int t = 0; t < 8; t++) {
            int i = base + t;
            if (i < NSEG) off[i] = b0 + tex + ex[t];
        }
        if (blockIdx.x == 0 && tid == 0) off[NSEG] = E;
    }
    grid_bar();
    for (long i = gt; i < E; i += gstride) {
        int seg = dst[i] * NRL + et[i];
        int p = off[seg] + atomicAdd(&pcur[seg], 1);
        ebuf[p] = src[i];
    }
}

#define MMA_BF16(ACC, A, B0, B1)                                              \
    asm volatile(                                                             \
        "mma.sync.aligned.m16n8k16.row.col.f32.bf16.bf16.f32 "                \
        "{%0,%1,%2,%3}, {%4,%5,%6,%7}, {%8,%9}, {%0,%1,%2,%3};"               \
        : "+f"((ACC)[0]), "+f"((ACC)[1]), "+f"((ACC)[2]), "+f"((ACC)[3])      \
        : "r"((A)[0]), "r"((A)[1]), "r"((A)[2]), "r"((A)[3]),                 \
          "r"(B0), "r"(B1))

// FUSED gather+GEMM, M-tile 64 rows, 512 threads (16 warps), 2 blocks/SM
// -> 1024 threads/SM (50% occupancy) to hide gather + MMA latency.
// Warp tile: 16 rows x 32 cols (wm=wid&3, wn=wid>>2). Gather: 32 parallel
// nodes, 2 serial segments/thread, pairwise-independent edge loads.
template <int DIN, int WS>
__global__ void __launch_bounds__(512, 2)
fused_gemm_kernel(const int* __restrict__ ebuf, const int* __restrict__ off,
                  const float* __restrict__ X,
                  const __nv_bfloat16* __restrict__ xh, const __nv_bfloat16* __restrict__ xl,
                  const __nv_bfloat16* __restrict__ Btgh, const __nv_bfloat16* __restrict__ Btgl,
                  const float* __restrict__ bias, float* __restrict__ C,
                  __nv_bfloat16* __restrict__ Ch, __nv_bfloat16* __restrict__ Cl, int relu) {
    const int KT = NRL * DIN + DIN;
    const int PITCH = DIN + 8;
    const int VEC = DIN / 64;         // float4s per lane per edge (1 or 2)

    extern __shared__ __align__(16) char smraw[];
    __nv_bfloat16* Ah  = reinterpret_cast<__nv_bfloat16*>(smraw);
    __nv_bfloat16* Al  = Ah  + 64 * PITCH;
    __nv_bfloat16* Bth = Al  + 64 * PITCH;
    __nv_bfloat16* Btl = Bth + 128 * PITCH;
    int* s_off = reinterpret_cast<int*>(Btl + 128 * PITCH);   // 64*NRL+1 ints

    int tid = threadIdx.x;
    int wid = tid >> 5;
    int lane = tid & 31;
    int wm = wid & 3;        // warp row tile (16 rows)
    int wn = wid >> 2;       // warp col tile (32 cols)
    int bm = blockIdx.x * 64;
    int lg = lane >> 2;
    int lq = lane & 3;

    // ---- cache this block's off[] slice (contiguous, coalesced)
    {
        int nvalid = (NN - bm < 64) ? (NN - bm) : 64;
        int cnt = nvalid * NRL + 1;
        int base = bm * NRL;
        for (int i = tid; i < cnt; i += 512) s_off[i] = off[base + i];
    }
    __syncthreads();

    float acc[4][4];
#pragma unroll
    for (int na = 0; na < 4; na++)
#pragma unroll
        for (int r = 0; r < 4; r++) acc[na][r] = 0.f;

    for (int rel = 0; rel <= NRL; rel++) {
        // ---- B chunk [128 out][DIN] from pre-transposed planes
        {
            const int ELS = 128 * (DIN / 8);
            for (int idx = tid; idx < ELS; idx += 512) {
                int nr = idx / (DIN / 8);
                int c8 = (idx % (DIN / 8)) * 8;
                long go = (long)nr * KT + rel * DIN + c8;
                uint4 vh = *reinterpret_cast<const uint4*>(Btgh + go);
                uint4 vl = *reinterpret_cast<const uint4*>(Btgl + go);
                __nv_bfloat16* ph = Bth + nr * PITCH + c8;
                __nv_bfloat16* pl = Btl + nr * PITCH + c8;
                *reinterpret_cast<uint2*>(ph)     = make_uint2(vh.x, vh.y);
                *reinterpret_cast<uint2*>(ph + 4) = make_uint2(vh.z, vh.w);
                *reinterpret_cast<uint2*>(pl)     = make_uint2(vl.x, vl.y);
                *reinterpret_cast<uint2*>(pl + 4) = make_uint2(vl.z, vl.w);
            }
        }
        // ---- A chunk: rel<NRL gathered mean; rel==NRL X rows (root term)
        if (rel < NRL) {
            int g = tid >> 4;            // 32 nodes in parallel
            int l = tid & 15;            // 16 lanes per node, VEC float4s each
            int bs[2], ns[2];
#pragma unroll
            for (int it = 0; it < 2; it++) {
                int node = it * 32 + g;
                int gn = bm + node;
                int s = node * NRL + rel;
                int bb = s_off[s];
                bs[it] = bb;
                ns[it] = (gn < NN) ? (s_off[s + 1] - bb) : 0;
            }
            int fe0[2], fe1[2];
#pragma unroll
            for (int it = 0; it < 2; it++) {
                fe0[it] = (ns[it] > 0) ? __ldg(&ebuf[bs[it]]) : 0;
                fe1[it] = (ns[it] > 1) ? __ldg(&ebuf[bs[it] + 1]) : 0;
            }
#pragma unroll
            for (int it = 0; it < 2; it++) {
                int node = it * 32 + g;
                int n = ns[it];
                uint2 h[VEC], lo[VEC];
#pragma unroll
                for (int v = 0; v < VEC; v++) {
                    h[v] = make_uint2(0u, 0u);
                    lo[v] = make_uint2(0u, 0u);
                }
                if (n == 1) {
                    long sid = fe0[it];
#pragma unroll
                    for (int v = 0; v < VEC; v++) {
                        h[v]  = __ldg(reinterpret_cast<const uint2*>(xh + sid * DIN) + l * VEC + v);
                        lo[v] = __ldg(reinterpret_cast<const uint2*>(xl + sid * DIN) + l * VEC + v);
                    }
                } else if (n >= 2) {
                    float4 a[VEC];
                    long s0 = fe0[it], s1 = fe1[it];
#pragma unroll
                    for (int v = 0; v < VEC; v++) {
                        float4 v0 = __ldg(reinterpret_cast<const float4*>(X + s0 * DIN) + l * VEC + v);
                        float4 v1 = __ldg(reinterpret_cast<const float4*>(X + s1 * DIN) + l * VEC + v);
                        a[v] = make_float4(v0.x + v1.x, v0.y + v1.y, v0.z + v1.z, v0.w + v1.w);
                    }
                    int b = bs[it], e = b + n, i = b + 2;
                    for (; i + 2 <= e; i += 2) {      // pairwise independent loads
                        long t0 = __ldg(&ebuf[i]);
                        long t1 = __ldg(&ebuf[i + 1]);
#pragma unroll
                        for (int v = 0; v < VEC; v++) {
                            float4 v0 = __ldg(reinterpret_cast<const float4*>(X + t0 * DIN) + l * VEC + v);
                            float4 v1 = __ldg(reinterpret_cast<const float4*>(X + t1 * DIN) + l * VEC + v);
                            a[v].x += v0.x + v1.x; a[v].y += v0.y + v1.y;
                            a[v].z += v0.z + v1.z; a[v].w += v0.w + v1.w;
                        }
                    }
                    if (i < e) {
                        long t0 = __ldg(&ebuf[i]);
#pragma unroll
                        for (int v = 0; v < VEC; v++) {
                            float4 v0 = __ldg(reinterpret_cast<const float4*>(X + t0 * DIN) + l * VEC + v);
                            a[v].x += v0.x; a[v].y += v0.y; a[v].z += v0.z; a[v].w += v0.w;
                        }
                    }
                    float sc = 1.f / (float)n;
#pragma unroll
                    for (int v = 0; v < VEC; v++) {
                        a[v].x *= sc; a[v].y *= sc; a[v].z *= sc; a[v].w *= sc;
                        split2(a[v].x, a[v].y, h[v].x, lo[v].x);
                        split2(a[v].z, a[v].w, h[v].y, lo[v].y);
                    }
                }
#pragma unroll
                for (int v = 0; v < VEC; v++) {
                    *reinterpret_cast<uint2*>(Ah + node * PITCH + (l * VEC + v) * 4) = h[v];
                    *reinterpret_cast<uint2*>(Al + node * PITCH + (l * VEC + v) * 4) = lo[v];
                }
            }
        } else {
            const int ELS = 64 * (DIN / 8);
            for (int idx = tid; idx < ELS; idx += 512) {
                int node = idx / (DIN / 8);
                int c8 = (idx % (DIN / 8)) * 8;
                int gn = bm + node;
                uint4 vh = make_uint4(0u, 0u, 0u, 0u), vl = make_uint4(0u, 0u, 0u, 0u);
                if (gn < NN) {
                    vh = *reinterpret_cast<const uint4*>(xh + (long)gn * DIN + c8);
                    vl = *reinterpret_cast<const uint4*>(xl + (long)gn * DIN + c8);
                }
                __nv_bfloat16* ph = Ah + node * PITCH + c8;
                __nv_bfloat16* pl = Al + node * PITCH + c8;
                *reinterpret_cast<uint2*>(ph)     = make_uint2(vh.x, vh.y);
                *reinterpret_cast<uint2*>(ph + 4) = make_uint2(vh.z, vh.w);
                *reinterpret_cast<uint2*>(pl)     = make_uint2(vl.x, vl.y);
                *reinterpret_cast<uint2*>(pl + 4) = make_uint2(vl.z, vl.w);
            }
        }
        __syncthreads();

        // ---- MMA over this DIN-wide chunk (3-pass bf16 split), 16x32 warp tile
#pragma unroll
        for (int ks = 0; ks < DIN; ks += 16) {
            unsigned ah[4], al[4];
            {
                int r0 = wm * 16 + lg;
                int kc = ks + lq * 2;
                const __nv_bfloat16* pa = Ah + r0 * PITCH + kc;
                const __nv_bfloat16* pb = Al + r0 * PITCH + kc;
                ah[0] = *reinterpret_cast<const unsigned*>(pa);
                ah[1] = *reinterpret_cast<const unsigned*>(pa + 8 * PITCH);
                ah[2] = *reinterpret_cast<const unsigned*>(pa + 8);
                ah[3] = *reinterpret_cast<const unsigned*>(pa + 8 * PITCH + 8);
                al[0] = *reinterpret_cast<const unsigned*>(pb);
                al[1] = *reinterpret_cast<const unsigned*>(pb + 8 * PITCH);
                al[2] = *reinterpret_cast<const unsigned*>(pb + 8);
                al[3] = *reinterpret_cast<const unsigned*>(pb + 8 * PITCH + 8);
            }
            unsigned bh0[4], bh1[4], bl0[4], bl1[4];
#pragma unroll
            for (int na = 0; na < 4; na++) {
                int nb = wn * 32 + na * 8 + lg;
                int kl = ks + lq * 2;
                const __nv_bfloat16* ph = Bth + nb * PITCH + kl;
                const __nv_bfloat16* pl = Btl + nb * PITCH + kl;
                bh0[na] = *reinterpret_cast<const unsigned*>(ph);
                bh1[na] = *reinterpret_cast<const unsigned*>(ph + 8);
                bl0[na] = *reinterpret_cast<const unsigned*>(pl);
                bl1[na] = *reinterpret_cast<const unsigned*>(pl + 8);
            }
#pragma unroll
            for (int na = 0; na < 4; na++)
                MMA_BF16(acc[na], ah, bh0[na], bh1[na]);
#pragma unroll
            for (int na = 0; na < 4; na++)
                MMA_BF16(acc[na], ah, bl0[na], bl1[na]);
#pragma unroll
            for (int na = 0; na < 4; na++)
                MMA_BF16(acc[na], al, bh0[na], bh1[na]);
        }
        __syncthreads();
    }

    // ---- epilogue: bias(+ReLU), store C; WS=1 also stores bf16 split planes
#pragma unroll
    for (int na = 0; na < 4; na++) {
        int col = wn * 32 + na * 8 + lq * 2;
        float2 bv = *reinterpret_cast<const float2*>(&bias[col]);
        float v0 = acc[na][0] + bv.x;
        float v1 = acc[na][1] + bv.y;
        float v2 = acc[na][2] + bv.x;
        float v3 = acc[na][3] + bv.y;
        if (relu) {
            v0 = fmaxf(v0, 0.f); v1 = fmaxf(v1, 0.f);
            v2 = fmaxf(v2, 0.f); v3 = fmaxf(v3, 0.f);
        }
        int row0 = bm + wm * 16 + lg;
        int row1 = row0 + 8;
        if (row0 < NN) {
            *reinterpret_cast<float2*>(&C[(long)row0 * DHID + col]) = make_float2(v0, v1);
            if (WS) {
                unsigned h, l;
                split2(v0, v1, h, l);
                *reinterpret_cast<unsigned*>(&Ch[(long)row0 * DHID + col]) = h;
                *reinterpret_cast<unsigned*>(&Cl[(long)row0 * DHID + col]) = l;
            }
        }
        if (row1 < NN) {
            *reinterpret_cast<float2*>(&C[(long)row1 * DHID + col]) = make_float2(v2, v3);
            if (WS) {
                unsigned h, l;
                split2(v2, v3, h, l);
                *reinterpret_cast<unsigned*>(&Ch[(long)row1 * DHID + col]) = h;
                *reinterpret_cast<unsigned*>(&Cl[(long)row1 * DHID + col]) = l;
            }
        }
    }
}

__global__ void decoder_kernel(const int* __restrict__ head, const int* __restrict__ tail,
                               const int* __restrict__ rel, const float* __restrict__ h,
                               const float* __restrict__ rel_emb, float* __restrict__ out,
                               int Bn) {
    int warp = (blockIdx.x * blockDim.x + threadIdx.x) >> 5;
    int lane = threadIdx.x & 31;
    if (warp >= Bn) return;
    const float4* hp = reinterpret_cast<const float4*>(h + (long)head[warp] * DHID);
    const float4* tp = reinterpret_cast<const float4*>(h + (long)tail[warp] * DHID);
    const float4* rp = reinterpret_cast<const float4*>(rel_emb + (long)rel[warp] * DHID);
    float4 a = hp[lane], b = tp[lane], c = rp[lane];
    float s = a.x * b.x * c.x + a.y * b.y * c.y + a.z * b.z * c.z + a.w * b.w * c.w;
#pragma unroll
    for (int o = 16; o; o >>= 1) s += __shfl_xor_sync(0xffffffffu, s, o);
    if (lane == 0) out[warp] = s;
}

extern "C" void kernel_launch(void* const* d_in, const int* in_sizes, int n_in,
                              void* d_out, int out_size) {
    const int*   edge_index = (const int*)d_in[0];
    const int*   edge_type  = (const int*)d_in[1];
    const int*   head       = (const int*)d_in[2];
    const int*   tail       = (const int*)d_in[3];
    const int*   rel        = (const int*)d_in[4];
    const float* node_emb   = (const float*)d_in[5];
    const float* W1         = (const float*)d_in[6];
    const float* root1      = (const float*)d_in[7];
    const float* b1         = (const float*)d_in[8];
    const float* W2         = (const float*)d_in[9];
    const float* root2      = (const float*)d_in[10];
    const float* b2         = (const float*)d_in[11];
    const float* rel_emb    = (const float*)d_in[12];

    int E = in_sizes[0] / 2;
    const int* src = edge_index;
    const int* dst = edge_index + E;

    __nv_bfloat16 *xh, *xl, *yh, *yl, *B1h, *B1l, *B2h, *B2l;
    float *h1, *h2;
    int *icnt, *off, *pcur, *bsum, *ebuf;
    cudaGetSymbolAddress((void**)&xh, g_xh);
    cudaGetSymbolAddress((void**)&xl, g_xl);
    cudaGetSymbolAddress((void**)&yh, g_yh);
    cudaGetSymbolAddress((void**)&yl, g_yl);
    cudaGetSymbolAddress((void**)&B1h, g_B1h);
    cudaGetSymbolAddress((void**)&B1l, g_B1l);
    cudaGetSymbolAddress((void**)&B2h, g_B2h);
    cudaGetSymbolAddress((void**)&B2l, g_B2l);
    cudaGetSymbolAddress((void**)&h1, g_h1);
    cudaGetSymbolAddress((void**)&h2, g_h2);
    cudaGetSymbolAddress((void**)&icnt, g_icnt);
    cudaGetSymbolAddress((void**)&off, g_off);
    cudaGetSymbolAddress((void**)&pcur, g_pcur);
    cudaGetSymbolAddress((void**)&bsum, g_bsum);
    cudaGetSymbolAddress((void**)&ebuf, g_ebuf);

    const int T = 256;
    const int KA2 = NRL * DHID;
    const int OFFB = (64 * NRL + 1 + 3) / 4 * 4 * 4;
    const int SM1 = 384 * (DEMB + 8) * 2 + OFFB;   // 60432 B
    const int SM2 = 384 * (DHID + 8) * 2 + OFFB;   // 109584 B -> 2 blocks/SM

    cudaFuncSetAttribute((const void*)fused_gemm_kernel<DEMB, 1>,
                         cudaFuncAttributeMaxDynamicSharedMemorySize, SM1);
    cudaFuncSetAttribute((const void*)fused_gemm_kernel<DHID, 0>,
                         cudaFuncAttributeMaxDynamicSharedMemorySize, SM2);

    // 1) independent prep: X planes + layer-1 B planes
    prep1_kernel<<<592, T>>>(node_emb, xh, xl, W1, root1, B1h, B1l);
    // 2) one-kernel counting sort (grid-resident barrier)
    sort_all_kernel<<<SORT_NB, T>>>(src, dst, edge_type, E, icnt, off, pcur, bsum, ebuf);
    // 3) layer-2 B planes
    prepB_kernel<<<(128 * KT2 / 2 + T - 1) / T, T>>>(W2, root2, KA2, KT2, B2h, B2l);
    // 4) layer 1 fused gather+GEMM (epilogue emits h1 planes)
    fused_gemm_kernel<DEMB, 1><<<(NN + 63) / 64, 512, SM1>>>(
        ebuf, off, node_emb, xh, xl, B1h, B1l, b1, h1, yh, yl, 1);
    // 5) layer 2
    fused_gemm_kernel<DHID, 0><<<(NN + 63) / 64, 512, SM2>>>(
        ebuf, off, h1, yh, yl, B2h, B2l, b2, h2, nullptr, nullptr, 0);
    // 6) DistMult decoder
    int Bn = in_sizes[2];
    decoder_kernel<<<(Bn * 32 + T - 1) / T, T>>>(head, tail, rel, h2, rel_emb,
                                                 (float*)d_out, Bn);
}